// round 6
// baseline (speedup 1.0000x reference)
#include <cuda_runtime.h>
#include <cuda_bf16.h>
#include <cstdint>

// ---------------------------------------------------------------------------
// FeatureAlign via mma.sync bf16 (HMMA) with fp32->bf16 hi/lo splitting.
//   Y = relu( A(fp32 gathered) @ W(fp32) + b ) * mask
//   A@W ~= Ah@Wh + Ah@Wl + Al@Wh   (fp32 accum)
// Separate im2col (writes Ah/Al), GEMM with 512 threads / 16 warps.
// All 3 pyramid levels concatenated into 28672 rows; one GEMM per layer.
// ---------------------------------------------------------------------------

#define BSZ 8
#define CCH 512
#define KT  3
#define ROWS_TOTAL 28672
#define LV0 16384
#define LV01 24576
#define KRED 1536

// GEMM tiling
#define BMM 128
#define BNN 128
#define BKK 32
#define AST 40                      // A smem row stride (bf16): 32 + 8 pad
#define BST 136                     // B smem row stride: 128 + 8 pad
#define A_ELE (BMM*AST)             // 5120
#define B_ELE (BKK*BST)             // 4352
#define STG_BYTES ((2*A_ELE + 2*B_ELE)*2)   // 37888 B per stage
#define NSTAGE 3
#define GEMM_SMEM (NSTAGE*STG_BYTES)        // 113664 B
#define KITERS (KRED/BKK)           // 48

// scratch (device globals; no runtime allocation allowed)
__device__ float g_x[ROWS_TOTAL * CCH];
__device__ float g_y[ROWS_TOTAL * CCH];
__device__ float g_offa[ROWS_TOTAL * 4];
__device__ float g_offb[ROWS_TOTAL * 4];
__device__ float g_mrow[ROWS_TOTAL];
__device__ __nv_bfloat16 g_Ah[(size_t)ROWS_TOTAL * KRED];
__device__ __nv_bfloat16 g_Al[(size_t)ROWS_TOTAL * KRED];
__device__ __nv_bfloat16 g_Wh[2 * KRED * CCH];
__device__ __nv_bfloat16 g_Wl[2 * KRED * CCH];

// ---------------------------------------------------------------------------
__device__ __forceinline__ uint32_t smem_u32(const void* p) {
    return (uint32_t)__cvta_generic_to_shared(p);
}
#define CP16(sa, gp) \
    asm volatile("cp.async.cg.shared.global [%0], [%1], 16;" :: "r"(sa), "l"(gp))
#define CP_COMMIT() asm volatile("cp.async.commit_group;")
#define CP_WAIT1()  asm volatile("cp.async.wait_group 1;")

__device__ __forceinline__ void ldsm_x4(uint32_t* r, uint32_t a) {
    asm volatile("ldmatrix.sync.aligned.m8n8.x4.shared.b16 {%0,%1,%2,%3}, [%4];"
                 : "=r"(r[0]), "=r"(r[1]), "=r"(r[2]), "=r"(r[3]) : "r"(a));
}
__device__ __forceinline__ void ldsm_x4_t(uint32_t* r, uint32_t a) {
    asm volatile("ldmatrix.sync.aligned.m8n8.x4.trans.shared.b16 {%0,%1,%2,%3}, [%4];"
                 : "=r"(r[0]), "=r"(r[1]), "=r"(r[2]), "=r"(r[3]) : "r"(a));
}
__device__ __forceinline__ void mma16816(float* d, const uint32_t* a,
                                         const uint32_t* b) {
    asm volatile("mma.sync.aligned.m16n8k16.row.col.f32.bf16.bf16.f32 "
                 "{%0,%1,%2,%3}, {%4,%5,%6,%7}, {%8,%9}, {%0,%1,%2,%3};"
                 : "+f"(d[0]), "+f"(d[1]), "+f"(d[2]), "+f"(d[3])
                 : "r"(a[0]), "r"(a[1]), "r"(a[2]), "r"(a[3]), "r"(b[0]), "r"(b[1]));
}

// ---------------------------------------------------------------------------
// batched transpose: in (B, R, S) -> out (B, S, R)
__global__ void transpose_kernel(const float* __restrict__ in,
                                 float* __restrict__ out, int R, int S) {
    __shared__ float tile[32][33];
    int b = blockIdx.z, s0 = blockIdx.x * 32, r0 = blockIdx.y * 32;
    const float* inb = in + (size_t)b * R * S;
    float* outb = out + (size_t)b * R * S;
    #pragma unroll
    for (int i = threadIdx.y; i < 32; i += 8)
        tile[i][threadIdx.x] = inb[(size_t)(r0 + i) * S + s0 + threadIdx.x];
    __syncthreads();
    #pragma unroll
    for (int i = threadIdx.y; i < 32; i += 8)
        outb[(size_t)(s0 + i) * R + r0 + threadIdx.x] = tile[threadIdx.x][i];
}

// ---------------------------------------------------------------------------
// Wh/Wl[l][k][n], k = ktap*512 + c ; from w[(n*512 + c)*3 + ktap]
__global__ void prep_wsplit_kernel(const float* __restrict__ w0,
                                   const float* __restrict__ w1,
                                   __nv_bfloat16* __restrict__ Wh,
                                   __nv_bfloat16* __restrict__ Wl) {
    int idx = blockIdx.x * blockDim.x + threadIdx.x;
    if (idx >= 2 * KRED * CCH) return;
    int n = idx & 511;
    int k = (idx >> 9) % KRED;
    int l = idx / (KRED * CCH);
    int ktap = k >> 9, c = k & 511;
    const float* w = l ? w1 : w0;
    float val = w[(n * CCH + c) * KT + ktap];
    __nv_bfloat16 hi = __float2bfloat16(val);
    Wh[idx] = hi;
    Wl[idx] = __float2bfloat16(val - __bfloat162float(hi));
}

// ---------------------------------------------------------------------------
__global__ void maskrow_kernel(const float* __restrict__ m0,
                               const float* __restrict__ m1,
                               const float* __restrict__ m2,
                               float* __restrict__ out) {
    int m = blockIdx.x * 256 + threadIdx.x;
    if (m >= ROWS_TOTAL) return;
    out[m] = (m < LV0) ? m0[m] : (m < LV01 ? m1[m - LV0] : m2[m - LV01]);
}
__global__ void maskout_kernel(const float* __restrict__ in,
                               float* __restrict__ out, int n) {
    int i = blockIdx.x * blockDim.x + threadIdx.x;
    if (i < n) out[i] = (in[i] != 0.f) ? 1.0f : 0.0f;
}

// ---------------------------------------------------------------------------
// offset conv: block = 8 consecutive rows of one level, staged in SMEM.
// ow_sh2[(kk*3 + j) * 512 + c] = ow[(kk*512 + c)*3 + j]  (f4-friendly)
template <bool EXT>
__global__ void offset_kernel(const float* __restrict__ X,
                              const float* __restrict__ off_in,
                              const float* __restrict__ ow,
                              const float* __restrict__ ob,
                              float* __restrict__ off_out,  // [m*4+k] absolute
                              int T, int lbase) {
    __shared__ float ow_sh2[KT * KT * CCH];   // 18 KB
    __shared__ float xs[10 * CCH];            // 20 KB
    int tid = threadIdx.x;

    for (int i = tid; i < KT * KT * CCH; i += 256) {
        // i = (kk*512 + c)*3 + j  ->  dst (kk*3 + j)*512 + c
        int j = i % 3;
        int r = i / 3;
        int kk = r >> 9, c = r & 511;
        ow_sh2[(kk * 3 + j) * CCH + c] = ow[i];
    }

    int rl0 = blockIdx.x * 8;
    int t0 = rl0 % T;
    // stage rows rl0-1 .. rl0+8 (zero outside [0,T) within batch)
    #pragma unroll
    for (int q = 0; q < 5; q++) {
        int fi = tid + q * 256;               // 0..1279 float4s
        int j = fi >> 7;                      // row 0..9
        int cf = (fi & 127) * 4;
        int t = t0 + j - 1;
        float4 v = make_float4(0.f, 0.f, 0.f, 0.f);
        if (t >= 0 && t < T)
            v = *(const float4*)(X + (size_t)(rl0 - 1 + j) * CCH + cf);
        *(float4*)(xs + j * CCH + cf) = v;
    }
    __syncthreads();

    int warp = tid >> 5, lane = tid & 31;
    int rl = rl0 + warp;
    int b = rl / T, t = rl % T;
    int m = lbase + rl;

    float a0 = 0.f, a1 = 0.f, a2 = 0.f;
    #pragma unroll
    for (int q = 0; q < 4; q++) {
        int c = lane * 4 + q * 128;
        float4 vm = *(const float4*)(xs + warp * CCH + c);
        float4 v0 = *(const float4*)(xs + (warp + 1) * CCH + c);
        float4 vp = *(const float4*)(xs + (warp + 2) * CCH + c);
        #pragma unroll
        for (int kk = 0; kk < 3; kk++) {
            float4 wmv = *(const float4*)(ow_sh2 + (kk * 3 + 0) * CCH + c);
            float4 w0v = *(const float4*)(ow_sh2 + (kk * 3 + 1) * CCH + c);
            float4 wpv = *(const float4*)(ow_sh2 + (kk * 3 + 2) * CCH + c);
            float s = wmv.x * vm.x + wmv.y * vm.y + wmv.z * vm.z + wmv.w * vm.w
                    + w0v.x * v0.x + w0v.y * v0.y + w0v.z * v0.z + w0v.w * v0.w
                    + wpv.x * vp.x + wpv.y * vp.y + wpv.z * vp.z + wpv.w * vp.w;
            if (kk == 0) a0 += s; else if (kk == 1) a1 += s; else a2 += s;
        }
    }
    #pragma unroll
    for (int s = 16; s; s >>= 1) {
        a0 += __shfl_down_sync(0xffffffffu, a0, s);
        a1 += __shfl_down_sync(0xffffffffu, a1, s);
        a2 += __shfl_down_sync(0xffffffffu, a2, s);
    }
    if (lane == 0) {
        float i0, i1, i2;
        if (EXT) {
            i0 = off_in[((size_t)b * KT + 0) * T + t];
            i1 = off_in[((size_t)b * KT + 1) * T + t];
            i2 = off_in[((size_t)b * KT + 2) * T + t];
        } else {
            i0 = off_in[(size_t)m * 4 + 0];
            i1 = off_in[(size_t)m * 4 + 1];
            i2 = off_in[(size_t)m * 4 + 2];
        }
        off_out[(size_t)m * 4 + 0] = a0 + ob[0] + i0;
        off_out[(size_t)m * 4 + 1] = a1 + ob[1] + i1;
        off_out[(size_t)m * 4 + 2] = a2 + ob[2] + i2;
    }
}

// ---------------------------------------------------------------------------
// im2col gather + lerp + bf16 hi/lo split. grid (ROWS_TOTAL, 3), block 128.
__global__ void im2col_split_kernel(const float* __restrict__ X,
                                    const float* __restrict__ OFF,
                                    __nv_bfloat16* __restrict__ Ah,
                                    __nv_bfloat16* __restrict__ Al) {
    int m = blockIdx.x, k = blockIdx.y;
    int lv = (m < LV0) ? 0 : (m < LV01 ? 1 : 2);
    int lbase = (lv == 0) ? 0 : (lv == 1 ? LV0 : LV01);
    int logT = 11 - lv;
    int T = 1 << logT;
    int rl = m - lbase;
    int b = rl >> logT, t = rl & (T - 1);

    float off = OFF[(size_t)m * 4 + k];
    float pos = (float)(t + k - 1) + off;
    float p0f = floorf(pos);
    float f = pos - p0f;
    int i0 = (int)p0f, i1 = i0 + 1;
    float w0 = (i0 >= 0 && i0 < T) ? (1.0f - f) : 0.0f;
    float w1 = (i1 >= 0 && i1 < T) ? f : 0.0f;
    int i0c = min(max(i0, 0), T - 1);
    int i1c = min(max(i1, 0), T - 1);

    size_t rb = (size_t)lbase + ((size_t)b << logT);
    const float4* r0 = (const float4*)(X + (rb + i0c) * CCH);
    const float4* r1 = (const float4*)(X + (rb + i1c) * CCH);

    int i = threadIdx.x;            // 0..127, 4 channels each
    float4 a = r0[i], c = r1[i];
    float e0 = w0 * a.x + w1 * c.x;
    float e1 = w0 * a.y + w1 * c.y;
    float e2 = w0 * a.z + w1 * c.z;
    float e3 = w0 * a.w + w1 * c.w;

    __nv_bfloat162 h01 = __floats2bfloat162_rn(e0, e1);
    __nv_bfloat162 h23 = __floats2bfloat162_rn(e2, e3);
    float2 f01 = __bfloat1622float2(h01);
    float2 f23 = __bfloat1622float2(h23);
    __nv_bfloat162 l01 = __floats2bfloat162_rn(e0 - f01.x, e1 - f01.y);
    __nv_bfloat162 l23 = __floats2bfloat162_rn(e2 - f23.x, e3 - f23.y);

    size_t base = (size_t)m * KRED + (size_t)k * CCH + i * 4;
    uint2 hv, lvv;
    hv.x = *reinterpret_cast<uint32_t*>(&h01);
    hv.y = *reinterpret_cast<uint32_t*>(&h23);
    lvv.x = *reinterpret_cast<uint32_t*>(&l01);
    lvv.y = *reinterpret_cast<uint32_t*>(&l23);
    *(uint2*)(Ah + base) = hv;
    *(uint2*)(Al + base) = lvv;
}

// ---------------------------------------------------------------------------
// GEMM: Y[m,n] = relu( (Ah@Wh + Ah@Wl + Al@Wh)[m,n] + bias[n] ) * maskrow[m]
// grid (4, 224), 512 threads (16 warps, warp tile 32x32), 3-stage cp.async.
__global__ __launch_bounds__(512, 1)
void gemm_mma_kernel(const __nv_bfloat16* __restrict__ Ahg,
                     const __nv_bfloat16* __restrict__ Alg,
                     const __nv_bfloat16* __restrict__ Whg,
                     const __nv_bfloat16* __restrict__ Wlg,
                     const float* __restrict__ bias,
                     const float* __restrict__ maskrow,
                     float* __restrict__ Y) {
    extern __shared__ __nv_bfloat16 sm[];
    uint32_t sbase = smem_u32(sm);
    int tid = threadIdx.x, warp = tid >> 5, lane = tid & 31;
    int m0 = blockIdx.y * BMM, n0 = blockIdx.x * BNN;

    const uint32_t offAl = A_ELE * 2;
    const uint32_t offBh = 2 * A_ELE * 2;
    const uint32_t offBl = offBh + B_ELE * 2;

    // cp.async per-thread geometry (512 threads: one 16B each per matrix)
    int ar0 = tid >> 2, akc = (tid & 3) * 8;            // A: 128 rows x 32 k
    int br0 = tid >> 4, bnc = (tid & 15) * 8;           // B: 32 k x 128 n
    const __nv_bfloat16* gAh = Ahg + (size_t)(m0 + ar0) * KRED + akc;
    const __nv_bfloat16* gAl = Alg + (size_t)(m0 + ar0) * KRED + akc;
    const __nv_bfloat16* gBh = Whg + (size_t)br0 * CCH + n0 + bnc;
    const __nv_bfloat16* gBl = Wlg + (size_t)br0 * CCH + n0 + bnc;
    uint32_t sA = (uint32_t)(ar0 * AST + akc) * 2;
    uint32_t sB = (uint32_t)(br0 * BST + bnc) * 2;

    // ldmatrix per-thread offsets; warp grid 4x4, warp tile 32x32
    int wm = (warp >> 2) * 32, wn = (warp & 3) * 32;
    int lr = lane & 15, lc = lane >> 4;
    uint32_t a_off[2], b_off[2];
    #pragma unroll
    for (int mt = 0; mt < 2; mt++)
        a_off[mt] = (uint32_t)((wm + mt * 16 + lr) * AST + lc * 8) * 2;
    #pragma unroll
    for (int nt = 0; nt < 2; nt++)
        b_off[nt] = (uint32_t)(lr * BST + wn + nt * 16 + lc * 8) * 2;

    float acc[2][4][4];
    #pragma unroll
    for (int i = 0; i < 2; i++)
        #pragma unroll
        for (int j = 0; j < 4; j++)
            #pragma unroll
            for (int q = 0; q < 4; q++) acc[i][j][q] = 0.f;

    auto load_stage = [&](int st, int k0) {
        uint32_t sb = sbase + (uint32_t)st * STG_BYTES;
        CP16(sb + sA, gAh + k0);
        CP16(sb + offAl + sA, gAl + k0);
        CP16(sb + offBh + sB, gBh + (size_t)k0 * CCH);
        CP16(sb + offBl + sB, gBl + (size_t)k0 * CCH);
    };

    load_stage(0, 0);  CP_COMMIT();
    load_stage(1, BKK); CP_COMMIT();

    for (int it = 0; it < KITERS; it++) {
        CP_WAIT1();
        __syncthreads();
        if (it + 2 < KITERS) load_stage((it + 2) % NSTAGE, (it + 2) * BKK);
        CP_COMMIT();

        uint32_t sb = sbase + (uint32_t)(it % NSTAGE) * STG_BYTES;
        #pragma unroll
        for (int ks = 0; ks < 2; ks++) {
            uint32_t ah[2][4], al[2][4], bh[2][4], bl[2][4];
            #pragma unroll
            for (int mt = 0; mt < 2; mt++) {
                ldsm_x4(ah[mt], sb + a_off[mt] + ks * 32);
                ldsm_x4(al[mt], sb + offAl + a_off[mt] + ks * 32);
            }
            #pragma unroll
            for (int nt = 0; nt < 2; nt++) {
                ldsm_x4_t(bh[nt], sb + offBh + b_off[nt] + ks * (16 * BST * 2));
                ldsm_x4_t(bl[nt], sb + offBl + b_off[nt] + ks * (16 * BST * 2));
            }
            #pragma unroll
            for (int mt = 0; mt < 2; mt++) {
                #pragma unroll
                for (int n8 = 0; n8 < 4; n8++) {
                    const uint32_t* ph = &bh[n8 >> 1][(n8 & 1) * 2];
                    const uint32_t* pl = &bl[n8 >> 1][(n8 & 1) * 2];
                    mma16816(acc[mt][n8], ah[mt], ph);
                    mma16816(acc[mt][n8], ah[mt], pl);
                    mma16816(acc[mt][n8], al[mt], ph);
                }
            }
        }
    }

    // epilogue
    #pragma unroll
    for (int mt = 0; mt < 2; mt++) {
        int r0g = m0 + wm + mt * 16 + (lane >> 2);
        float mv0 = maskrow[r0g], mv1 = maskrow[r0g + 8];
        float* y0 = Y + (size_t)r0g * CCH;
        float* y1 = y0 + (size_t)8 * CCH;
        #pragma unroll
        for (int n8 = 0; n8 < 4; n8++) {
            int c0g = n0 + wn + n8 * 8 + (lane & 3) * 2;
            float b0 = bias[c0g], b1 = bias[c0g + 1];
            float2 v0, v1;
            v0.x = fmaxf(acc[mt][n8][0] + b0, 0.f) * mv0;
            v0.y = fmaxf(acc[mt][n8][1] + b1, 0.f) * mv0;
            v1.x = fmaxf(acc[mt][n8][2] + b0, 0.f) * mv1;
            v1.y = fmaxf(acc[mt][n8][3] + b1, 0.f) * mv1;
            *(float2*)(y0 + c0g) = v0;
            *(float2*)(y1 + c0g) = v1;
        }
    }
}

// ---------------------------------------------------------------------------
extern "C" void kernel_launch(void* const* d_in, const int* in_sizes, int n_in,
                              void* d_out, int out_size) {
    const float *feats[3] = {}, *masks[3] = {}, *offs[3] = {};
    const float *w[2] = {}, *bias[2] = {}, *ow[2] = {}, *ob[2] = {};
    int wi = 0, bi = 0, owi = 0, obi = 0;
    for (int i = 0; i < n_in; i++) {
        const float* p = (const float*)d_in[i];
        switch (in_sizes[i]) {
            case 8 * 512 * 2048: feats[0] = p; break;
            case 8 * 512 * 1024: feats[1] = p; break;
            case 8 * 512 * 512:  feats[2] = p; break;
            case 8 * 2048:       masks[0] = p; break;
            case 8 * 1024:       masks[1] = p; break;
            case 8 * 512:        masks[2] = p; break;
            case 8 * 3 * 2048:   offs[0] = p; break;
            case 8 * 3 * 1024:   offs[1] = p; break;
            case 8 * 3 * 512:    offs[2] = p; break;
            case 512 * 512 * 3:  if (wi < 2)  w[wi++] = p; break;
            case 512:            if (bi < 2)  bias[bi++] = p; break;
            case 3 * 512 * 3:    if (owi < 2) ow[owi++] = p; break;
            case 3:              if (obi < 2) ob[obi++] = p; break;
            default: break;
        }
    }

    float *xb, *yb, *offa, *offb, *mrow;
    __nv_bfloat16 *Ah, *Al, *Wh, *Wl;
    cudaGetSymbolAddress((void**)&xb, g_x);
    cudaGetSymbolAddress((void**)&yb, g_y);
    cudaGetSymbolAddress((void**)&offa, g_offa);
    cudaGetSymbolAddress((void**)&offb, g_offb);
    cudaGetSymbolAddress((void**)&mrow, g_mrow);
    cudaGetSymbolAddress((void**)&Ah, g_Ah);
    cudaGetSymbolAddress((void**)&Al, g_Al);
    cudaGetSymbolAddress((void**)&Wh, g_Wh);
    cudaGetSymbolAddress((void**)&Wl, g_Wl);
    float* out = (float*)d_out;

    cudaFuncSetAttribute(gemm_mma_kernel,
                         cudaFuncAttributeMaxDynamicSharedMemorySize, GEMM_SMEM);

    {
        int total = 2 * KRED * CCH;
        prep_wsplit_kernel<<<(total + 255) / 256, 256>>>(w[0], w[1], Wh, Wl);
        maskrow_kernel<<<(ROWS_TOTAL + 255) / 256, 256>>>(masks[0], masks[1],
                                                          masks[2], mrow);
    }

    const int Ts[3]    = {2048, 1024, 512};
    const int lbase[3] = {0, LV0, LV01};

    for (int lv = 0; lv < 3; lv++) {
        int T = Ts[lv];
        transpose_kernel<<<dim3(T / 32, CCH / 32, BSZ), dim3(32, 8)>>>(
            feats[lv], xb + (size_t)lbase[lv] * CCH, CCH, T);
    }

    // ---- layer 0 ----
    for (int lv = 0; lv < 3; lv++)
        offset_kernel<true><<<Ts[lv], 256>>>(xb + (size_t)lbase[lv] * CCH, offs[lv],
                                             ow[0], ob[0], offa, Ts[lv], lbase[lv]);
    im2col_split_kernel<<<dim3(ROWS_TOTAL, KT), 128>>>(xb, offa, Ah, Al);
    gemm_mma_kernel<<<dim3(4, ROWS_TOTAL / BMM), 512, GEMM_SMEM>>>(
        Ah, Al, Wh, Wl, bias[0], mrow, yb);

    // ---- layer 1 ----
    for (int lv = 0; lv < 3; lv++)
        offset_kernel<false><<<Ts[lv], 256>>>(yb + (size_t)lbase[lv] * CCH, offa,
                                              ow[1], ob[1], offb, Ts[lv], lbase[lv]);
    im2col_split_kernel<<<dim3(ROWS_TOTAL, KT), 128>>>(yb, offb, Ah, Al);
    gemm_mma_kernel<<<dim3(4, ROWS_TOTAL / BMM), 512, GEMM_SMEM>>>(
        Ah, Al, Wh + (size_t)KRED * CCH, Wl + (size_t)KRED * CCH,
        bias[1], mrow, xb);

    // outputs
    size_t outBase[3] = {0, (size_t)BSZ * CCH * 2048,
                         (size_t)BSZ * CCH * (2048 + 1024)};
    size_t mb0 = (size_t)BSZ * CCH * 3584;
    size_t maskBase[3] = {mb0, mb0 + (size_t)BSZ * 2048, mb0 + (size_t)BSZ * 3072};
    for (int lv = 0; lv < 3; lv++) {
        int T = Ts[lv];
        transpose_kernel<<<dim3(CCH / 32, T / 32, BSZ), dim3(32, 8)>>>(
            xb + (size_t)lbase[lv] * CCH, out + outBase[lv], T, CCH);
        int nm = BSZ * T;
        maskout_kernel<<<(nm + 255) / 256, 256>>>(masks[lv], out + maskBase[lv], nm);
    }
}

// round 7
// speedup vs baseline: 1.1331x; 1.1331x over previous
#include <cuda_runtime.h>
#include <cuda_bf16.h>
#include <cstdint>

// ---------------------------------------------------------------------------
// FeatureAlign via mma.sync bf16 (HMMA) with fp32->bf16 hi/lo splitting.
//   Y = relu( A(fp32 gathered) @ W(fp32) + b ) * mask
//   A@W ~= Ah@Wh + Ah@Wl + Al@Wh   (fp32 accum)
// GEMM: 8 warps, 2-stage cp.async, occupancy 2.  One offset launch per layer.
// All 3 pyramid levels concatenated into 28672 rows; one GEMM per layer.
// ---------------------------------------------------------------------------

#define BSZ 8
#define CCH 512
#define KT  3
#define ROWS_TOTAL 28672
#define LV0 16384
#define LV01 24576
#define KRED 1536

// GEMM tiling
#define BMM 128
#define BNN 128
#define BKK 32
#define AST 40                      // A smem row stride (bf16): 32 + 8 pad
#define BST 136                     // B smem row stride: 128 + 8 pad
#define A_ELE (BMM*AST)             // 5120
#define B_ELE (BKK*BST)             // 4352
#define STG_BYTES ((2*A_ELE + 2*B_ELE)*2)   // 37888 B per stage
#define NSTAGE 2
#define GEMM_SMEM (NSTAGE*STG_BYTES)        // 75776 B -> 2 CTAs/SM
#define KITERS (KRED/BKK)           // 48

// scratch (device globals; no runtime allocation allowed)
__device__ float g_x[ROWS_TOTAL * CCH];
__device__ float g_y[ROWS_TOTAL * CCH];
__device__ float g_offa[ROWS_TOTAL * 4];
__device__ float g_offb[ROWS_TOTAL * 4];
__device__ float g_mrow[ROWS_TOTAL];
__device__ __nv_bfloat16 g_Ah[(size_t)ROWS_TOTAL * KRED];
__device__ __nv_bfloat16 g_Al[(size_t)ROWS_TOTAL * KRED];
__device__ __nv_bfloat16 g_Wh[2 * KRED * CCH];
__device__ __nv_bfloat16 g_Wl[2 * KRED * CCH];

// ---------------------------------------------------------------------------
__device__ __forceinline__ uint32_t smem_u32(const void* p) {
    return (uint32_t)__cvta_generic_to_shared(p);
}
#define CP16(sa, gp) \
    asm volatile("cp.async.cg.shared.global [%0], [%1], 16;" :: "r"(sa), "l"(gp))
#define CP_COMMIT() asm volatile("cp.async.commit_group;")
#define CP_WAIT0()  asm volatile("cp.async.wait_group 0;")

__device__ __forceinline__ void ldsm_x4(uint32_t* r, uint32_t a) {
    asm volatile("ldmatrix.sync.aligned.m8n8.x4.shared.b16 {%0,%1,%2,%3}, [%4];"
                 : "=r"(r[0]), "=r"(r[1]), "=r"(r[2]), "=r"(r[3]) : "r"(a));
}
__device__ __forceinline__ void ldsm_x4_t(uint32_t* r, uint32_t a) {
    asm volatile("ldmatrix.sync.aligned.m8n8.x4.trans.shared.b16 {%0,%1,%2,%3}, [%4];"
                 : "=r"(r[0]), "=r"(r[1]), "=r"(r[2]), "=r"(r[3]) : "r"(a));
}
__device__ __forceinline__ void mma16816(float* d, const uint32_t* a,
                                         const uint32_t* b) {
    asm volatile("mma.sync.aligned.m16n8k16.row.col.f32.bf16.bf16.f32 "
                 "{%0,%1,%2,%3}, {%4,%5,%6,%7}, {%8,%9}, {%0,%1,%2,%3};"
                 : "+f"(d[0]), "+f"(d[1]), "+f"(d[2]), "+f"(d[3])
                 : "r"(a[0]), "r"(a[1]), "r"(a[2]), "r"(a[3]), "r"(b[0]), "r"(b[1]));
}

// ---------------------------------------------------------------------------
// batched transpose: in (B, R, S) -> out (B, S, R)
__global__ void transpose_kernel(const float* __restrict__ in,
                                 float* __restrict__ out, int R, int S) {
    __shared__ float tile[32][33];
    int b = blockIdx.z, s0 = blockIdx.x * 32, r0 = blockIdx.y * 32;
    const float* inb = in + (size_t)b * R * S;
    float* outb = out + (size_t)b * R * S;
    #pragma unroll
    for (int i = threadIdx.y; i < 32; i += 8)
        tile[i][threadIdx.x] = inb[(size_t)(r0 + i) * S + s0 + threadIdx.x];
    __syncthreads();
    #pragma unroll
    for (int i = threadIdx.y; i < 32; i += 8)
        outb[(size_t)(s0 + i) * R + r0 + threadIdx.x] = tile[threadIdx.x][i];
}

// ---------------------------------------------------------------------------
// Wh/Wl[l][k][n], k = ktap*512 + c ; from w[(n*512 + c)*3 + ktap]
__global__ void prep_wsplit_kernel(const float* __restrict__ w0,
                                   const float* __restrict__ w1,
                                   __nv_bfloat16* __restrict__ Wh,
                                   __nv_bfloat16* __restrict__ Wl) {
    int idx = blockIdx.x * blockDim.x + threadIdx.x;
    if (idx >= 2 * KRED * CCH) return;
    int n = idx & 511;
    int k = (idx >> 9) % KRED;
    int l = idx / (KRED * CCH);
    int ktap = k >> 9, c = k & 511;
    const float* w = l ? w1 : w0;
    float val = w[(n * CCH + c) * KT + ktap];
    __nv_bfloat16 hi = __float2bfloat16(val);
    Wh[idx] = hi;
    Wl[idx] = __float2bfloat16(val - __bfloat162float(hi));
}

// ---------------------------------------------------------------------------
__global__ void maskrow_kernel(const float* __restrict__ m0,
                               const float* __restrict__ m1,
                               const float* __restrict__ m2,
                               float* __restrict__ out) {
    int m = blockIdx.x * 256 + threadIdx.x;
    if (m >= ROWS_TOTAL) return;
    out[m] = (m < LV0) ? m0[m] : (m < LV01 ? m1[m - LV0] : m2[m - LV01]);
}
__global__ void maskout_kernel(const float* __restrict__ in,
                               float* __restrict__ out, int n) {
    int i = blockIdx.x * blockDim.x + threadIdx.x;
    if (i < n) out[i] = (in[i] != 0.f) ? 1.0f : 0.0f;
}

// ---------------------------------------------------------------------------
// offset conv over ALL levels in one launch: block = 8 consecutive rows.
// Level derived from global row (level sizes are multiples of 8).
// EXT: external offsets o0/o1/o2 (B,3,T) per level; else internal [m*4+k] in o0.
template <bool EXT>
__global__ void offset_kernel(const float* __restrict__ X,
                              const float* __restrict__ o0,
                              const float* __restrict__ o1,
                              const float* __restrict__ o2,
                              const float* __restrict__ ow,
                              const float* __restrict__ ob,
                              float* __restrict__ off_out) {
    __shared__ float ow_sh2[KT * KT * CCH];   // 18 KB
    __shared__ float xs[10 * CCH];            // 20 KB
    int tid = threadIdx.x;

    int rl0g = blockIdx.x * 8;
    int lv = (rl0g < LV0) ? 0 : (rl0g < LV01 ? 1 : 2);
    int lbase = (lv == 0) ? 0 : (lv == 1 ? LV0 : LV01);
    int logT = 11 - lv;
    int T = 1 << logT;
    int rl0 = rl0g - lbase;
    const float* Xl = X + (size_t)lbase * CCH;

    for (int i = tid; i < KT * KT * CCH; i += 256) {
        // i = (kk*512 + c)*3 + j  ->  dst (kk*3 + j)*512 + c
        int j = i % 3;
        int r = i / 3;
        int kk = r >> 9, c = r & 511;
        ow_sh2[(kk * 3 + j) * CCH + c] = ow[i];
    }

    int t0 = rl0 & (T - 1);
    // stage rows rl0-1 .. rl0+8 (zero where t outside [0,T))
    #pragma unroll
    for (int q = 0; q < 5; q++) {
        int fi = tid + q * 256;               // 0..1279 float4s
        int j = fi >> 7;                      // row 0..9
        int cf = (fi & 127) * 4;
        int t = t0 + j - 1;
        float4 v = make_float4(0.f, 0.f, 0.f, 0.f);
        if (t >= 0 && t < T)
            v = *(const float4*)(Xl + (size_t)(rl0 - 1 + j) * CCH + cf);
        *(float4*)(xs + j * CCH + cf) = v;
    }
    __syncthreads();

    int warp = tid >> 5, lane = tid & 31;
    int rl = rl0 + warp;
    int b = rl >> logT, t = rl & (T - 1);
    int m = rl0g + warp;

    float a0 = 0.f, a1 = 0.f, a2 = 0.f;
    #pragma unroll
    for (int q = 0; q < 4; q++) {
        int c = lane * 4 + q * 128;
        float4 vm = *(const float4*)(xs + warp * CCH + c);
        float4 v0 = *(const float4*)(xs + (warp + 1) * CCH + c);
        float4 vp = *(const float4*)(xs + (warp + 2) * CCH + c);
        #pragma unroll
        for (int kk = 0; kk < 3; kk++) {
            float4 wmv = *(const float4*)(ow_sh2 + (kk * 3 + 0) * CCH + c);
            float4 w0v = *(const float4*)(ow_sh2 + (kk * 3 + 1) * CCH + c);
            float4 wpv = *(const float4*)(ow_sh2 + (kk * 3 + 2) * CCH + c);
            float s = wmv.x * vm.x + wmv.y * vm.y + wmv.z * vm.z + wmv.w * vm.w
                    + w0v.x * v0.x + w0v.y * v0.y + w0v.z * v0.z + w0v.w * v0.w
                    + wpv.x * vp.x + wpv.y * vp.y + wpv.z * vp.z + wpv.w * vp.w;
            if (kk == 0) a0 += s; else if (kk == 1) a1 += s; else a2 += s;
        }
    }
    #pragma unroll
    for (int s = 16; s; s >>= 1) {
        a0 += __shfl_down_sync(0xffffffffu, a0, s);
        a1 += __shfl_down_sync(0xffffffffu, a1, s);
        a2 += __shfl_down_sync(0xffffffffu, a2, s);
    }
    if (lane == 0) {
        float i0, i1, i2;
        if (EXT) {
            const float* oin = (lv == 0) ? o0 : (lv == 1 ? o1 : o2);
            i0 = oin[((size_t)b * KT + 0) * T + t];
            i1 = oin[((size_t)b * KT + 1) * T + t];
            i2 = oin[((size_t)b * KT + 2) * T + t];
        } else {
            i0 = o0[(size_t)m * 4 + 0];
            i1 = o0[(size_t)m * 4 + 1];
            i2 = o0[(size_t)m * 4 + 2];
        }
        off_out[(size_t)m * 4 + 0] = a0 + ob[0] + i0;
        off_out[(size_t)m * 4 + 1] = a1 + ob[1] + i1;
        off_out[(size_t)m * 4 + 2] = a2 + ob[2] + i2;
    }
}

// ---------------------------------------------------------------------------
// im2col gather + lerp + bf16 hi/lo split. grid (ROWS_TOTAL, 3), block 128.
__global__ void im2col_split_kernel(const float* __restrict__ X,
                                    const float* __restrict__ OFF,
                                    __nv_bfloat16* __restrict__ Ah,
                                    __nv_bfloat16* __restrict__ Al) {
    int m = blockIdx.x, k = blockIdx.y;
    int lv = (m < LV0) ? 0 : (m < LV01 ? 1 : 2);
    int lbase = (lv == 0) ? 0 : (lv == 1 ? LV0 : LV01);
    int logT = 11 - lv;
    int T = 1 << logT;
    int rl = m - lbase;
    int b = rl >> logT, t = rl & (T - 1);

    float off = OFF[(size_t)m * 4 + k];
    float pos = (float)(t + k - 1) + off;
    float p0f = floorf(pos);
    float f = pos - p0f;
    int i0 = (int)p0f, i1 = i0 + 1;
    float w0 = (i0 >= 0 && i0 < T) ? (1.0f - f) : 0.0f;
    float w1 = (i1 >= 0 && i1 < T) ? f : 0.0f;
    int i0c = min(max(i0, 0), T - 1);
    int i1c = min(max(i1, 0), T - 1);

    size_t rb = (size_t)lbase + ((size_t)b << logT);
    const float4* r0 = (const float4*)(X + (rb + i0c) * CCH);
    const float4* r1 = (const float4*)(X + (rb + i1c) * CCH);

    int i = threadIdx.x;            // 0..127, 4 channels each
    float4 a = r0[i], c = r1[i];
    float e0 = w0 * a.x + w1 * c.x;
    float e1 = w0 * a.y + w1 * c.y;
    float e2 = w0 * a.z + w1 * c.z;
    float e3 = w0 * a.w + w1 * c.w;

    __nv_bfloat162 h01 = __floats2bfloat162_rn(e0, e1);
    __nv_bfloat162 h23 = __floats2bfloat162_rn(e2, e3);
    float2 f01 = __bfloat1622float2(h01);
    float2 f23 = __bfloat1622float2(h23);
    __nv_bfloat162 l01 = __floats2bfloat162_rn(e0 - f01.x, e1 - f01.y);
    __nv_bfloat162 l23 = __floats2bfloat162_rn(e2 - f23.x, e3 - f23.y);

    size_t base = (size_t)m * KRED + (size_t)k * CCH + i * 4;
    uint2 hv, lvv;
    hv.x = *reinterpret_cast<uint32_t*>(&h01);
    hv.y = *reinterpret_cast<uint32_t*>(&h23);
    lvv.x = *reinterpret_cast<uint32_t*>(&l01);
    lvv.y = *reinterpret_cast<uint32_t*>(&l23);
    *(uint2*)(Ah + base) = hv;
    *(uint2*)(Al + base) = lvv;
}

// ---------------------------------------------------------------------------
// GEMM: Y[m,n] = relu( (Ah@Wh + Ah@Wl + Al@Wh)[m,n] + bias[n] ) * maskrow[m]
// grid (4, 224), 256 threads (8 warps, warp tile 64x32), 2-stage, occ 2.
__global__ __launch_bounds__(256, 2)
void gemm_mma_kernel(const __nv_bfloat16* __restrict__ Ahg,
                     const __nv_bfloat16* __restrict__ Alg,
                     const __nv_bfloat16* __restrict__ Whg,
                     const __nv_bfloat16* __restrict__ Wlg,
                     const float* __restrict__ bias,
                     const float* __restrict__ maskrow,
                     float* __restrict__ Y) {
    extern __shared__ __nv_bfloat16 sm[];
    uint32_t sbase = smem_u32(sm);
    int tid = threadIdx.x, warp = tid >> 5, lane = tid & 31;
    int m0 = blockIdx.y * BMM, n0 = blockIdx.x * BNN;

    const uint32_t offAl = A_ELE * 2;
    const uint32_t offBh = 2 * A_ELE * 2;
    const uint32_t offBl = offBh + B_ELE * 2;

    // cp.async per-thread geometry (2 chunks each per matrix)
    int ar0 = tid >> 2, akc = (tid & 3) * 8;
    int br0 = tid >> 4, bnc = (tid & 15) * 8;
    const __nv_bfloat16* gAh0 = Ahg + (size_t)(m0 + ar0) * KRED + akc;
    const __nv_bfloat16* gAh1 = Ahg + (size_t)(m0 + ar0 + 64) * KRED + akc;
    const __nv_bfloat16* gAl0 = Alg + (size_t)(m0 + ar0) * KRED + akc;
    const __nv_bfloat16* gAl1 = Alg + (size_t)(m0 + ar0 + 64) * KRED + akc;
    const __nv_bfloat16* gBh0 = Whg + (size_t)br0 * CCH + n0 + bnc;
    const __nv_bfloat16* gBh1 = Whg + (size_t)(br0 + 16) * CCH + n0 + bnc;
    const __nv_bfloat16* gBl0 = Wlg + (size_t)br0 * CCH + n0 + bnc;
    const __nv_bfloat16* gBl1 = Wlg + (size_t)(br0 + 16) * CCH + n0 + bnc;
    uint32_t sA0 = (uint32_t)(ar0 * AST + akc) * 2;
    uint32_t sA1 = (uint32_t)((ar0 + 64) * AST + akc) * 2;
    uint32_t sB0 = (uint32_t)(br0 * BST + bnc) * 2;
    uint32_t sB1 = (uint32_t)((br0 + 16) * BST + bnc) * 2;

    // ldmatrix per-thread offsets; warp grid 2x4, warp tile 64x32
    int wm = (warp >> 2) * 64, wn = (warp & 3) * 32;
    int lr = lane & 15, lc = lane >> 4;
    uint32_t a_off[4], b_off[2];
    #pragma unroll
    for (int mt = 0; mt < 4; mt++)
        a_off[mt] = (uint32_t)((wm + mt * 16 + lr) * AST + lc * 8) * 2;
    #pragma unroll
    for (int nt = 0; nt < 2; nt++)
        b_off[nt] = (uint32_t)(lr * BST + wn + nt * 16 + lc * 8) * 2;

    float acc[4][4][4];
    #pragma unroll
    for (int i = 0; i < 4; i++)
        #pragma unroll
        for (int j = 0; j < 4; j++)
            #pragma unroll
            for (int q = 0; q < 4; q++) acc[i][j][q] = 0.f;

    auto load_stage = [&](int st, int k0) {
        uint32_t sb = sbase + (uint32_t)st * STG_BYTES;
        CP16(sb + sA0, gAh0 + k0);
        CP16(sb + sA1, gAh1 + k0);
        CP16(sb + offAl + sA0, gAl0 + k0);
        CP16(sb + offAl + sA1, gAl1 + k0);
        CP16(sb + offBh + sB0, gBh0 + (size_t)k0 * CCH);
        CP16(sb + offBh + sB1, gBh1 + (size_t)k0 * CCH);
        CP16(sb + offBl + sB0, gBl0 + (size_t)k0 * CCH);
        CP16(sb + offBl + sB1, gBl1 + (size_t)k0 * CCH);
    };

    load_stage(0, 0);
    CP_COMMIT();
    CP_WAIT0();
    __syncthreads();

    for (int it = 0; it < KITERS; it++) {
        if (it + 1 < KITERS) {          // prefetch next stage under the MMAs
            load_stage((it + 1) & 1, (it + 1) * BKK);
            CP_COMMIT();
        }

        uint32_t sb = sbase + (uint32_t)(it & 1) * STG_BYTES;
        #pragma unroll
        for (int ks = 0; ks < 2; ks++) {
            uint32_t bh[2][4], bl[2][4];
            #pragma unroll
            for (int nt = 0; nt < 2; nt++) {
                ldsm_x4_t(bh[nt], sb + offBh + b_off[nt] + ks * (16 * BST * 2));
                ldsm_x4_t(bl[nt], sb + offBl + b_off[nt] + ks * (16 * BST * 2));
            }
            #pragma unroll
            for (int mt = 0; mt < 4; mt++) {
                uint32_t ah[4], al[4];
                ldsm_x4(ah, sb + a_off[mt] + ks * 32);
                ldsm_x4(al, sb + offAl + a_off[mt] + ks * 32);
                #pragma unroll
                for (int n8 = 0; n8 < 4; n8++) {
                    const uint32_t* ph = &bh[n8 >> 1][(n8 & 1) * 2];
                    const uint32_t* pl = &bl[n8 >> 1][(n8 & 1) * 2];
                    mma16816(acc[mt][n8], ah, ph);
                    mma16816(acc[mt][n8], ah, pl);
                    mma16816(acc[mt][n8], al, ph);
                }
            }
        }

        if (it + 1 < KITERS) {
            CP_WAIT0();
            __syncthreads();            // next stage visible; this stage free
        }
    }

    // epilogue
    #pragma unroll
    for (int mt = 0; mt < 4; mt++) {
        int r0g = m0 + wm + mt * 16 + (lane >> 2);
        float mv0 = maskrow[r0g], mv1 = maskrow[r0g + 8];
        float* y0 = Y + (size_t)r0g * CCH;
        float* y1 = y0 + (size_t)8 * CCH;
        #pragma unroll
        for (int n8 = 0; n8 < 4; n8++) {
            int c0g = n0 + wn + n8 * 8 + (lane & 3) * 2;
            float b0 = bias[c0g], b1 = bias[c0g + 1];
            float2 v0, v1;
            v0.x = fmaxf(acc[mt][n8][0] + b0, 0.f) * mv0;
            v0.y = fmaxf(acc[mt][n8][1] + b1, 0.f) * mv0;
            v1.x = fmaxf(acc[mt][n8][2] + b0, 0.f) * mv1;
            v1.y = fmaxf(acc[mt][n8][3] + b1, 0.f) * mv1;
            *(float2*)(y0 + c0g) = v0;
            *(float2*)(y1 + c0g) = v1;
        }
    }
}

// ---------------------------------------------------------------------------
extern "C" void kernel_launch(void* const* d_in, const int* in_sizes, int n_in,
                              void* d_out, int out_size) {
    const float *feats[3] = {}, *masks[3] = {}, *offs[3] = {};
    const float *w[2] = {}, *bias[2] = {}, *ow[2] = {}, *ob[2] = {};
    int wi = 0, bi = 0, owi = 0, obi = 0;
    for (int i = 0; i < n_in; i++) {
        const float* p = (const float*)d_in[i];
        switch (in_sizes[i]) {
            case 8 * 512 * 2048: feats[0] = p; break;
            case 8 * 512 * 1024: feats[1] = p; break;
            case 8 * 512 * 512:  feats[2] = p; break;
            case 8 * 2048:       masks[0] = p; break;
            case 8 * 1024:       masks[1] = p; break;
            case 8 * 512:        masks[2] = p; break;
            case 8 * 3 * 2048:   offs[0] = p; break;
            case 8 * 3 * 1024:   offs[1] = p; break;
            case 8 * 3 * 512:    offs[2] = p; break;
            case 512 * 512 * 3:  if (wi < 2)  w[wi++] = p; break;
            case 512:            if (bi < 2)  bias[bi++] = p; break;
            case 3 * 512 * 3:    if (owi < 2) ow[owi++] = p; break;
            case 3:              if (obi < 2) ob[obi++] = p; break;
            default: break;
        }
    }

    float *xb, *yb, *offa, *offb, *mrow;
    __nv_bfloat16 *Ah, *Al, *Wh, *Wl;
    cudaGetSymbolAddress((void**)&xb, g_x);
    cudaGetSymbolAddress((void**)&yb, g_y);
    cudaGetSymbolAddress((void**)&offa, g_offa);
    cudaGetSymbolAddress((void**)&offb, g_offb);
    cudaGetSymbolAddress((void**)&mrow, g_mrow);
    cudaGetSymbolAddress((void**)&Ah, g_Ah);
    cudaGetSymbolAddress((void**)&Al, g_Al);
    cudaGetSymbolAddress((void**)&Wh, g_Wh);
    cudaGetSymbolAddress((void**)&Wl, g_Wl);
    float* out = (float*)d_out;

    cudaFuncSetAttribute(gemm_mma_kernel,
                         cudaFuncAttributeMaxDynamicSharedMemorySize, GEMM_SMEM);

    {
        int total = 2 * KRED * CCH;
        prep_wsplit_kernel<<<(total + 255) / 256, 256>>>(w[0], w[1], Wh, Wl);
        maskrow_kernel<<<(ROWS_TOTAL + 255) / 256, 256>>>(masks[0], masks[1],
                                                          masks[2], mrow);
    }

    const int Ts[3]    = {2048, 1024, 512};
    const int lbase[3] = {0, LV0, LV01};

    for (int lv = 0; lv < 3; lv++) {
        int T = Ts[lv];
        transpose_kernel<<<dim3(T / 32, CCH / 32, BSZ), dim3(32, 8)>>>(
            feats[lv], xb + (size_t)lbase[lv] * CCH, CCH, T);
    }

    // ---- layer 0 ----
    offset_kernel<true><<<ROWS_TOTAL / 8, 256>>>(xb, offs[0], offs[1], offs[2],
                                                 ow[0], ob[0], offa);
    im2col_split_kernel<<<dim3(ROWS_TOTAL, KT), 128>>>(xb, offa, Ah, Al);
    gemm_mma_kernel<<<dim3(4, ROWS_TOTAL / BMM), 256, GEMM_SMEM>>>(
        Ah, Al, Wh, Wl, bias[0], mrow, yb);

    // ---- layer 1 ----
    offset_kernel<false><<<ROWS_TOTAL / 8, 256>>>(yb, offa, nullptr, nullptr,
                                                  ow[1], ob[1], offb);
    im2col_split_kernel<<<dim3(ROWS_TOTAL, KT), 128>>>(yb, offb, Ah, Al);
    gemm_mma_kernel<<<dim3(4, ROWS_TOTAL / BMM), 256, GEMM_SMEM>>>(
        Ah, Al, Wh + (size_t)KRED * CCH, Wl + (size_t)KRED * CCH,
        bias[1], mrow, xb);

    // outputs
    size_t outBase[3] = {0, (size_t)BSZ * CCH * 2048,
                         (size_t)BSZ * CCH * (2048 + 1024)};
    size_t mb0 = (size_t)BSZ * CCH * 3584;
    size_t maskBase[3] = {mb0, mb0 + (size_t)BSZ * 2048, mb0 + (size_t)BSZ * 3072};
    for (int lv = 0; lv < 3; lv++) {
        int T = Ts[lv];
        transpose_kernel<<<dim3(CCH / 32, T / 32, BSZ), dim3(32, 8)>>>(
            xb + (size_t)lbase[lv] * CCH, out + outBase[lv], T, CCH);
        int nm = BSZ * T;
        maskout_kernel<<<(nm + 255) / 256, 256>>>(masks[lv], out + maskBase[lv], nm);
    }
}

// round 8
// speedup vs baseline: 1.1495x; 1.0144x over previous
#include <cuda_runtime.h>
#include <cuda_bf16.h>
#include <cstdint>

// ---------------------------------------------------------------------------
// FeatureAlign via mma.sync bf16 (HMMA) with fp32->bf16 hi/lo splitting.
//   Y = relu( A(fp32 gathered) @ W(fp32) + b ) * mask
//   A@W ~= Ah@Wh + Ah@Wl + Al@Wh   (fp32 accum)
// GEMM: 8 warps, 2-stage cp.async, occupancy 2.
// Launch order arranged so ncu (-s 5 -c 1) captures the GEMM.
// ---------------------------------------------------------------------------

#define BSZ 8
#define CCH 512
#define KT  3
#define ROWS_TOTAL 28672
#define LV0 16384
#define LV01 24576
#define KRED 1536

// GEMM tiling
#define BMM 128
#define BNN 128
#define BKK 32
#define AST 40                      // A smem row stride (bf16): 32 + 8 pad
#define BST 136                     // B smem row stride: 128 + 8 pad
#define A_ELE (BMM*AST)             // 5120
#define B_ELE (BKK*BST)             // 4352
#define STG_BYTES ((2*A_ELE + 2*B_ELE)*2)   // 37888 B per stage
#define NSTAGE 2
#define GEMM_SMEM (NSTAGE*STG_BYTES)        // 75776 B -> 2 CTAs/SM
#define KITERS (KRED/BKK)           // 48

// scratch (device globals; no runtime allocation allowed)
__device__ float g_x[ROWS_TOTAL * CCH];
__device__ float g_y[ROWS_TOTAL * CCH];
__device__ float g_offa[ROWS_TOTAL * 4];
__device__ float g_offb[ROWS_TOTAL * 4];
__device__ float g_mrow[ROWS_TOTAL];
__device__ __nv_bfloat16 g_Ah[(size_t)ROWS_TOTAL * KRED];
__device__ __nv_bfloat16 g_Al[(size_t)ROWS_TOTAL * KRED];
__device__ __nv_bfloat16 g_Wh[2 * KRED * CCH];
__device__ __nv_bfloat16 g_Wl[2 * KRED * CCH];

// ---------------------------------------------------------------------------
__device__ __forceinline__ uint32_t smem_u32(const void* p) {
    return (uint32_t)__cvta_generic_to_shared(p);
}
#define CP16(sa, gp) \
    asm volatile("cp.async.cg.shared.global [%0], [%1], 16;" :: "r"(sa), "l"(gp))
#define CP_COMMIT() asm volatile("cp.async.commit_group;")
#define CP_WAIT0()  asm volatile("cp.async.wait_group 0;")

__device__ __forceinline__ void ldsm_x4(uint32_t* r, uint32_t a) {
    asm volatile("ldmatrix.sync.aligned.m8n8.x4.shared.b16 {%0,%1,%2,%3}, [%4];"
                 : "=r"(r[0]), "=r"(r[1]), "=r"(r[2]), "=r"(r[3]) : "r"(a));
}
__device__ __forceinline__ void ldsm_x4_t(uint32_t* r, uint32_t a) {
    asm volatile("ldmatrix.sync.aligned.m8n8.x4.trans.shared.b16 {%0,%1,%2,%3}, [%4];"
                 : "=r"(r[0]), "=r"(r[1]), "=r"(r[2]), "=r"(r[3]) : "r"(a));
}
__device__ __forceinline__ void mma16816(float* d, const uint32_t* a,
                                         const uint32_t* b) {
    asm volatile("mma.sync.aligned.m16n8k16.row.col.f32.bf16.bf16.f32 "
                 "{%0,%1,%2,%3}, {%4,%5,%6,%7}, {%8,%9}, {%0,%1,%2,%3};"
                 : "+f"(d[0]), "+f"(d[1]), "+f"(d[2]), "+f"(d[3])
                 : "r"(a[0]), "r"(a[1]), "r"(a[2]), "r"(a[3]), "r"(b[0]), "r"(b[1]));
}

// ---------------------------------------------------------------------------
// prep: weight bf16 hi/lo split + concatenated mask row vector, one kernel.
// Wh/Wl[l][k][n], k = ktap*512 + c ; from w[(n*512 + c)*3 + ktap]
__global__ void prepmask_kernel(const float* __restrict__ w0,
                                const float* __restrict__ w1,
                                const float* __restrict__ m0,
                                const float* __restrict__ m1,
                                const float* __restrict__ m2,
                                __nv_bfloat16* __restrict__ Wh,
                                __nv_bfloat16* __restrict__ Wl,
                                float* __restrict__ mrow) {
    int idx = blockIdx.x * blockDim.x + threadIdx.x;
    if (idx < 2 * KRED * CCH) {
        int n = idx & 511;
        int k = (idx >> 9) % KRED;
        int l = idx / (KRED * CCH);
        int ktap = k >> 9, c = k & 511;
        const float* w = l ? w1 : w0;
        float val = w[(n * CCH + c) * KT + ktap];
        __nv_bfloat16 hi = __float2bfloat16(val);
        Wh[idx] = hi;
        Wl[idx] = __float2bfloat16(val - __bfloat162float(hi));
    } else {
        int m = idx - 2 * KRED * CCH;
        if (m < ROWS_TOTAL)
            mrow[m] = (m < LV0) ? m0[m] : (m < LV01 ? m1[m - LV0] : m2[m - LV01]);
    }
}

// ---------------------------------------------------------------------------
// merged input transpose: feats (B,C,T) per level -> concatenated rows (m, C)
// grid (112, 16, 8): x decodes level + T-tile, y = C-tile, z = batch
__global__ void tin_kernel(const float* __restrict__ f0,
                           const float* __restrict__ f1,
                           const float* __restrict__ f2,
                           float* __restrict__ xb) {
    __shared__ float tile[32][33];
    int xv = blockIdx.x;
    int lv, xs, T, lbase;
    if (xv < 64)      { lv = 0; xs = xv;      T = 2048; lbase = 0;    }
    else if (xv < 96) { lv = 1; xs = xv - 64; T = 1024; lbase = LV0;  }
    else              { lv = 2; xs = xv - 96; T = 512;  lbase = LV01; }
    const float* f = (lv == 0) ? f0 : (lv == 1 ? f1 : f2);
    int b = blockIdx.z;
    int s0 = xs * 32, r0 = blockIdx.y * 32;
    const float* inb = f + (size_t)b * CCH * T;
    float* outb = xb + (size_t)(lbase + b * T) * CCH;
    #pragma unroll
    for (int i = threadIdx.y; i < 32; i += 8)
        tile[i][threadIdx.x] = inb[(size_t)(r0 + i) * T + s0 + threadIdx.x];
    __syncthreads();
    #pragma unroll
    for (int i = threadIdx.y; i < 32; i += 8)
        outb[(size_t)(s0 + i) * CCH + r0 + threadIdx.x] = tile[threadIdx.x][i];
}

// merged output transpose: rows (m, C) -> out (B,C,T) per level slot
// grid (16, 112, 8): x = C-tile, y decodes level + T-tile, z = batch
__global__ void tout_kernel(const float* __restrict__ xb,
                            float* __restrict__ out) {
    __shared__ float tile[32][33];
    int yv = blockIdx.y;
    int lv, ys, T, lbase;
    size_t obase;
    if (yv < 64)      { lv = 0; ys = yv;      T = 2048; lbase = 0;
                        obase = 0; }
    else if (yv < 96) { lv = 1; ys = yv - 64; T = 1024; lbase = LV0;
                        obase = (size_t)BSZ * CCH * 2048; }
    else              { lv = 2; ys = yv - 96; T = 512;  lbase = LV01;
                        obase = (size_t)BSZ * CCH * (2048 + 1024); }
    int b = blockIdx.z;
    int r0 = ys * 32;                 // over T (rows of input)
    int s0 = blockIdx.x * 32;         // over CCH
    const float* inb = xb + (size_t)(lbase + b * T) * CCH;
    float* outb = out + obase + (size_t)b * CCH * T;
    #pragma unroll
    for (int i = threadIdx.y; i < 32; i += 8)
        tile[i][threadIdx.x] = inb[(size_t)(r0 + i) * CCH + s0 + threadIdx.x];
    __syncthreads();
    #pragma unroll
    for (int i = threadIdx.y; i < 32; i += 8)
        outb[(size_t)(s0 + i) * T + r0 + threadIdx.x] = tile[threadIdx.x][i];
}

// merged bool-mask outputs: out[mb0 + m] = mrow[m] != 0
__global__ void maskoutall_kernel(const float* __restrict__ mrow,
                                  float* __restrict__ out) {
    int m = blockIdx.x * 256 + threadIdx.x;
    if (m < ROWS_TOTAL)
        out[(size_t)BSZ * CCH * 3584 + m] = (mrow[m] != 0.f) ? 1.0f : 0.0f;
}

// ---------------------------------------------------------------------------
// offset conv over ALL levels in one launch: block = 8 consecutive rows.
template <bool EXT>
__global__ void offset_kernel(const float* __restrict__ X,
                              const float* __restrict__ o0,
                              const float* __restrict__ o1,
                              const float* __restrict__ o2,
                              const float* __restrict__ ow,
                              const float* __restrict__ ob,
                              float* __restrict__ off_out) {
    __shared__ float ow_sh2[KT * KT * CCH];   // 18 KB
    __shared__ float xs[10 * CCH];            // 20 KB
    int tid = threadIdx.x;

    int rl0g = blockIdx.x * 8;
    int lv = (rl0g < LV0) ? 0 : (rl0g < LV01 ? 1 : 2);
    int lbase = (lv == 0) ? 0 : (lv == 1 ? LV0 : LV01);
    int logT = 11 - lv;
    int T = 1 << logT;
    int rl0 = rl0g - lbase;
    const float* Xl = X + (size_t)lbase * CCH;

    for (int i = tid; i < KT * KT * CCH; i += 256) {
        int j = i % 3;
        int r = i / 3;
        int kk = r >> 9, c = r & 511;
        ow_sh2[(kk * 3 + j) * CCH + c] = ow[i];
    }

    int t0 = rl0 & (T - 1);
    #pragma unroll
    for (int q = 0; q < 5; q++) {
        int fi = tid + q * 256;
        int j = fi >> 7;
        int cf = (fi & 127) * 4;
        int t = t0 + j - 1;
        float4 v = make_float4(0.f, 0.f, 0.f, 0.f);
        if (t >= 0 && t < T)
            v = *(const float4*)(Xl + (size_t)(rl0 - 1 + j) * CCH + cf);
        *(float4*)(xs + j * CCH + cf) = v;
    }
    __syncthreads();

    int warp = tid >> 5, lane = tid & 31;
    int rl = rl0 + warp;
    int b = rl >> logT, t = rl & (T - 1);
    int m = rl0g + warp;

    float a0 = 0.f, a1 = 0.f, a2 = 0.f;
    #pragma unroll
    for (int q = 0; q < 4; q++) {
        int c = lane * 4 + q * 128;
        float4 vm = *(const float4*)(xs + warp * CCH + c);
        float4 v0 = *(const float4*)(xs + (warp + 1) * CCH + c);
        float4 vp = *(const float4*)(xs + (warp + 2) * CCH + c);
        #pragma unroll
        for (int kk = 0; kk < 3; kk++) {
            float4 wmv = *(const float4*)(ow_sh2 + (kk * 3 + 0) * CCH + c);
            float4 w0v = *(const float4*)(ow_sh2 + (kk * 3 + 1) * CCH + c);
            float4 wpv = *(const float4*)(ow_sh2 + (kk * 3 + 2) * CCH + c);
            float s = wmv.x * vm.x + wmv.y * vm.y + wmv.z * vm.z + wmv.w * vm.w
                    + w0v.x * v0.x + w0v.y * v0.y + w0v.z * v0.z + w0v.w * v0.w
                    + wpv.x * vp.x + wpv.y * vp.y + wpv.z * vp.z + wpv.w * vp.w;
            if (kk == 0) a0 += s; else if (kk == 1) a1 += s; else a2 += s;
        }
    }
    #pragma unroll
    for (int s = 16; s; s >>= 1) {
        a0 += __shfl_down_sync(0xffffffffu, a0, s);
        a1 += __shfl_down_sync(0xffffffffu, a1, s);
        a2 += __shfl_down_sync(0xffffffffu, a2, s);
    }
    if (lane == 0) {
        float i0, i1, i2;
        if (EXT) {
            const float* oin = (lv == 0) ? o0 : (lv == 1 ? o1 : o2);
            i0 = oin[((size_t)b * KT + 0) * T + t];
            i1 = oin[((size_t)b * KT + 1) * T + t];
            i2 = oin[((size_t)b * KT + 2) * T + t];
        } else {
            i0 = o0[(size_t)m * 4 + 0];
            i1 = o0[(size_t)m * 4 + 1];
            i2 = o0[(size_t)m * 4 + 2];
        }
        off_out[(size_t)m * 4 + 0] = a0 + ob[0] + i0;
        off_out[(size_t)m * 4 + 1] = a1 + ob[1] + i1;
        off_out[(size_t)m * 4 + 2] = a2 + ob[2] + i2;
    }
}

// ---------------------------------------------------------------------------
// im2col gather + lerp + bf16 hi/lo split. grid (ROWS_TOTAL, 3), block 128.
__global__ void im2col_split_kernel(const float* __restrict__ X,
                                    const float* __restrict__ OFF,
                                    __nv_bfloat16* __restrict__ Ah,
                                    __nv_bfloat16* __restrict__ Al) {
    int m = blockIdx.x, k = blockIdx.y;
    int lv = (m < LV0) ? 0 : (m < LV01 ? 1 : 2);
    int lbase = (lv == 0) ? 0 : (lv == 1 ? LV0 : LV01);
    int logT = 11 - lv;
    int T = 1 << logT;
    int rl = m - lbase;
    int b = rl >> logT, t = rl & (T - 1);

    float off = OFF[(size_t)m * 4 + k];
    float pos = (float)(t + k - 1) + off;
    float p0f = floorf(pos);
    float f = pos - p0f;
    int i0 = (int)p0f, i1 = i0 + 1;
    float w0 = (i0 >= 0 && i0 < T) ? (1.0f - f) : 0.0f;
    float w1 = (i1 >= 0 && i1 < T) ? f : 0.0f;
    int i0c = min(max(i0, 0), T - 1);
    int i1c = min(max(i1, 0), T - 1);

    size_t rb = (size_t)lbase + ((size_t)b << logT);
    const float4* r0 = (const float4*)(X + (rb + i0c) * CCH);
    const float4* r1 = (const float4*)(X + (rb + i1c) * CCH);

    int i = threadIdx.x;
    float4 a = r0[i], c = r1[i];
    float e0 = w0 * a.x + w1 * c.x;
    float e1 = w0 * a.y + w1 * c.y;
    float e2 = w0 * a.z + w1 * c.z;
    float e3 = w0 * a.w + w1 * c.w;

    __nv_bfloat162 h01 = __floats2bfloat162_rn(e0, e1);
    __nv_bfloat162 h23 = __floats2bfloat162_rn(e2, e3);
    float2 f01 = __bfloat1622float2(h01);
    float2 f23 = __bfloat1622float2(h23);
    __nv_bfloat162 l01 = __floats2bfloat162_rn(e0 - f01.x, e1 - f01.y);
    __nv_bfloat162 l23 = __floats2bfloat162_rn(e2 - f23.x, e3 - f23.y);

    size_t base = (size_t)m * KRED + (size_t)k * CCH + i * 4;
    uint2 hv, lvv;
    hv.x = *reinterpret_cast<uint32_t*>(&h01);
    hv.y = *reinterpret_cast<uint32_t*>(&h23);
    lvv.x = *reinterpret_cast<uint32_t*>(&l01);
    lvv.y = *reinterpret_cast<uint32_t*>(&l23);
    *(uint2*)(Ah + base) = hv;
    *(uint2*)(Al + base) = lvv;
}

// ---------------------------------------------------------------------------
// GEMM: Y[m,n] = relu( (Ah@Wh + Ah@Wl + Al@Wh)[m,n] + bias[n] ) * maskrow[m]
// grid (4, 224), 256 threads (8 warps, warp tile 64x32), 2-stage, occ 2.
__global__ __launch_bounds__(256, 2)
void gemm_mma_kernel(const __nv_bfloat16* __restrict__ Ahg,
                     const __nv_bfloat16* __restrict__ Alg,
                     const __nv_bfloat16* __restrict__ Whg,
                     const __nv_bfloat16* __restrict__ Wlg,
                     const float* __restrict__ bias,
                     const float* __restrict__ maskrow,
                     float* __restrict__ Y) {
    extern __shared__ __nv_bfloat16 sm[];
    uint32_t sbase = smem_u32(sm);
    int tid = threadIdx.x, warp = tid >> 5, lane = tid & 31;
    int m0 = blockIdx.y * BMM, n0 = blockIdx.x * BNN;

    const uint32_t offAl = A_ELE * 2;
    const uint32_t offBh = 2 * A_ELE * 2;
    const uint32_t offBl = offBh + B_ELE * 2;

    int ar0 = tid >> 2, akc = (tid & 3) * 8;
    int br0 = tid >> 4, bnc = (tid & 15) * 8;
    const __nv_bfloat16* gAh0 = Ahg + (size_t)(m0 + ar0) * KRED + akc;
    const __nv_bfloat16* gAh1 = Ahg + (size_t)(m0 + ar0 + 64) * KRED + akc;
    const __nv_bfloat16* gAl0 = Alg + (size_t)(m0 + ar0) * KRED + akc;
    const __nv_bfloat16* gAl1 = Alg + (size_t)(m0 + ar0 + 64) * KRED + akc;
    const __nv_bfloat16* gBh0 = Whg + (size_t)br0 * CCH + n0 + bnc;
    const __nv_bfloat16* gBh1 = Whg + (size_t)(br0 + 16) * CCH + n0 + bnc;
    const __nv_bfloat16* gBl0 = Wlg + (size_t)br0 * CCH + n0 + bnc;
    const __nv_bfloat16* gBl1 = Wlg + (size_t)(br0 + 16) * CCH + n0 + bnc;
    uint32_t sA0 = (uint32_t)(ar0 * AST + akc) * 2;
    uint32_t sA1 = (uint32_t)((ar0 + 64) * AST + akc) * 2;
    uint32_t sB0 = (uint32_t)(br0 * BST + bnc) * 2;
    uint32_t sB1 = (uint32_t)((br0 + 16) * BST + bnc) * 2;

    int wm = (warp >> 2) * 64, wn = (warp & 3) * 32;
    int lr = lane & 15, lc = lane >> 4;
    uint32_t a_off[4], b_off[2];
    #pragma unroll
    for (int mt = 0; mt < 4; mt++)
        a_off[mt] = (uint32_t)((wm + mt * 16 + lr) * AST + lc * 8) * 2;
    #pragma unroll
    for (int nt = 0; nt < 2; nt++)
        b_off[nt] = (uint32_t)(lr * BST + wn + nt * 16 + lc * 8) * 2;

    float acc[4][4][4];
    #pragma unroll
    for (int i = 0; i < 4; i++)
        #pragma unroll
        for (int j = 0; j < 4; j++)
            #pragma unroll
            for (int q = 0; q < 4; q++) acc[i][j][q] = 0.f;

    auto load_stage = [&](int st, int k0) {
        uint32_t sb = sbase + (uint32_t)st * STG_BYTES;
        CP16(sb + sA0, gAh0 + k0);
        CP16(sb + sA1, gAh1 + k0);
        CP16(sb + offAl + sA0, gAl0 + k0);
        CP16(sb + offAl + sA1, gAl1 + k0);
        CP16(sb + offBh + sB0, gBh0 + (size_t)k0 * CCH);
        CP16(sb + offBh + sB1, gBh1 + (size_t)k0 * CCH);
        CP16(sb + offBl + sB0, gBl0 + (size_t)k0 * CCH);
        CP16(sb + offBl + sB1, gBl1 + (size_t)k0 * CCH);
    };

    load_stage(0, 0);
    CP_COMMIT();
    CP_WAIT0();
    __syncthreads();

    for (int it = 0; it < KITERS; it++) {
        if (it + 1 < KITERS) {
            load_stage((it + 1) & 1, (it + 1) * BKK);
            CP_COMMIT();
        }

        uint32_t sb = sbase + (uint32_t)(it & 1) * STG_BYTES;
        #pragma unroll
        for (int ks = 0; ks < 2; ks++) {
            uint32_t bh[2][4], bl[2][4];
            #pragma unroll
            for (int nt = 0; nt < 2; nt++) {
                ldsm_x4_t(bh[nt], sb + offBh + b_off[nt] + ks * (16 * BST * 2));
                ldsm_x4_t(bl[nt], sb + offBl + b_off[nt] + ks * (16 * BST * 2));
            }
            #pragma unroll
            for (int mt = 0; mt < 4; mt++) {
                uint32_t ah[4], al[4];
                ldsm_x4(ah, sb + a_off[mt] + ks * 32);
                ldsm_x4(al, sb + offAl + a_off[mt] + ks * 32);
                #pragma unroll
                for (int n8 = 0; n8 < 4; n8++) {
                    const uint32_t* ph = &bh[n8 >> 1][(n8 & 1) * 2];
                    const uint32_t* pl = &bl[n8 >> 1][(n8 & 1) * 2];
                    mma16816(acc[mt][n8], ah, ph);
                    mma16816(acc[mt][n8], ah, pl);
                    mma16816(acc[mt][n8], al, ph);
                }
            }
        }

        if (it + 1 < KITERS) {
            CP_WAIT0();
            __syncthreads();
        }
    }

    #pragma unroll
    for (int mt = 0; mt < 4; mt++) {
        int r0g = m0 + wm + mt * 16 + (lane >> 2);
        float mv0 = maskrow[r0g], mv1 = maskrow[r0g + 8];
        float* y0 = Y + (size_t)r0g * CCH;
        float* y1 = y0 + (size_t)8 * CCH;
        #pragma unroll
        for (int n8 = 0; n8 < 4; n8++) {
            int c0g = n0 + wn + n8 * 8 + (lane & 3) * 2;
            float b0 = bias[c0g], b1 = bias[c0g + 1];
            float2 v0, v1;
            v0.x = fmaxf(acc[mt][n8][0] + b0, 0.f) * mv0;
            v0.y = fmaxf(acc[mt][n8][1] + b1, 0.f) * mv0;
            v1.x = fmaxf(acc[mt][n8][2] + b0, 0.f) * mv1;
            v1.y = fmaxf(acc[mt][n8][3] + b1, 0.f) * mv1;
            *(float2*)(y0 + c0g) = v0;
            *(float2*)(y1 + c0g) = v1;
        }
    }
}

// ---------------------------------------------------------------------------
extern "C" void kernel_launch(void* const* d_in, const int* in_sizes, int n_in,
                              void* d_out, int out_size) {
    const float *feats[3] = {}, *masks[3] = {}, *offs[3] = {};
    const float *w[2] = {}, *bias[2] = {}, *ow[2] = {}, *ob[2] = {};
    int wi = 0, bi = 0, owi = 0, obi = 0;
    for (int i = 0; i < n_in; i++) {
        const float* p = (const float*)d_in[i];
        switch (in_sizes[i]) {
            case 8 * 512 * 2048: feats[0] = p; break;
            case 8 * 512 * 1024: feats[1] = p; break;
            case 8 * 512 * 512:  feats[2] = p; break;
            case 8 * 2048:       masks[0] = p; break;
            case 8 * 1024:       masks[1] = p; break;
            case 8 * 512:        masks[2] = p; break;
            case 8 * 3 * 2048:   offs[0] = p; break;
            case 8 * 3 * 1024:   offs[1] = p; break;
            case 8 * 3 * 512:    offs[2] = p; break;
            case 512 * 512 * 3:  if (wi < 2)  w[wi++] = p; break;
            case 512:            if (bi < 2)  bias[bi++] = p; break;
            case 3 * 512 * 3:    if (owi < 2) ow[owi++] = p; break;
            case 3:              if (obi < 2) ob[obi++] = p; break;
            default: break;
        }
    }

    float *xb, *yb, *offa, *offb, *mrow;
    __nv_bfloat16 *Ah, *Al, *Wh, *Wl;
    cudaGetSymbolAddress((void**)&xb, g_x);
    cudaGetSymbolAddress((void**)&yb, g_y);
    cudaGetSymbolAddress((void**)&offa, g_offa);
    cudaGetSymbolAddress((void**)&offb, g_offb);
    cudaGetSymbolAddress((void**)&mrow, g_mrow);
    cudaGetSymbolAddress((void**)&Ah, g_Ah);
    cudaGetSymbolAddress((void**)&Al, g_Al);
    cudaGetSymbolAddress((void**)&Wh, g_Wh);
    cudaGetSymbolAddress((void**)&Wl, g_Wl);
    float* out = (float*)d_out;

    cudaFuncSetAttribute(gemm_mma_kernel,
                         cudaFuncAttributeMaxDynamicSharedMemorySize, GEMM_SMEM);

    // launch 0: weight split + mask rows
    {
        int total = 2 * KRED * CCH + ROWS_TOTAL;
        prepmask_kernel<<<(total + 255) / 256, 256>>>(
            w[0], w[1], masks[0], masks[1], masks[2], Wh, Wl, mrow);
    }
    // launch 1: merged input transposes
    tin_kernel<<<dim3(112, 16, 8), dim3(32, 8)>>>(feats[0], feats[1], feats[2], xb);
    // launch 2: merged bool-mask outputs
    maskoutall_kernel<<<(ROWS_TOTAL + 255) / 256, 256>>>(mrow, out);

    // ---- layer 0 ----  (launches 3,4,5 — ncu -s 5 captures the GEMM)
    offset_kernel<true><<<ROWS_TOTAL / 8, 256>>>(xb, offs[0], offs[1], offs[2],
                                                 ow[0], ob[0], offa);
    im2col_split_kernel<<<dim3(ROWS_TOTAL, KT), 128>>>(xb, offa, Ah, Al);
    gemm_mma_kernel<<<dim3(4, ROWS_TOTAL / BMM), 256, GEMM_SMEM>>>(
        Ah, Al, Wh, Wl, bias[0], mrow, yb);

    // ---- layer 1 ----
    offset_kernel<false><<<ROWS_TOTAL / 8, 256>>>(yb, offa, nullptr, nullptr,
                                                  ow[1], ob[1], offb);
    im2col_split_kernel<<<dim3(ROWS_TOTAL, KT), 128>>>(yb, offb, Ah, Al);
    gemm_mma_kernel<<<dim3(4, ROWS_TOTAL / BMM), 256, GEMM_SMEM>>>(
        Ah, Al, Wh + (size_t)KRED * CCH, Wl + (size_t)KRED * CCH,
        bias[1], mrow, xb);

    // merged output transpose
    tout_kernel<<<dim3(16, 112, 8), dim3(32, 8)>>>(xb, out);
}

// round 9
// speedup vs baseline: 1.1608x; 1.0098x over previous
#include <cuda_runtime.h>
#include <cuda_bf16.h>
#include <cstdint>

// ---------------------------------------------------------------------------
// FeatureAlign via mma.sync bf16 (HMMA) with fp32->bf16 hi/lo splitting.
//   Y = relu( A(fp32 gathered) @ W(fp32) + b ) * mask
//   A@W ~= Ah@Wh + Ah@Wl + Al@Wh   (fp32 accum)
// GEMM: 8 warps, 2-stage cp.async, occupancy 2.  Launch order puts the GEMM
// at index 3 (the launch ncu captures).
// ---------------------------------------------------------------------------

#define BSZ 8
#define CCH 512
#define KT  3
#define ROWS_TOTAL 28672
#define LV0 16384
#define LV01 24576
#define KRED 1536

// GEMM tiling
#define BMM 128
#define BNN 128
#define BKK 32
#define AST 40                      // A smem row stride (bf16): 32 + 8 pad
#define BST 136                     // B smem row stride: 128 + 8 pad
#define A_ELE (BMM*AST)             // 5120
#define B_ELE (BKK*BST)             // 4352
#define STG_BYTES ((2*A_ELE + 2*B_ELE)*2)   // 37888 B per stage
#define NSTAGE 2
#define GEMM_SMEM (NSTAGE*STG_BYTES)        // 75776 B -> 2 CTAs/SM
#define KITERS (KRED/BKK)           // 48

// offset kernel smem: 34 staged rows + transposed weights
#define OFF_XS_FLOATS (34*CCH)              // 17408
#define OFF_SMEM ((OFF_XS_FLOATS + KT*KT*CCH) * 4)   // 88064 B

// prep_all grid regions
#define TIN_BLOCKS 14336                    // 112*16*8
#define WSPLIT_TOTAL (2*KRED*CCH + ROWS_TOTAL)
#define PREP_BLOCKS (TIN_BLOCKS + (WSPLIT_TOTAL + 255)/256)

// scratch (device globals; no runtime allocation allowed)
__device__ float g_x[ROWS_TOTAL * CCH];
__device__ float g_y[ROWS_TOTAL * CCH];
__device__ float g_offa[ROWS_TOTAL * 4];
__device__ float g_offb[ROWS_TOTAL * 4];
__device__ float g_mrow[ROWS_TOTAL];
__device__ __nv_bfloat16 g_Ah[(size_t)ROWS_TOTAL * KRED];
__device__ __nv_bfloat16 g_Al[(size_t)ROWS_TOTAL * KRED];
__device__ __nv_bfloat16 g_Wh[2 * KRED * CCH];
__device__ __nv_bfloat16 g_Wl[2 * KRED * CCH];

// ---------------------------------------------------------------------------
__device__ __forceinline__ uint32_t smem_u32(const void* p) {
    return (uint32_t)__cvta_generic_to_shared(p);
}
#define CP16(sa, gp) \
    asm volatile("cp.async.cg.shared.global [%0], [%1], 16;" :: "r"(sa), "l"(gp))
#define CP_COMMIT() asm volatile("cp.async.commit_group;")
#define CP_WAIT0()  asm volatile("cp.async.wait_group 0;")

__device__ __forceinline__ void ldsm_x4(uint32_t* r, uint32_t a) {
    asm volatile("ldmatrix.sync.aligned.m8n8.x4.shared.b16 {%0,%1,%2,%3}, [%4];"
                 : "=r"(r[0]), "=r"(r[1]), "=r"(r[2]), "=r"(r[3]) : "r"(a));
}
__device__ __forceinline__ void ldsm_x4_t(uint32_t* r, uint32_t a) {
    asm volatile("ldmatrix.sync.aligned.m8n8.x4.trans.shared.b16 {%0,%1,%2,%3}, [%4];"
                 : "=r"(r[0]), "=r"(r[1]), "=r"(r[2]), "=r"(r[3]) : "r"(a));
}
__device__ __forceinline__ void mma16816(float* d, const uint32_t* a,
                                         const uint32_t* b) {
    asm volatile("mma.sync.aligned.m16n8k16.row.col.f32.bf16.bf16.f32 "
                 "{%0,%1,%2,%3}, {%4,%5,%6,%7}, {%8,%9}, {%0,%1,%2,%3};"
                 : "+f"(d[0]), "+f"(d[1]), "+f"(d[2]), "+f"(d[3])
                 : "r"(a[0]), "r"(a[1]), "r"(a[2]), "r"(a[3]), "r"(b[0]), "r"(b[1]));
}

// ---------------------------------------------------------------------------
// prep_all: merged input transposes + weight bf16 hi/lo split + mask rows.
// Region A (blocks [0, TIN_BLOCKS)): transpose feats (B,C,T) -> rows (m,C).
// Region B: elementwise weight split / maskrow.
__global__ void prep_all_kernel(const float* __restrict__ f0,
                                const float* __restrict__ f1,
                                const float* __restrict__ f2,
                                const float* __restrict__ w0,
                                const float* __restrict__ w1,
                                const float* __restrict__ m0,
                                const float* __restrict__ m1,
                                const float* __restrict__ m2,
                                float* __restrict__ xb,
                                __nv_bfloat16* __restrict__ Wh,
                                __nv_bfloat16* __restrict__ Wl,
                                float* __restrict__ mrow) {
    __shared__ float tile[32][33];
    int bid = blockIdx.x, tid = threadIdx.x;
    if (bid < TIN_BLOCKS) {
        int xv = bid % 112;
        int y  = (bid / 112) % 16;
        int b  = bid / (112 * 16);
        int lv, xs, T, lbase;
        if (xv < 64)      { lv = 0; xs = xv;      T = 2048; lbase = 0;    }
        else if (xv < 96) { lv = 1; xs = xv - 64; T = 1024; lbase = LV0;  }
        else              { lv = 2; xs = xv - 96; T = 512;  lbase = LV01; }
        const float* f = (lv == 0) ? f0 : (lv == 1 ? f1 : f2);
        int tx = tid & 31, ty = tid >> 5;
        int s0 = xs * 32, r0 = y * 32;
        const float* inb = f + (size_t)b * CCH * T;
        float* outb = xb + (size_t)(lbase + b * T) * CCH;
        #pragma unroll
        for (int i = ty; i < 32; i += 8)
            tile[i][tx] = inb[(size_t)(r0 + i) * T + s0 + tx];
        __syncthreads();
        #pragma unroll
        for (int i = ty; i < 32; i += 8)
            outb[(size_t)(s0 + i) * CCH + r0 + tx] = tile[tx][i];
    } else {
        int idx = (bid - TIN_BLOCKS) * 256 + tid;
        if (idx < 2 * KRED * CCH) {
            int n = idx & 511;
            int k = (idx >> 9) % KRED;
            int l = idx / (KRED * CCH);
            int ktap = k >> 9, c = k & 511;
            const float* w = l ? w1 : w0;
            float val = w[(n * CCH + c) * KT + ktap];
            __nv_bfloat16 hi = __float2bfloat16(val);
            Wh[idx] = hi;
            Wl[idx] = __float2bfloat16(val - __bfloat162float(hi));
        } else if (idx < WSPLIT_TOTAL) {
            int m = idx - 2 * KRED * CCH;
            mrow[m] = (m < LV0) ? m0[m] : (m < LV01 ? m1[m - LV0] : m2[m - LV01]);
        }
    }
}

// ---------------------------------------------------------------------------
// merged output transpose: rows (m, C) -> out (B,C,T) per level slot
__global__ void tout_kernel(const float* __restrict__ xb,
                            float* __restrict__ out) {
    __shared__ float tile[32][33];
    int yv = blockIdx.y;
    int ys, T, lbase;
    size_t obase;
    if (yv < 64)      { ys = yv;      T = 2048; lbase = 0;
                        obase = 0; }
    else if (yv < 96) { ys = yv - 64; T = 1024; lbase = LV0;
                        obase = (size_t)BSZ * CCH * 2048; }
    else              { ys = yv - 96; T = 512;  lbase = LV01;
                        obase = (size_t)BSZ * CCH * (2048 + 1024); }
    int b = blockIdx.z;
    int r0 = ys * 32;
    int s0 = blockIdx.x * 32;
    const float* inb = xb + (size_t)(lbase + b * T) * CCH;
    float* outb = out + obase + (size_t)b * CCH * T;
    #pragma unroll
    for (int i = threadIdx.y; i < 32; i += 8)
        tile[i][threadIdx.x] = inb[(size_t)(r0 + i) * CCH + s0 + threadIdx.x];
    __syncthreads();
    #pragma unroll
    for (int i = threadIdx.y; i < 32; i += 8)
        outb[(size_t)(s0 + i) * T + r0 + threadIdx.x] = tile[threadIdx.x][i];
}

__global__ void maskoutall_kernel(const float* __restrict__ mrow,
                                  float* __restrict__ out) {
    int m = blockIdx.x * 256 + threadIdx.x;
    if (m < ROWS_TOTAL)
        out[(size_t)BSZ * CCH * 3584 + m] = (mrow[m] != 0.f) ? 1.0f : 0.0f;
}

// ---------------------------------------------------------------------------
// offset conv: 32 rows/block, 4 rows/warp; weights+x held in regs per q-chunk.
template <bool EXT>
__global__ void offset_kernel(const float* __restrict__ X,
                              const float* __restrict__ o0,
                              const float* __restrict__ o1,
                              const float* __restrict__ o2,
                              const float* __restrict__ ow,
                              const float* __restrict__ ob,
                              float* __restrict__ off_out) {
    extern __shared__ float sdyn[];
    float* xs = sdyn;                       // 34*512
    float* ow_sh2 = sdyn + OFF_XS_FLOATS;   // 4608: [(kk*3+j)*512 + c]
    int tid = threadIdx.x;

    int rl0g = blockIdx.x * 32;
    int lv = (rl0g < LV0) ? 0 : (rl0g < LV01 ? 1 : 2);
    int lbase = (lv == 0) ? 0 : (lv == 1 ? LV0 : LV01);
    int logT = 11 - lv;
    int T = 1 << logT;
    int rl0 = rl0g - lbase;
    const float* Xl = X + (size_t)lbase * CCH;

    for (int i = tid; i < KT * KT * CCH; i += 256) {
        int j = i % 3;
        int r = i / 3;
        int kk = r >> 9, c = r & 511;
        ow_sh2[(kk * 3 + j) * CCH + c] = ow[i];
    }

    int t0 = rl0 & (T - 1);
    // stage 34 rows: staged j holds global row rl0 + j - 1 (zero if t out of range)
    for (int fi = tid; fi < 34 * 128; fi += 256) {
        int j = fi >> 7;
        int cf = (fi & 127) * 4;
        int t = t0 + j - 1;
        float4 v = make_float4(0.f, 0.f, 0.f, 0.f);
        if (t >= 0 && t < T)
            v = *(const float4*)(Xl + (size_t)(rl0 - 1 + j) * CCH + cf);
        *(float4*)(xs + j * CCH + cf) = v;
    }
    __syncthreads();

    int warp = tid >> 5, lane = tid & 31;
    int r0l = warp * 4;                     // local row base (0..28)

    float acc[4][3];
    #pragma unroll
    for (int i = 0; i < 4; i++)
        #pragma unroll
        for (int kk = 0; kk < 3; kk++) acc[i][kk] = 0.f;

    #pragma unroll
    for (int q = 0; q < 4; q++) {
        int c = lane * 4 + q * 128;
        float4 wv[3][3];
        #pragma unroll
        for (int kk = 0; kk < 3; kk++)
            #pragma unroll
            for (int j = 0; j < 3; j++)
                wv[kk][j] = *(const float4*)(ow_sh2 + (kk * 3 + j) * CCH + c);
        float4 xv[6];
        #pragma unroll
        for (int u = 0; u < 6; u++)
            xv[u] = *(const float4*)(xs + (r0l + u) * CCH + c);
        #pragma unroll
        for (int i = 0; i < 4; i++) {
            #pragma unroll
            for (int kk = 0; kk < 3; kk++) {
                float s = 0.f;
                #pragma unroll
                for (int j = 0; j < 3; j++) {
                    float4 wf = wv[kk][j];
                    float4 xf = xv[i + j];
                    s += wf.x * xf.x + wf.y * xf.y + wf.z * xf.z + wf.w * xf.w;
                }
                acc[i][kk] += s;
            }
        }
    }

    #pragma unroll
    for (int i = 0; i < 4; i++)
        #pragma unroll
        for (int kk = 0; kk < 3; kk++)
            #pragma unroll
            for (int s = 16; s; s >>= 1)
                acc[i][kk] += __shfl_down_sync(0xffffffffu, acc[i][kk], s);

    if (lane == 0) {
        #pragma unroll
        for (int i = 0; i < 4; i++) {
            int rl = rl0 + r0l + i;
            int b = rl >> logT, t = rl & (T - 1);
            int m = rl0g + r0l + i;
            float i0, i1, i2;
            if (EXT) {
                const float* oin = (lv == 0) ? o0 : (lv == 1 ? o1 : o2);
                i0 = oin[((size_t)b * KT + 0) * T + t];
                i1 = oin[((size_t)b * KT + 1) * T + t];
                i2 = oin[((size_t)b * KT + 2) * T + t];
            } else {
                i0 = o0[(size_t)m * 4 + 0];
                i1 = o0[(size_t)m * 4 + 1];
                i2 = o0[(size_t)m * 4 + 2];
            }
            off_out[(size_t)m * 4 + 0] = acc[i][0] + ob[0] + i0;
            off_out[(size_t)m * 4 + 1] = acc[i][1] + ob[1] + i1;
            off_out[(size_t)m * 4 + 2] = acc[i][2] + ob[2] + i2;
        }
    }
}

// ---------------------------------------------------------------------------
// im2col gather + lerp + bf16 hi/lo split. grid (ROWS_TOTAL, 3), block 128.
__global__ void im2col_split_kernel(const float* __restrict__ X,
                                    const float* __restrict__ OFF,
                                    __nv_bfloat16* __restrict__ Ah,
                                    __nv_bfloat16* __restrict__ Al) {
    int m = blockIdx.x, k = blockIdx.y;
    int lv = (m < LV0) ? 0 : (m < LV01 ? 1 : 2);
    int lbase = (lv == 0) ? 0 : (lv == 1 ? LV0 : LV01);
    int logT = 11 - lv;
    int T = 1 << logT;
    int rl = m - lbase;
    int b = rl >> logT, t = rl & (T - 1);

    float off = OFF[(size_t)m * 4 + k];
    float pos = (float)(t + k - 1) + off;
    float p0f = floorf(pos);
    float f = pos - p0f;
    int i0 = (int)p0f, i1 = i0 + 1;
    float w0 = (i0 >= 0 && i0 < T) ? (1.0f - f) : 0.0f;
    float w1 = (i1 >= 0 && i1 < T) ? f : 0.0f;
    int i0c = min(max(i0, 0), T - 1);
    int i1c = min(max(i1, 0), T - 1);

    size_t rb = (size_t)lbase + ((size_t)b << logT);
    const float4* r0 = (const float4*)(X + (rb + i0c) * CCH);
    const float4* r1 = (const float4*)(X + (rb + i1c) * CCH);

    int i = threadIdx.x;
    float4 a = r0[i], c = r1[i];
    float e0 = w0 * a.x + w1 * c.x;
    float e1 = w0 * a.y + w1 * c.y;
    float e2 = w0 * a.z + w1 * c.z;
    float e3 = w0 * a.w + w1 * c.w;

    __nv_bfloat162 h01 = __floats2bfloat162_rn(e0, e1);
    __nv_bfloat162 h23 = __floats2bfloat162_rn(e2, e3);
    float2 f01 = __bfloat1622float2(h01);
    float2 f23 = __bfloat1622float2(h23);
    __nv_bfloat162 l01 = __floats2bfloat162_rn(e0 - f01.x, e1 - f01.y);
    __nv_bfloat162 l23 = __floats2bfloat162_rn(e2 - f23.x, e3 - f23.y);

    size_t base = (size_t)m * KRED + (size_t)k * CCH + i * 4;
    uint2 hv, lvv;
    hv.x = *reinterpret_cast<uint32_t*>(&h01);
    hv.y = *reinterpret_cast<uint32_t*>(&h23);
    lvv.x = *reinterpret_cast<uint32_t*>(&l01);
    lvv.y = *reinterpret_cast<uint32_t*>(&l23);
    *(uint2*)(Ah + base) = hv;
    *(uint2*)(Al + base) = lvv;
}

// ---------------------------------------------------------------------------
// GEMM: Y[m,n] = relu( (Ah@Wh + Ah@Wl + Al@Wh)[m,n] + bias[n] ) * maskrow[m]
// grid (4, 224), 256 threads (8 warps, warp tile 64x32), 2-stage, occ 2.
__global__ __launch_bounds__(256, 2)
void gemm_mma_kernel(const __nv_bfloat16* __restrict__ Ahg,
                     const __nv_bfloat16* __restrict__ Alg,
                     const __nv_bfloat16* __restrict__ Whg,
                     const __nv_bfloat16* __restrict__ Wlg,
                     const float* __restrict__ bias,
                     const float* __restrict__ maskrow,
                     float* __restrict__ Y) {
    extern __shared__ __nv_bfloat16 sm[];
    uint32_t sbase = smem_u32(sm);
    int tid = threadIdx.x, warp = tid >> 5, lane = tid & 31;
    int m0 = blockIdx.y * BMM, n0 = blockIdx.x * BNN;

    const uint32_t offAl = A_ELE * 2;
    const uint32_t offBh = 2 * A_ELE * 2;
    const uint32_t offBl = offBh + B_ELE * 2;

    int ar0 = tid >> 2, akc = (tid & 3) * 8;
    int br0 = tid >> 4, bnc = (tid & 15) * 8;
    const __nv_bfloat16* gAh0 = Ahg + (size_t)(m0 + ar0) * KRED + akc;
    const __nv_bfloat16* gAh1 = Ahg + (size_t)(m0 + ar0 + 64) * KRED + akc;
    const __nv_bfloat16* gAl0 = Alg + (size_t)(m0 + ar0) * KRED + akc;
    const __nv_bfloat16* gAl1 = Alg + (size_t)(m0 + ar0 + 64) * KRED + akc;
    const __nv_bfloat16* gBh0 = Whg + (size_t)br0 * CCH + n0 + bnc;
    const __nv_bfloat16* gBh1 = Whg + (size_t)(br0 + 16) * CCH + n0 + bnc;
    const __nv_bfloat16* gBl0 = Wlg + (size_t)br0 * CCH + n0 + bnc;
    const __nv_bfloat16* gBl1 = Wlg + (size_t)(br0 + 16) * CCH + n0 + bnc;
    uint32_t sA0 = (uint32_t)(ar0 * AST + akc) * 2;
    uint32_t sA1 = (uint32_t)((ar0 + 64) * AST + akc) * 2;
    uint32_t sB0 = (uint32_t)(br0 * BST + bnc) * 2;
    uint32_t sB1 = (uint32_t)((br0 + 16) * BST + bnc) * 2;

    int wm = (warp >> 2) * 64, wn = (warp & 3) * 32;
    int lr = lane & 15, lc = lane >> 4;
    uint32_t a_off[4], b_off[2];
    #pragma unroll
    for (int mt = 0; mt < 4; mt++)
        a_off[mt] = (uint32_t)((wm + mt * 16 + lr) * AST + lc * 8) * 2;
    #pragma unroll
    for (int nt = 0; nt < 2; nt++)
        b_off[nt] = (uint32_t)(lr * BST + wn + nt * 16 + lc * 8) * 2;

    float acc[4][4][4];
    #pragma unroll
    for (int i = 0; i < 4; i++)
        #pragma unroll
        for (int j = 0; j < 4; j++)
            #pragma unroll
            for (int q = 0; q < 4; q++) acc[i][j][q] = 0.f;

    auto load_stage = [&](int st, int k0) {
        uint32_t sb = sbase + (uint32_t)st * STG_BYTES;
        CP16(sb + sA0, gAh0 + k0);
        CP16(sb + sA1, gAh1 + k0);
        CP16(sb + offAl + sA0, gAl0 + k0);
        CP16(sb + offAl + sA1, gAl1 + k0);
        CP16(sb + offBh + sB0, gBh0 + (size_t)k0 * CCH);
        CP16(sb + offBh + sB1, gBh1 + (size_t)k0 * CCH);
        CP16(sb + offBl + sB0, gBl0 + (size_t)k0 * CCH);
        CP16(sb + offBl + sB1, gBl1 + (size_t)k0 * CCH);
    };

    load_stage(0, 0);
    CP_COMMIT();
    CP_WAIT0();
    __syncthreads();

    for (int it = 0; it < KITERS; it++) {
        if (it + 1 < KITERS) {
            load_stage((it + 1) & 1, (it + 1) * BKK);
            CP_COMMIT();
        }

        uint32_t sb = sbase + (uint32_t)(it & 1) * STG_BYTES;
        #pragma unroll
        for (int ks = 0; ks < 2; ks++) {
            uint32_t bh[2][4], bl[2][4];
            #pragma unroll
            for (int nt = 0; nt < 2; nt++) {
                ldsm_x4_t(bh[nt], sb + offBh + b_off[nt] + ks * (16 * BST * 2));
                ldsm_x4_t(bl[nt], sb + offBl + b_off[nt] + ks * (16 * BST * 2));
            }
            #pragma unroll
            for (int mt = 0; mt < 4; mt++) {
                uint32_t ah[4], al[4];
                ldsm_x4(ah, sb + a_off[mt] + ks * 32);
                ldsm_x4(al, sb + offAl + a_off[mt] + ks * 32);
                #pragma unroll
                for (int n8 = 0; n8 < 4; n8++) {
                    const uint32_t* ph = &bh[n8 >> 1][(n8 & 1) * 2];
                    const uint32_t* pl = &bl[n8 >> 1][(n8 & 1) * 2];
                    mma16816(acc[mt][n8], ah, ph);
                    mma16816(acc[mt][n8], ah, pl);
                    mma16816(acc[mt][n8], al, ph);
                }
            }
        }

        if (it + 1 < KITERS) {
            CP_WAIT0();
            __syncthreads();
        }
    }

    #pragma unroll
    for (int mt = 0; mt < 4; mt++) {
        int r0g = m0 + wm + mt * 16 + (lane >> 2);
        float mv0 = maskrow[r0g], mv1 = maskrow[r0g + 8];
        float* y0 = Y + (size_t)r0g * CCH;
        float* y1 = y0 + (size_t)8 * CCH;
        #pragma unroll
        for (int n8 = 0; n8 < 4; n8++) {
            int c0g = n0 + wn + n8 * 8 + (lane & 3) * 2;
            float b0 = bias[c0g], b1 = bias[c0g + 1];
            float2 v0, v1;
            v0.x = fmaxf(acc[mt][n8][0] + b0, 0.f) * mv0;
            v0.y = fmaxf(acc[mt][n8][1] + b1, 0.f) * mv0;
            v1.x = fmaxf(acc[mt][n8][2] + b0, 0.f) * mv1;
            v1.y = fmaxf(acc[mt][n8][3] + b1, 0.f) * mv1;
            *(float2*)(y0 + c0g) = v0;
            *(float2*)(y1 + c0g) = v1;
        }
    }
}

// ---------------------------------------------------------------------------
extern "C" void kernel_launch(void* const* d_in, const int* in_sizes, int n_in,
                              void* d_out, int out_size) {
    const float *feats[3] = {}, *masks[3] = {}, *offs[3] = {};
    const float *w[2] = {}, *bias[2] = {}, *ow[2] = {}, *ob[2] = {};
    int wi = 0, bi = 0, owi = 0, obi = 0;
    for (int i = 0; i < n_in; i++) {
        const float* p = (const float*)d_in[i];
        switch (in_sizes[i]) {
            case 8 * 512 * 2048: feats[0] = p; break;
            case 8 * 512 * 1024: feats[1] = p; break;
            case 8 * 512 * 512:  feats[2] = p; break;
            case 8 * 2048:       masks[0] = p; break;
            case 8 * 1024:       masks[1] = p; break;
            case 8 * 512:        masks[2] = p; break;
            case 8 * 3 * 2048:   offs[0] = p; break;
            case 8 * 3 * 1024:   offs[1] = p; break;
            case 8 * 3 * 512:    offs[2] = p; break;
            case 512 * 512 * 3:  if (wi < 2)  w[wi++] = p; break;
            case 512:            if (bi < 2)  bias[bi++] = p; break;
            case 3 * 512 * 3:    if (owi < 2) ow[owi++] = p; break;
            case 3:              if (obi < 2) ob[obi++] = p; break;
            default: break;
        }
    }

    float *xb, *yb, *offa, *offb, *mrow;
    __nv_bfloat16 *Ah, *Al, *Wh, *Wl;
    cudaGetSymbolAddress((void**)&xb, g_x);
    cudaGetSymbolAddress((void**)&yb, g_y);
    cudaGetSymbolAddress((void**)&offa, g_offa);
    cudaGetSymbolAddress((void**)&offb, g_offb);
    cudaGetSymbolAddress((void**)&mrow, g_mrow);
    cudaGetSymbolAddress((void**)&Ah, g_Ah);
    cudaGetSymbolAddress((void**)&Al, g_Al);
    cudaGetSymbolAddress((void**)&Wh, g_Wh);
    cudaGetSymbolAddress((void**)&Wl, g_Wl);
    float* out = (float*)d_out;

    cudaFuncSetAttribute(gemm_mma_kernel,
                         cudaFuncAttributeMaxDynamicSharedMemorySize, GEMM_SMEM);
    cudaFuncSetAttribute(offset_kernel<true>,
                         cudaFuncAttributeMaxDynamicSharedMemorySize, OFF_SMEM);
    cudaFuncSetAttribute(offset_kernel<false>,
                         cudaFuncAttributeMaxDynamicSharedMemorySize, OFF_SMEM);

    // launch 0: merged prep (transposes + weight split + mask rows)
    prep_all_kernel<<<PREP_BLOCKS, 256>>>(feats[0], feats[1], feats[2],
                                          w[0], w[1], masks[0], masks[1], masks[2],
                                          xb, Wh, Wl, mrow);

    // ---- layer 0 ----  (launches 1,2,3 — ncu captures launch 3 = GEMM)
    offset_kernel<true><<<ROWS_TOTAL / 32, 256, OFF_SMEM>>>(
        xb, offs[0], offs[1], offs[2], ow[0], ob[0], offa);
    im2col_split_kernel<<<dim3(ROWS_TOTAL, KT), 128>>>(xb, offa, Ah, Al);
    gemm_mma_kernel<<<dim3(4, ROWS_TOTAL / BMM), 256, GEMM_SMEM>>>(
        Ah, Al, Wh, Wl, bias[0], mrow, yb);

    // ---- layer 1 ----
    offset_kernel<false><<<ROWS_TOTAL / 32, 256, OFF_SMEM>>>(
        yb, offa, nullptr, nullptr, ow[1], ob[1], offb);
    im2col_split_kernel<<<dim3(ROWS_TOTAL, KT), 128>>>(yb, offb, Ah, Al);
    gemm_mma_kernel<<<dim3(4, ROWS_TOTAL / BMM), 256, GEMM_SMEM>>>(
        Ah, Al, Wh + (size_t)KRED * CCH, Wl + (size_t)KRED * CCH,
        bias[1], mrow, xb);

    // outputs
    tout_kernel<<<dim3(16, 112, 8), dim3(32, 8)>>>(xb, out);
    maskoutall_kernel<<<(ROWS_TOTAL + 255) / 256, 256>>>(mrow, out);
}

// round 10
// speedup vs baseline: 1.1657x; 1.0042x over previous
#include <cuda_runtime.h>
#include <cuda_bf16.h>
#include <cstdint>

// ---------------------------------------------------------------------------
// FeatureAlign via mma.sync bf16 (HMMA) with fp32->bf16 hi/lo splitting.
//   Y = relu( A(fp32 gathered) @ W(fp32) + b ) * mask
//   A@W ~= Ah@Wh + Ah@Wl + Al@Wh   (fp32 accum)
// GEMM: 8 warps, 3-stage cp.async pipeline AND occupancy 2 (227KB/SM).
// Launch order puts the GEMM at index 3 (the launch ncu captures).
// ---------------------------------------------------------------------------

#define BSZ 8
#define CCH 512
#define KT  3
#define ROWS_TOTAL 28672
#define LV0 16384
#define LV01 24576
#define KRED 1536

// GEMM tiling
#define BMM 128
#define BNN 128
#define BKK 32
#define AST 40                      // A smem row stride (bf16): 32 + 8 pad
#define BST 136                     // B smem row stride: 128 + 8 pad
#define A_ELE (BMM*AST)             // 5120
#define B_ELE (BKK*BST)             // 4352
#define STG_BYTES ((2*A_ELE + 2*B_ELE)*2)   // 37888 B per stage
#define NSTAGE 3
#define GEMM_SMEM (NSTAGE*STG_BYTES)        // 113664 B; 2 CTAs = 227328 <= 228KB
#define KITERS (KRED/BKK)           // 48

// offset kernel smem: 34 staged rows + transposed weights
#define OFF_XS_FLOATS (34*CCH)              // 17408
#define OFF_SMEM ((OFF_XS_FLOATS + KT*KT*CCH) * 4)   // 88064 B

// prep_all grid regions
#define TIN_BLOCKS 14336                    // 112*16*8
#define WSPLIT_TOTAL (2*KRED*CCH + ROWS_TOTAL)
#define PREP_BLOCKS (TIN_BLOCKS + (WSPLIT_TOTAL + 255)/256)

// scratch (device globals; no runtime allocation allowed)
__device__ float g_x[ROWS_TOTAL * CCH];
__device__ float g_y[ROWS_TOTAL * CCH];
__device__ float g_offa[ROWS_TOTAL * 4];
__device__ float g_offb[ROWS_TOTAL * 4];
__device__ float g_mrow[ROWS_TOTAL];
__device__ __nv_bfloat16 g_Ah[(size_t)ROWS_TOTAL * KRED];
__device__ __nv_bfloat16 g_Al[(size_t)ROWS_TOTAL * KRED];
__device__ __nv_bfloat16 g_Wh[2 * KRED * CCH];
__device__ __nv_bfloat16 g_Wl[2 * KRED * CCH];

// ---------------------------------------------------------------------------
__device__ __forceinline__ uint32_t smem_u32(const void* p) {
    return (uint32_t)__cvta_generic_to_shared(p);
}
#define CP16(sa, gp) \
    asm volatile("cp.async.cg.shared.global [%0], [%1], 16;" :: "r"(sa), "l"(gp))
#define CP_COMMIT() asm volatile("cp.async.commit_group;")
#define CP_WAIT1()  asm volatile("cp.async.wait_group 1;")

__device__ __forceinline__ void ldsm_x4(uint32_t* r, uint32_t a) {
    asm volatile("ldmatrix.sync.aligned.m8n8.x4.shared.b16 {%0,%1,%2,%3}, [%4];"
                 : "=r"(r[0]), "=r"(r[1]), "=r"(r[2]), "=r"(r[3]) : "r"(a));
}
__device__ __forceinline__ void ldsm_x4_t(uint32_t* r, uint32_t a) {
    asm volatile("ldmatrix.sync.aligned.m8n8.x4.trans.shared.b16 {%0,%1,%2,%3}, [%4];"
                 : "=r"(r[0]), "=r"(r[1]), "=r"(r[2]), "=r"(r[3]) : "r"(a));
}
__device__ __forceinline__ void mma16816(float* d, const uint32_t* a,
                                         const uint32_t* b) {
    asm volatile("mma.sync.aligned.m16n8k16.row.col.f32.bf16.bf16.f32 "
                 "{%0,%1,%2,%3}, {%4,%5,%6,%7}, {%8,%9}, {%0,%1,%2,%3};"
                 : "+f"(d[0]), "+f"(d[1]), "+f"(d[2]), "+f"(d[3])
                 : "r"(a[0]), "r"(a[1]), "r"(a[2]), "r"(a[3]), "r"(b[0]), "r"(b[1]));
}

// ---------------------------------------------------------------------------
// prep_all: merged input transposes + weight bf16 hi/lo split + mask rows.
__global__ void prep_all_kernel(const float* __restrict__ f0,
                                const float* __restrict__ f1,
                                const float* __restrict__ f2,
                                const float* __restrict__ w0,
                                const float* __restrict__ w1,
                                const float* __restrict__ m0,
                                const float* __restrict__ m1,
                                const float* __restrict__ m2,
                                float* __restrict__ xb,
                                __nv_bfloat16* __restrict__ Wh,
                                __nv_bfloat16* __restrict__ Wl,
                                float* __restrict__ mrow) {
    __shared__ float tile[32][33];
    int bid = blockIdx.x, tid = threadIdx.x;
    if (bid < TIN_BLOCKS) {
        int xv = bid % 112;
        int y  = (bid / 112) % 16;
        int b  = bid / (112 * 16);
        int lv, xs, T, lbase;
        if (xv < 64)      { lv = 0; xs = xv;      T = 2048; lbase = 0;    }
        else if (xv < 96) { lv = 1; xs = xv - 64; T = 1024; lbase = LV0;  }
        else              { lv = 2; xs = xv - 96; T = 512;  lbase = LV01; }
        const float* f = (lv == 0) ? f0 : (lv == 1 ? f1 : f2);
        int tx = tid & 31, ty = tid >> 5;
        int s0 = xs * 32, r0 = y * 32;
        const float* inb = f + (size_t)b * CCH * T;
        float* outb = xb + (size_t)(lbase + b * T) * CCH;
        #pragma unroll
        for (int i = ty; i < 32; i += 8)
            tile[i][tx] = inb[(size_t)(r0 + i) * T + s0 + tx];
        __syncthreads();
        #pragma unroll
        for (int i = ty; i < 32; i += 8)
            outb[(size_t)(s0 + i) * CCH + r0 + tx] = tile[tx][i];
    } else {
        int idx = (bid - TIN_BLOCKS) * 256 + tid;
        if (idx < 2 * KRED * CCH) {
            int n = idx & 511;
            int k = (idx >> 9) % KRED;
            int l = idx / (KRED * CCH);
            int ktap = k >> 9, c = k & 511;
            const float* w = l ? w1 : w0;
            float val = w[(n * CCH + c) * KT + ktap];
            __nv_bfloat16 hi = __float2bfloat16(val);
            Wh[idx] = hi;
            Wl[idx] = __float2bfloat16(val - __bfloat162float(hi));
        } else if (idx < WSPLIT_TOTAL) {
            int m = idx - 2 * KRED * CCH;
            mrow[m] = (m < LV0) ? m0[m] : (m < LV01 ? m1[m - LV0] : m2[m - LV01]);
        }
    }
}

// ---------------------------------------------------------------------------
// merged output transpose: rows (m, C) -> out (B,C,T) per level slot
__global__ void tout_kernel(const float* __restrict__ xb,
                            float* __restrict__ out) {
    __shared__ float tile[32][33];
    int yv = blockIdx.y;
    int ys, T, lbase;
    size_t obase;
    if (yv < 64)      { ys = yv;      T = 2048; lbase = 0;
                        obase = 0; }
    else if (yv < 96) { ys = yv - 64; T = 1024; lbase = LV0;
                        obase = (size_t)BSZ * CCH * 2048; }
    else              { ys = yv - 96; T = 512;  lbase = LV01;
                        obase = (size_t)BSZ * CCH * (2048 + 1024); }
    int b = blockIdx.z;
    int r0 = ys * 32;
    int s0 = blockIdx.x * 32;
    const float* inb = xb + (size_t)(lbase + b * T) * CCH;
    float* outb = out + obase + (size_t)b * CCH * T;
    #pragma unroll
    for (int i = threadIdx.y; i < 32; i += 8)
        tile[i][threadIdx.x] = inb[(size_t)(r0 + i) * CCH + s0 + threadIdx.x];
    __syncthreads();
    #pragma unroll
    for (int i = threadIdx.y; i < 32; i += 8)
        outb[(size_t)(s0 + i) * T + r0 + threadIdx.x] = tile[threadIdx.x][i];
}

__global__ void maskoutall_kernel(const float* __restrict__ mrow,
                                  float* __restrict__ out) {
    int m = blockIdx.x * 256 + threadIdx.x;
    if (m < ROWS_TOTAL)
        out[(size_t)BSZ * CCH * 3584 + m] = (mrow[m] != 0.f) ? 1.0f : 0.0f;
}

// ---------------------------------------------------------------------------
// offset conv: 32 rows/block, 4 rows/warp; weights+x held in regs per q-chunk.
template <bool EXT>
__global__ void offset_kernel(const float* __restrict__ X,
                              const float* __restrict__ o0,
                              const float* __restrict__ o1,
                              const float* __restrict__ o2,
                              const float* __restrict__ ow,
                              const float* __restrict__ ob,
                              float* __restrict__ off_out) {
    extern __shared__ float sdyn[];
    float* xs = sdyn;                       // 34*512
    float* ow_sh2 = sdyn + OFF_XS_FLOATS;   // 4608: [(kk*3+j)*512 + c]
    int tid = threadIdx.x;

    int rl0g = blockIdx.x * 32;
    int lv = (rl0g < LV0) ? 0 : (rl0g < LV01 ? 1 : 2);
    int lbase = (lv == 0) ? 0 : (lv == 1 ? LV0 : LV01);
    int logT = 11 - lv;
    int T = 1 << logT;
    int rl0 = rl0g - lbase;
    const float* Xl = X + (size_t)lbase * CCH;

    for (int i = tid; i < KT * KT * CCH; i += 256) {
        int j = i % 3;
        int r = i / 3;
        int kk = r >> 9, c = r & 511;
        ow_sh2[(kk * 3 + j) * CCH + c] = ow[i];
    }

    int t0 = rl0 & (T - 1);
    for (int fi = tid; fi < 34 * 128; fi += 256) {
        int j = fi >> 7;
        int cf = (fi & 127) * 4;
        int t = t0 + j - 1;
        float4 v = make_float4(0.f, 0.f, 0.f, 0.f);
        if (t >= 0 && t < T)
            v = *(const float4*)(Xl + (size_t)(rl0 - 1 + j) * CCH + cf);
        *(float4*)(xs + j * CCH + cf) = v;
    }
    __syncthreads();

    int warp = tid >> 5, lane = tid & 31;
    int r0l = warp * 4;

    float acc[4][3];
    #pragma unroll
    for (int i = 0; i < 4; i++)
        #pragma unroll
        for (int kk = 0; kk < 3; kk++) acc[i][kk] = 0.f;

    #pragma unroll
    for (int q = 0; q < 4; q++) {
        int c = lane * 4 + q * 128;
        float4 wv[3][3];
        #pragma unroll
        for (int kk = 0; kk < 3; kk++)
            #pragma unroll
            for (int j = 0; j < 3; j++)
                wv[kk][j] = *(const float4*)(ow_sh2 + (kk * 3 + j) * CCH + c);
        float4 xv[6];
        #pragma unroll
        for (int u = 0; u < 6; u++)
            xv[u] = *(const float4*)(xs + (r0l + u) * CCH + c);
        #pragma unroll
        for (int i = 0; i < 4; i++) {
            #pragma unroll
            for (int kk = 0; kk < 3; kk++) {
                float s = 0.f;
                #pragma unroll
                for (int j = 0; j < 3; j++) {
                    float4 wf = wv[kk][j];
                    float4 xf = xv[i + j];
                    s += wf.x * xf.x + wf.y * xf.y + wf.z * xf.z + wf.w * xf.w;
                }
                acc[i][kk] += s;
            }
        }
    }

    #pragma unroll
    for (int i = 0; i < 4; i++)
        #pragma unroll
        for (int kk = 0; kk < 3; kk++)
            #pragma unroll
            for (int s = 16; s; s >>= 1)
                acc[i][kk] += __shfl_down_sync(0xffffffffu, acc[i][kk], s);

    if (lane == 0) {
        #pragma unroll
        for (int i = 0; i < 4; i++) {
            int rl = rl0 + r0l + i;
            int b = rl >> logT, t = rl & (T - 1);
            int m = rl0g + r0l + i;
            float i0, i1, i2;
            if (EXT) {
                const float* oin = (lv == 0) ? o0 : (lv == 1 ? o1 : o2);
                i0 = oin[((size_t)b * KT + 0) * T + t];
                i1 = oin[((size_t)b * KT + 1) * T + t];
                i2 = oin[((size_t)b * KT + 2) * T + t];
            } else {
                i0 = o0[(size_t)m * 4 + 0];
                i1 = o0[(size_t)m * 4 + 1];
                i2 = o0[(size_t)m * 4 + 2];
            }
            off_out[(size_t)m * 4 + 0] = acc[i][0] + ob[0] + i0;
            off_out[(size_t)m * 4 + 1] = acc[i][1] + ob[1] + i1;
            off_out[(size_t)m * 4 + 2] = acc[i][2] + ob[2] + i2;
        }
    }
}

// ---------------------------------------------------------------------------
// im2col gather + lerp + bf16 hi/lo split. grid (ROWS_TOTAL, 3), block 128.
__global__ void im2col_split_kernel(const float* __restrict__ X,
                                    const float* __restrict__ OFF,
                                    __nv_bfloat16* __restrict__ Ah,
                                    __nv_bfloat16* __restrict__ Al) {
    int m = blockIdx.x, k = blockIdx.y;
    int lv = (m < LV0) ? 0 : (m < LV01 ? 1 : 2);
    int lbase = (lv == 0) ? 0 : (lv == 1 ? LV0 : LV01);
    int logT = 11 - lv;
    int T = 1 << logT;
    int rl = m - lbase;
    int b = rl >> logT, t = rl & (T - 1);

    float off = OFF[(size_t)m * 4 + k];
    float pos = (float)(t + k - 1) + off;
    float p0f = floorf(pos);
    float f = pos - p0f;
    int i0 = (int)p0f, i1 = i0 + 1;
    float w0 = (i0 >= 0 && i0 < T) ? (1.0f - f) : 0.0f;
    float w1 = (i1 >= 0 && i1 < T) ? f : 0.0f;
    int i0c = min(max(i0, 0), T - 1);
    int i1c = min(max(i1, 0), T - 1);

    size_t rb = (size_t)lbase + ((size_t)b << logT);
    const float4* r0 = (const float4*)(X + (rb + i0c) * CCH);
    const float4* r1 = (const float4*)(X + (rb + i1c) * CCH);

    int i = threadIdx.x;
    float4 a = r0[i], c = r1[i];
    float e0 = w0 * a.x + w1 * c.x;
    float e1 = w0 * a.y + w1 * c.y;
    float e2 = w0 * a.z + w1 * c.z;
    float e3 = w0 * a.w + w1 * c.w;

    __nv_bfloat162 h01 = __floats2bfloat162_rn(e0, e1);
    __nv_bfloat162 h23 = __floats2bfloat162_rn(e2, e3);
    float2 f01 = __bfloat1622float2(h01);
    float2 f23 = __bfloat1622float2(h23);
    __nv_bfloat162 l01 = __floats2bfloat162_rn(e0 - f01.x, e1 - f01.y);
    __nv_bfloat162 l23 = __floats2bfloat162_rn(e2 - f23.x, e3 - f23.y);

    size_t base = (size_t)m * KRED + (size_t)k * CCH + i * 4;
    uint2 hv, lvv;
    hv.x = *reinterpret_cast<uint32_t*>(&h01);
    hv.y = *reinterpret_cast<uint32_t*>(&h23);
    lvv.x = *reinterpret_cast<uint32_t*>(&l01);
    lvv.y = *reinterpret_cast<uint32_t*>(&l23);
    *(uint2*)(Ah + base) = hv;
    *(uint2*)(Al + base) = lvv;
}

// ---------------------------------------------------------------------------
// GEMM: Y[m,n] = relu( (Ah@Wh + Ah@Wl + Al@Wh)[m,n] + bias[n] ) * maskrow[m]
// grid (4, 224), 256 threads (8 warps, warp tile 64x32), 3-stage, occ 2.
__global__ __launch_bounds__(256, 2)
void gemm_mma_kernel(const __nv_bfloat16* __restrict__ Ahg,
                     const __nv_bfloat16* __restrict__ Alg,
                     const __nv_bfloat16* __restrict__ Whg,
                     const __nv_bfloat16* __restrict__ Wlg,
                     const float* __restrict__ bias,
                     const float* __restrict__ maskrow,
                     float* __restrict__ Y) {
    extern __shared__ __nv_bfloat16 sm[];
    uint32_t sbase = smem_u32(sm);
    int tid = threadIdx.x, warp = tid >> 5, lane = tid & 31;
    int m0 = blockIdx.y * BMM, n0 = blockIdx.x * BNN;

    const uint32_t offAl = A_ELE * 2;
    const uint32_t offBh = 2 * A_ELE * 2;
    const uint32_t offBl = offBh + B_ELE * 2;

    int ar0 = tid >> 2, akc = (tid & 3) * 8;
    int br0 = tid >> 4, bnc = (tid & 15) * 8;
    const __nv_bfloat16* gAh0 = Ahg + (size_t)(m0 + ar0) * KRED + akc;
    const __nv_bfloat16* gAh1 = Ahg + (size_t)(m0 + ar0 + 64) * KRED + akc;
    const __nv_bfloat16* gAl0 = Alg + (size_t)(m0 + ar0) * KRED + akc;
    const __nv_bfloat16* gAl1 = Alg + (size_t)(m0 + ar0 + 64) * KRED + akc;
    const __nv_bfloat16* gBh0 = Whg + (size_t)br0 * CCH + n0 + bnc;
    const __nv_bfloat16* gBh1 = Whg + (size_t)(br0 + 16) * CCH + n0 + bnc;
    const __nv_bfloat16* gBl0 = Wlg + (size_t)br0 * CCH + n0 + bnc;
    const __nv_bfloat16* gBl1 = Wlg + (size_t)(br0 + 16) * CCH + n0 + bnc;
    uint32_t sA0 = (uint32_t)(ar0 * AST + akc) * 2;
    uint32_t sA1 = (uint32_t)((ar0 + 64) * AST + akc) * 2;
    uint32_t sB0 = (uint32_t)(br0 * BST + bnc) * 2;
    uint32_t sB1 = (uint32_t)((br0 + 16) * BST + bnc) * 2;

    int wm = (warp >> 2) * 64, wn = (warp & 3) * 32;
    int lr = lane & 15, lc = lane >> 4;
    uint32_t a_off[4], b_off[2];
    #pragma unroll
    for (int mt = 0; mt < 4; mt++)
        a_off[mt] = (uint32_t)((wm + mt * 16 + lr) * AST + lc * 8) * 2;
    #pragma unroll
    for (int nt = 0; nt < 2; nt++)
        b_off[nt] = (uint32_t)(lr * BST + wn + nt * 16 + lc * 8) * 2;

    float acc[4][4][4];
    #pragma unroll
    for (int i = 0; i < 4; i++)
        #pragma unroll
        for (int j = 0; j < 4; j++)
            #pragma unroll
            for (int q = 0; q < 4; q++) acc[i][j][q] = 0.f;

    auto load_stage = [&](int st, int k0) {
        uint32_t sb = sbase + (uint32_t)st * STG_BYTES;
        CP16(sb + sA0, gAh0 + k0);
        CP16(sb + sA1, gAh1 + k0);
        CP16(sb + offAl + sA0, gAl0 + k0);
        CP16(sb + offAl + sA1, gAl1 + k0);
        CP16(sb + offBh + sB0, gBh0 + (size_t)k0 * CCH);
        CP16(sb + offBh + sB1, gBh1 + (size_t)k0 * CCH);
        CP16(sb + offBl + sB0, gBl0 + (size_t)k0 * CCH);
        CP16(sb + offBl + sB1, gBl1 + (size_t)k0 * CCH);
    };

    load_stage(0, 0);  CP_COMMIT();
    load_stage(1, BKK); CP_COMMIT();

    for (int it = 0; it < KITERS; it++) {
        CP_WAIT1();                    // stage `it` complete (1 group in flight)
        __syncthreads();
        if (it + 2 < KITERS) load_stage((it + 2) % NSTAGE, (it + 2) * BKK);
        CP_COMMIT();                   // unconditional: keeps group count aligned

        uint32_t sb = sbase + (uint32_t)(it % NSTAGE) * STG_BYTES;
        #pragma unroll
        for (int ks = 0; ks < 2; ks++) {
            uint32_t bh[2][4], bl[2][4];
            #pragma unroll
            for (int nt = 0; nt < 2; nt++) {
                ldsm_x4_t(bh[nt], sb + offBh + b_off[nt] + ks * (16 * BST * 2));
                ldsm_x4_t(bl[nt], sb + offBl + b_off[nt] + ks * (16 * BST * 2));
            }
            #pragma unroll
            for (int mt = 0; mt < 4; mt++) {
                uint32_t ah[4], al[4];
                ldsm_x4(ah, sb + a_off[mt] + ks * 32);
                ldsm_x4(al, sb + offAl + a_off[mt] + ks * 32);
                #pragma unroll
                for (int n8 = 0; n8 < 4; n8++) {
                    const uint32_t* ph = &bh[n8 >> 1][(n8 & 1) * 2];
                    const uint32_t* pl = &bl[n8 >> 1][(n8 & 1) * 2];
                    mma16816(acc[mt][n8], ah, ph);
                    mma16816(acc[mt][n8], ah, pl);
                    mma16816(acc[mt][n8], al, ph);
                }
            }
        }
    }

    #pragma unroll
    for (int mt = 0; mt < 4; mt++) {
        int r0g = m0 + wm + mt * 16 + (lane >> 2);
        float mv0 = maskrow[r0g], mv1 = maskrow[r0g + 8];
        float* y0 = Y + (size_t)r0g * CCH;
        float* y1 = y0 + (size_t)8 * CCH;
        #pragma unroll
        for (int n8 = 0; n8 < 4; n8++) {
            int c0g = n0 + wn + n8 * 8 + (lane & 3) * 2;
            float b0 = bias[c0g], b1 = bias[c0g + 1];
            float2 v0, v1;
            v0.x = fmaxf(acc[mt][n8][0] + b0, 0.f) * mv0;
            v0.y = fmaxf(acc[mt][n8][1] + b1, 0.f) * mv0;
            v1.x = fmaxf(acc[mt][n8][2] + b0, 0.f) * mv1;
            v1.y = fmaxf(acc[mt][n8][3] + b1, 0.f) * mv1;
            *(float2*)(y0 + c0g) = v0;
            *(float2*)(y1 + c0g) = v1;
        }
    }
}

// ---------------------------------------------------------------------------
extern "C" void kernel_launch(void* const* d_in, const int* in_sizes, int n_in,
                              void* d_out, int out_size) {
    const float *feats[3] = {}, *masks[3] = {}, *offs[3] = {};
    const float *w[2] = {}, *bias[2] = {}, *ow[2] = {}, *ob[2] = {};
    int wi = 0, bi = 0, owi = 0, obi = 0;
    for (int i = 0; i < n_in; i++) {
        const float* p = (const float*)d_in[i];
        switch (in_sizes[i]) {
            case 8 * 512 * 2048: feats[0] = p; break;
            case 8 * 512 * 1024: feats[1] = p; break;
            case 8 * 512 * 512:  feats[2] = p; break;
            case 8 * 2048:       masks[0] = p; break;
            case 8 * 1024:       masks[1] = p; break;
            case 8 * 512:        masks[2] = p; break;
            case 8 * 3 * 2048:   offs[0] = p; break;
            case 8 * 3 * 1024:   offs[1] = p; break;
            case 8 * 3 * 512:    offs[2] = p; break;
            case 512 * 512 * 3:  if (wi < 2)  w[wi++] = p; break;
            case 512:            if (bi < 2)  bias[bi++] = p; break;
            case 3 * 512 * 3:    if (owi < 2) ow[owi++] = p; break;
            case 3:              if (obi < 2) ob[obi++] = p; break;
            default: break;
        }
    }

    float *xb, *yb, *offa, *offb, *mrow;
    __nv_bfloat16 *Ah, *Al, *Wh, *Wl;
    cudaGetSymbolAddress((void**)&xb, g_x);
    cudaGetSymbolAddress((void**)&yb, g_y);
    cudaGetSymbolAddress((void**)&offa, g_offa);
    cudaGetSymbolAddress((void**)&offb, g_offb);
    cudaGetSymbolAddress((void**)&mrow, g_mrow);
    cudaGetSymbolAddress((void**)&Ah, g_Ah);
    cudaGetSymbolAddress((void**)&Al, g_Al);
    cudaGetSymbolAddress((void**)&Wh, g_Wh);
    cudaGetSymbolAddress((void**)&Wl, g_Wl);
    float* out = (float*)d_out;

    cudaFuncSetAttribute(gemm_mma_kernel,
                         cudaFuncAttributeMaxDynamicSharedMemorySize, GEMM_SMEM);
    cudaFuncSetAttribute(offset_kernel<true>,
                         cudaFuncAttributeMaxDynamicSharedMemorySize, OFF_SMEM);
    cudaFuncSetAttribute(offset_kernel<false>,
                         cudaFuncAttributeMaxDynamicSharedMemorySize, OFF_SMEM);

    // launch 0: merged prep (transposes + weight split + mask rows)
    prep_all_kernel<<<PREP_BLOCKS, 256>>>(feats[0], feats[1], feats[2],
                                          w[0], w[1], masks[0], masks[1], masks[2],
                                          xb, Wh, Wl, mrow);

    // ---- layer 0 ----  (launches 1,2,3 — ncu captures launch 3 = GEMM)
    offset_kernel<true><<<ROWS_TOTAL / 32, 256, OFF_SMEM>>>(
        xb, offs[0], offs[1], offs[2], ow[0], ob[0], offa);
    im2col_split_kernel<<<dim3(ROWS_TOTAL, KT), 128>>>(xb, offa, Ah, Al);
    gemm_mma_kernel<<<dim3(4, ROWS_TOTAL / BMM), 256, GEMM_SMEM>>>(
        Ah, Al, Wh, Wl, bias[0], mrow, yb);

    // ---- layer 1 ----
    offset_kernel<false><<<ROWS_TOTAL / 32, 256, OFF_SMEM>>>(
        yb, offa, nullptr, nullptr, ow[1], ob[1], offb);
    im2col_split_kernel<<<dim3(ROWS_TOTAL, KT), 128>>>(yb, offb, Ah, Al);
    gemm_mma_kernel<<<dim3(4, ROWS_TOTAL / BMM), 256, GEMM_SMEM>>>(
        Ah, Al, Wh + (size_t)KRED * CCH, Wl + (size_t)KRED * CCH,
        bias[1], mrow, xb);

    // outputs
    tout_kernel<<<dim3(16, 112, 8), dim3(32, 8)>>>(xb, out);
    maskoutall_kernel<<<(ROWS_TOTAL + 255) / 256, 256>>>(mrow, out);
}

// round 11
// speedup vs baseline: 1.1728x; 1.0061x over previous
#include <cuda_runtime.h>
#include <cuda_bf16.h>
#include <cstdint>

// ---------------------------------------------------------------------------
// FeatureAlign via mma.sync bf16 (HMMA) with fp32->bf16 hi/lo splitting.
//   Y = relu( A(fp32 gathered) @ W(fp32) + b ) * mask
//   A@W ~= Ah@Wh + Ah@Wl + Al@Wh   (fp32 accum)
// GEMM: 8 warps, 3-stage cp.async, occ 2; B-frags hoisted per iteration.
// ---------------------------------------------------------------------------

#define BSZ 8
#define CCH 512
#define KT  3
#define ROWS_TOTAL 28672
#define LV0 16384
#define LV01 24576
#define KRED 1536

// GEMM tiling
#define BMM 128
#define BNN 128
#define BKK 32
#define AST 40                      // A smem row stride (bf16): 32 + 8 pad
#define BST 136                     // B smem row stride: 128 + 8 pad
#define A_ELE (BMM*AST)             // 5120
#define B_ELE (BKK*BST)             // 4352
#define STG_BYTES ((2*A_ELE + 2*B_ELE)*2)   // 37888 B per stage
#define NSTAGE 3
#define GEMM_SMEM (NSTAGE*STG_BYTES)        // 113664 B; 2 CTAs = 227328 <= 228KB
#define KITERS (KRED/BKK)           // 48

// offset kernel smem
#define OFF_XS_FLOATS (34*CCH)
#define OFF_SMEM ((OFF_XS_FLOATS + KT*KT*CCH) * 4)   // 88064 B

// prep_all grid regions
#define TIN_BLOCKS 14336                    // 112*16*8
#define WSPLIT_TOTAL (2*KRED*CCH + ROWS_TOTAL)
#define PREP_BLOCKS (TIN_BLOCKS + (WSPLIT_TOTAL + 255)/256)

// scratch (device globals; no runtime allocation allowed)
__device__ float g_x[ROWS_TOTAL * CCH];
__device__ float g_y[ROWS_TOTAL * CCH];
__device__ float g_offa[ROWS_TOTAL * 4];
__device__ float g_offb[ROWS_TOTAL * 4];
__device__ float g_mrow[ROWS_TOTAL];
__device__ __nv_bfloat16 g_Ah[(size_t)ROWS_TOTAL * KRED];
__device__ __nv_bfloat16 g_Al[(size_t)ROWS_TOTAL * KRED];
__device__ __nv_bfloat16 g_Wh[2 * KRED * CCH];
__device__ __nv_bfloat16 g_Wl[2 * KRED * CCH];

// ---------------------------------------------------------------------------
__device__ __forceinline__ uint32_t smem_u32(const void* p) {
    return (uint32_t)__cvta_generic_to_shared(p);
}
#define CP16(sa, gp) \
    asm volatile("cp.async.cg.shared.global [%0], [%1], 16;" :: "r"(sa), "l"(gp))
#define CP_COMMIT() asm volatile("cp.async.commit_group;")
#define CP_WAIT1()  asm volatile("cp.async.wait_group 1;")

__device__ __forceinline__ void ldsm_x4(uint32_t* r, uint32_t a) {
    asm volatile("ldmatrix.sync.aligned.m8n8.x4.shared.b16 {%0,%1,%2,%3}, [%4];"
                 : "=r"(r[0]), "=r"(r[1]), "=r"(r[2]), "=r"(r[3]) : "r"(a));
}
__device__ __forceinline__ void ldsm_x4_t(uint32_t* r, uint32_t a) {
    asm volatile("ldmatrix.sync.aligned.m8n8.x4.trans.shared.b16 {%0,%1,%2,%3}, [%4];"
                 : "=r"(r[0]), "=r"(r[1]), "=r"(r[2]), "=r"(r[3]) : "r"(a));
}
__device__ __forceinline__ void mma16816(float* d, const uint32_t* a,
                                         const uint32_t* b) {
    asm volatile("mma.sync.aligned.m16n8k16.row.col.f32.bf16.bf16.f32 "
                 "{%0,%1,%2,%3}, {%4,%5,%6,%7}, {%8,%9}, {%0,%1,%2,%3};"
                 : "+f"(d[0]), "+f"(d[1]), "+f"(d[2]), "+f"(d[3])
                 : "r"(a[0]), "r"(a[1]), "r"(a[2]), "r"(a[3]), "r"(b[0]), "r"(b[1]));
}

// ---------------------------------------------------------------------------
// prep_all: input transposes + weight bf16 hi/lo split + mask rows + bool out.
__global__ void prep_all_kernel(const float* __restrict__ f0,
                                const float* __restrict__ f1,
                                const float* __restrict__ f2,
                                const float* __restrict__ w0,
                                const float* __restrict__ w1,
                                const float* __restrict__ m0,
                                const float* __restrict__ m1,
                                const float* __restrict__ m2,
                                float* __restrict__ xb,
                                __nv_bfloat16* __restrict__ Wh,
                                __nv_bfloat16* __restrict__ Wl,
                                float* __restrict__ mrow,
                                float* __restrict__ out) {
    __shared__ float tile[32][33];
    int bid = blockIdx.x, tid = threadIdx.x;
    if (bid < TIN_BLOCKS) {
        int xv = bid % 112;
        int y  = (bid / 112) % 16;
        int b  = bid / (112 * 16);
        int lv, xs, T, lbase;
        if (xv < 64)      { lv = 0; xs = xv;      T = 2048; lbase = 0;    }
        else if (xv < 96) { lv = 1; xs = xv - 64; T = 1024; lbase = LV0;  }
        else              { lv = 2; xs = xv - 96; T = 512;  lbase = LV01; }
        const float* f = (lv == 0) ? f0 : (lv == 1 ? f1 : f2);
        int tx = tid & 31, ty = tid >> 5;
        int s0 = xs * 32, r0 = y * 32;
        const float* inb = f + (size_t)b * CCH * T;
        float* outb = xb + (size_t)(lbase + b * T) * CCH;
        #pragma unroll
        for (int i = ty; i < 32; i += 8)
            tile[i][tx] = inb[(size_t)(r0 + i) * T + s0 + tx];
        __syncthreads();
        #pragma unroll
        for (int i = ty; i < 32; i += 8)
            outb[(size_t)(s0 + i) * CCH + r0 + tx] = tile[tx][i];
    } else {
        int idx = (bid - TIN_BLOCKS) * 256 + tid;
        if (idx < 2 * KRED * CCH) {
            int n = idx & 511;
            int k = (idx >> 9) % KRED;
            int l = idx / (KRED * CCH);
            int ktap = k >> 9, c = k & 511;
            const float* w = l ? w1 : w0;
            float val = w[(n * CCH + c) * KT + ktap];
            __nv_bfloat16 hi = __float2bfloat16(val);
            Wh[idx] = hi;
            Wl[idx] = __float2bfloat16(val - __bfloat162float(hi));
        } else if (idx < WSPLIT_TOTAL) {
            int m = idx - 2 * KRED * CCH;
            float v = (m < LV0) ? m0[m] : (m < LV01 ? m1[m - LV0] : m2[m - LV01]);
            mrow[m] = v;
            out[(size_t)BSZ * CCH * 3584 + m] = (v != 0.f) ? 1.0f : 0.0f;
        }
    }
}

// ---------------------------------------------------------------------------
// merged output transpose: rows (m, C) -> out (B,C,T) per level slot
__global__ void tout_kernel(const float* __restrict__ xb,
                            float* __restrict__ out) {
    __shared__ float tile[32][33];
    int yv = blockIdx.y;
    int ys, T, lbase;
    size_t obase;
    if (yv < 64)      { ys = yv;      T = 2048; lbase = 0;
                        obase = 0; }
    else if (yv < 96) { ys = yv - 64; T = 1024; lbase = LV0;
                        obase = (size_t)BSZ * CCH * 2048; }
    else              { ys = yv - 96; T = 512;  lbase = LV01;
                        obase = (size_t)BSZ * CCH * (2048 + 1024); }
    int b = blockIdx.z;
    int r0 = ys * 32;
    int s0 = blockIdx.x * 32;
    const float* inb = xb + (size_t)(lbase + b * T) * CCH;
    float* outb = out + obase + (size_t)b * CCH * T;
    #pragma unroll
    for (int i = threadIdx.y; i < 32; i += 8)
        tile[i][threadIdx.x] = inb[(size_t)(r0 + i) * CCH + s0 + threadIdx.x];
    __syncthreads();
    #pragma unroll
    for (int i = threadIdx.y; i < 32; i += 8)
        outb[(size_t)(s0 + i) * T + r0 + threadIdx.x] = tile[threadIdx.x][i];
}

// ---------------------------------------------------------------------------
// offset conv: 32 rows/block, 4 rows/warp; weights+x held in regs per q-chunk.
template <bool EXT>
__global__ void offset_kernel(const float* __restrict__ X,
                              const float* __restrict__ o0,
                              const float* __restrict__ o1,
                              const float* __restrict__ o2,
                              const float* __restrict__ ow,
                              const float* __restrict__ ob,
                              float* __restrict__ off_out) {
    extern __shared__ float sdyn[];
    float* xs = sdyn;
    float* ow_sh2 = sdyn + OFF_XS_FLOATS;
    int tid = threadIdx.x;

    int rl0g = blockIdx.x * 32;
    int lv = (rl0g < LV0) ? 0 : (rl0g < LV01 ? 1 : 2);
    int lbase = (lv == 0) ? 0 : (lv == 1 ? LV0 : LV01);
    int logT = 11 - lv;
    int T = 1 << logT;
    int rl0 = rl0g - lbase;
    const float* Xl = X + (size_t)lbase * CCH;

    for (int i = tid; i < KT * KT * CCH; i += 256) {
        int j = i % 3;
        int r = i / 3;
        int kk = r >> 9, c = r & 511;
        ow_sh2[(kk * 3 + j) * CCH + c] = ow[i];
    }

    int t0 = rl0 & (T - 1);
    for (int fi = tid; fi < 34 * 128; fi += 256) {
        int j = fi >> 7;
        int cf = (fi & 127) * 4;
        int t = t0 + j - 1;
        float4 v = make_float4(0.f, 0.f, 0.f, 0.f);
        if (t >= 0 && t < T)
            v = *(const float4*)(Xl + (size_t)(rl0 - 1 + j) * CCH + cf);
        *(float4*)(xs + j * CCH + cf) = v;
    }
    __syncthreads();

    int warp = tid >> 5, lane = tid & 31;
    int r0l = warp * 4;

    float acc[4][3];
    #pragma unroll
    for (int i = 0; i < 4; i++)
        #pragma unroll
        for (int kk = 0; kk < 3; kk++) acc[i][kk] = 0.f;

    #pragma unroll
    for (int q = 0; q < 4; q++) {
        int c = lane * 4 + q * 128;
        float4 wv[3][3];
        #pragma unroll
        for (int kk = 0; kk < 3; kk++)
            #pragma unroll
            for (int j = 0; j < 3; j++)
                wv[kk][j] = *(const float4*)(ow_sh2 + (kk * 3 + j) * CCH + c);
        float4 xv[6];
        #pragma unroll
        for (int u = 0; u < 6; u++)
            xv[u] = *(const float4*)(xs + (r0l + u) * CCH + c);
        #pragma unroll
        for (int i = 0; i < 4; i++) {
            #pragma unroll
            for (int kk = 0; kk < 3; kk++) {
                float s = 0.f;
                #pragma unroll
                for (int j = 0; j < 3; j++) {
                    float4 wf = wv[kk][j];
                    float4 xf = xv[i + j];
                    s += wf.x * xf.x + wf.y * xf.y + wf.z * xf.z + wf.w * xf.w;
                }
                acc[i][kk] += s;
            }
        }
    }

    #pragma unroll
    for (int i = 0; i < 4; i++)
        #pragma unroll
        for (int kk = 0; kk < 3; kk++)
            #pragma unroll
            for (int s = 16; s; s >>= 1)
                acc[i][kk] += __shfl_down_sync(0xffffffffu, acc[i][kk], s);

    if (lane == 0) {
        #pragma unroll
        for (int i = 0; i < 4; i++) {
            int rl = rl0 + r0l + i;
            int b = rl >> logT, t = rl & (T - 1);
            int m = rl0g + r0l + i;
            float i0, i1, i2;
            if (EXT) {
                const float* oin = (lv == 0) ? o0 : (lv == 1 ? o1 : o2);
                i0 = oin[((size_t)b * KT + 0) * T + t];
                i1 = oin[((size_t)b * KT + 1) * T + t];
                i2 = oin[((size_t)b * KT + 2) * T + t];
            } else {
                i0 = o0[(size_t)m * 4 + 0];
                i1 = o0[(size_t)m * 4 + 1];
                i2 = o0[(size_t)m * 4 + 2];
            }
            off_out[(size_t)m * 4 + 0] = acc[i][0] + ob[0] + i0;
            off_out[(size_t)m * 4 + 1] = acc[i][1] + ob[1] + i1;
            off_out[(size_t)m * 4 + 2] = acc[i][2] + ob[2] + i2;
        }
    }
}

// ---------------------------------------------------------------------------
// im2col gather + lerp + bf16 hi/lo split. grid (ROWS_TOTAL, 3), block 128.
__global__ void im2col_split_kernel(const float* __restrict__ X,
                                    const float* __restrict__ OFF,
                                    __nv_bfloat16* __restrict__ Ah,
                                    __nv_bfloat16* __restrict__ Al) {
    int m = blockIdx.x, k = blockIdx.y;
    int lv = (m < LV0) ? 0 : (m < LV01 ? 1 : 2);
    int lbase = (lv == 0) ? 0 : (lv == 1 ? LV0 : LV01);
    int logT = 11 - lv;
    int T = 1 << logT;
    int rl = m - lbase;
    int b = rl >> logT, t = rl & (T - 1);

    float off = OFF[(size_t)m * 4 + k];
    float pos = (float)(t + k - 1) + off;
    float p0f = floorf(pos);
    float f = pos - p0f;
    int i0 = (int)p0f, i1 = i0 + 1;
    float w0 = (i0 >= 0 && i0 < T) ? (1.0f - f) : 0.0f;
    float w1 = (i1 >= 0 && i1 < T) ? f : 0.0f;
    int i0c = min(max(i0, 0), T - 1);
    int i1c = min(max(i1, 0), T - 1);

    size_t rb = (size_t)lbase + ((size_t)b << logT);
    const float4* r0 = (const float4*)(X + (rb + i0c) * CCH);
    const float4* r1 = (const float4*)(X + (rb + i1c) * CCH);

    int i = threadIdx.x;
    float4 a = r0[i], c = r1[i];
    float e0 = w0 * a.x + w1 * c.x;
    float e1 = w0 * a.y + w1 * c.y;
    float e2 = w0 * a.z + w1 * c.z;
    float e3 = w0 * a.w + w1 * c.w;

    __nv_bfloat162 h01 = __floats2bfloat162_rn(e0, e1);
    __nv_bfloat162 h23 = __floats2bfloat162_rn(e2, e3);
    float2 f01 = __bfloat1622float2(h01);
    float2 f23 = __bfloat1622float2(h23);
    __nv_bfloat162 l01 = __floats2bfloat162_rn(e0 - f01.x, e1 - f01.y);
    __nv_bfloat162 l23 = __floats2bfloat162_rn(e2 - f23.x, e3 - f23.y);

    size_t base = (size_t)m * KRED + (size_t)k * CCH + i * 4;
    uint2 hv, lvv;
    hv.x = *reinterpret_cast<uint32_t*>(&h01);
    hv.y = *reinterpret_cast<uint32_t*>(&h23);
    lvv.x = *reinterpret_cast<uint32_t*>(&l01);
    lvv.y = *reinterpret_cast<uint32_t*>(&l23);
    *(uint2*)(Ah + base) = hv;
    *(uint2*)(Al + base) = lvv;
}

// ---------------------------------------------------------------------------
// GEMM: Y[m,n] = relu( (Ah@Wh + Ah@Wl + Al@Wh)[m,n] + bias[n] ) * maskrow[m]
// grid (4, 224), 256 threads (8 warps, warp tile 64x32), 3-stage, occ 2.
// B fragments hoisted per iteration; A ldsm interleaved with MMA batches.
__global__ __launch_bounds__(256, 2)
void gemm_mma_kernel(const __nv_bfloat16* __restrict__ Ahg,
                     const __nv_bfloat16* __restrict__ Alg,
                     const __nv_bfloat16* __restrict__ Whg,
                     const __nv_bfloat16* __restrict__ Wlg,
                     const float* __restrict__ bias,
                     const float* __restrict__ maskrow,
                     float* __restrict__ Y) {
    extern __shared__ __nv_bfloat16 sm[];
    uint32_t sbase = smem_u32(sm);
    int tid = threadIdx.x, warp = tid >> 5, lane = tid & 31;
    int m0 = blockIdx.y * BMM, n0 = blockIdx.x * BNN;

    const uint32_t offAl = A_ELE * 2;
    const uint32_t offBh = 2 * A_ELE * 2;
    const uint32_t offBl = offBh + B_ELE * 2;

    // 4 base pointers; second chunks via constant offsets (reg pressure)
    int ar0 = tid >> 2, akc = (tid & 3) * 8;
    int br0 = tid >> 4, bnc = (tid & 15) * 8;
    const __nv_bfloat16* gAh = Ahg + (size_t)(m0 + ar0) * KRED + akc;
    const __nv_bfloat16* gAl = Alg + (size_t)(m0 + ar0) * KRED + akc;
    const __nv_bfloat16* gBh = Whg + (size_t)br0 * CCH + n0 + bnc;
    const __nv_bfloat16* gBl = Wlg + (size_t)br0 * CCH + n0 + bnc;
    const uint32_t A2 = 64u * KRED;       // elems to row +64
    const uint32_t B2 = 16u * CCH;        // elems to k-row +16
    uint32_t sA0 = (uint32_t)(ar0 * AST + akc) * 2;
    uint32_t sA1 = sA0 + 64u * AST * 2;
    uint32_t sB0 = (uint32_t)(br0 * BST + bnc) * 2;
    uint32_t sB1 = sB0 + 16u * BST * 2;

    int wm = (warp >> 2) * 64, wn = (warp & 3) * 32;
    int lr = lane & 15, lc = lane >> 4;
    uint32_t a_off[4], b_off[2];
    #pragma unroll
    for (int mt = 0; mt < 4; mt++)
        a_off[mt] = (uint32_t)((wm + mt * 16 + lr) * AST + lc * 8) * 2;
    #pragma unroll
    for (int nt = 0; nt < 2; nt++)
        b_off[nt] = (uint32_t)(lr * BST + wn + nt * 16 + lc * 8) * 2;

    float acc[4][4][4];
    #pragma unroll
    for (int i = 0; i < 4; i++)
        #pragma unroll
        for (int j = 0; j < 4; j++)
            #pragma unroll
            for (int q = 0; q < 4; q++) acc[i][j][q] = 0.f;

    auto load_stage = [&](int st, int k0) {
        uint32_t sb = sbase + (uint32_t)st * STG_BYTES;
        CP16(sb + sA0, gAh + k0);
        CP16(sb + sA1, gAh + A2 + k0);
        CP16(sb + offAl + sA0, gAl + k0);
        CP16(sb + offAl + sA1, gAl + A2 + k0);
        CP16(sb + offBh + sB0, gBh + (size_t)k0 * CCH);
        CP16(sb + offBh + sB1, gBh + B2 + (size_t)k0 * CCH);
        CP16(sb + offBl + sB0, gBl + (size_t)k0 * CCH);
        CP16(sb + offBl + sB1, gBl + B2 + (size_t)k0 * CCH);
    };

    load_stage(0, 0);  CP_COMMIT();
    load_stage(1, BKK); CP_COMMIT();

    for (int it = 0; it < KITERS; it++) {
        CP_WAIT1();
        __syncthreads();
        if (it + 2 < KITERS) load_stage((it + 2) % NSTAGE, (it + 2) * BKK);
        CP_COMMIT();

        uint32_t sb = sbase + (uint32_t)(it % NSTAGE) * STG_BYTES;

        // hoist all B fragments for this iteration (both k-halves)
        uint32_t bh[2][2][4], bl[2][2][4];   // [nt][ks][4]
        #pragma unroll
        for (int ks = 0; ks < 2; ks++)
            #pragma unroll
            for (int nt = 0; nt < 2; nt++) {
                ldsm_x4_t(bh[nt][ks], sb + offBh + b_off[nt] + ks * (16 * BST * 2));
                ldsm_x4_t(bl[nt][ks], sb + offBl + b_off[nt] + ks * (16 * BST * 2));
            }

        #pragma unroll
        for (int mt = 0; mt < 4; mt++) {
            #pragma unroll
            for (int ks = 0; ks < 2; ks++) {
                uint32_t ah[4], al[4];
                ldsm_x4(ah, sb + a_off[mt] + ks * 32);
                ldsm_x4(al, sb + offAl + a_off[mt] + ks * 32);
                #pragma unroll
                for (int n8 = 0; n8 < 4; n8++) {
                    const uint32_t* ph = &bh[n8 >> 1][ks][(n8 & 1) * 2];
                    const uint32_t* pl = &bl[n8 >> 1][ks][(n8 & 1) * 2];
                    mma16816(acc[mt][n8], ah, ph);
                    mma16816(acc[mt][n8], ah, pl);
                    mma16816(acc[mt][n8], al, ph);
                }
            }
        }
    }

    #pragma unroll
    for (int mt = 0; mt < 4; mt++) {
        int r0g = m0 + wm + mt * 16 + (lane >> 2);
        float mv0 = maskrow[r0g], mv1 = maskrow[r0g + 8];
        float* y0 = Y + (size_t)r0g * CCH;
        float* y1 = y0 + (size_t)8 * CCH;
        #pragma unroll
        for (int n8 = 0; n8 < 4; n8++) {
            int c0g = n0 + wn + n8 * 8 + (lane & 3) * 2;
            float b0 = bias[c0g], b1 = bias[c0g + 1];
            float2 v0, v1;
            v0.x = fmaxf(acc[mt][n8][0] + b0, 0.f) * mv0;
            v0.y = fmaxf(acc[mt][n8][1] + b1, 0.f) * mv0;
            v1.x = fmaxf(acc[mt][n8][2] + b0, 0.f) * mv1;
            v1.y = fmaxf(acc[mt][n8][3] + b1, 0.f) * mv1;
            *(float2*)(y0 + c0g) = v0;
            *(float2*)(y1 + c0g) = v1;
        }
    }
}

// ---------------------------------------------------------------------------
extern "C" void kernel_launch(void* const* d_in, const int* in_sizes, int n_in,
                              void* d_out, int out_size) {
    const float *feats[3] = {}, *masks[3] = {}, *offs[3] = {};
    const float *w[2] = {}, *bias[2] = {}, *ow[2] = {}, *ob[2] = {};
    int wi = 0, bi = 0, owi = 0, obi = 0;
    for (int i = 0; i < n_in; i++) {
        const float* p = (const float*)d_in[i];
        switch (in_sizes[i]) {
            case 8 * 512 * 2048: feats[0] = p; break;
            case 8 * 512 * 1024: feats[1] = p; break;
            case 8 * 512 * 512:  feats[2] = p; break;
            case 8 * 2048:       masks[0] = p; break;
            case 8 * 1024:       masks[1] = p; break;
            case 8 * 512:        masks[2] = p; break;
            case 8 * 3 * 2048:   offs[0] = p; break;
            case 8 * 3 * 1024:   offs[1] = p; break;
            case 8 * 3 * 512:    offs[2] = p; break;
            case 512 * 512 * 3:  if (wi < 2)  w[wi++] = p; break;
            case 512:            if (bi < 2)  bias[bi++] = p; break;
            case 3 * 512 * 3:    if (owi < 2) ow[owi++] = p; break;
            case 3:              if (obi < 2) ob[obi++] = p; break;
            default: break;
        }
    }

    float *xb, *yb, *offa, *offb, *mrow;
    __nv_bfloat16 *Ah, *Al, *Wh, *Wl;
    cudaGetSymbolAddress((void**)&xb, g_x);
    cudaGetSymbolAddress((void**)&yb, g_y);
    cudaGetSymbolAddress((void**)&offa, g_offa);
    cudaGetSymbolAddress((void**)&offb, g_offb);
    cudaGetSymbolAddress((void**)&mrow, g_mrow);
    cudaGetSymbolAddress((void**)&Ah, g_Ah);
    cudaGetSymbolAddress((void**)&Al, g_Al);
    cudaGetSymbolAddress((void**)&Wh, g_Wh);
    cudaGetSymbolAddress((void**)&Wl, g_Wl);
    float* out = (float*)d_out;

    cudaFuncSetAttribute(gemm_mma_kernel,
                         cudaFuncAttributeMaxDynamicSharedMemorySize, GEMM_SMEM);
    cudaFuncSetAttribute(offset_kernel<true>,
                         cudaFuncAttributeMaxDynamicSharedMemorySize, OFF_SMEM);
    cudaFuncSetAttribute(offset_kernel<false>,
                         cudaFuncAttributeMaxDynamicSharedMemorySize, OFF_SMEM);

    // launch 0: merged prep (transposes + weight split + mask rows + bool out)
    prep_all_kernel<<<PREP_BLOCKS, 256>>>(feats[0], feats[1], feats[2],
                                          w[0], w[1], masks[0], masks[1], masks[2],
                                          xb, Wh, Wl, mrow, out);

    // ---- layer 0 ----  (launches 1,2,3 — ncu captures launch 3 = GEMM)
    offset_kernel<true><<<ROWS_TOTAL / 32, 256, OFF_SMEM>>>(
        xb, offs[0], offs[1], offs[2], ow[0], ob[0], offa);
    im2col_split_kernel<<<dim3(ROWS_TOTAL, KT), 128>>>(xb, offa, Ah, Al);
    gemm_mma_kernel<<<dim3(4, ROWS_TOTAL / BMM), 256, GEMM_SMEM>>>(
        Ah, Al, Wh, Wl, bias[0], mrow, yb);

    // ---- layer 1 ----
    offset_kernel<false><<<ROWS_TOTAL / 32, 256, OFF_SMEM>>>(
        yb, offa, nullptr, nullptr, ow[1], ob[1], offb);
    im2col_split_kernel<<<dim3(ROWS_TOTAL, KT), 128>>>(yb, offb, Ah, Al);
    gemm_mma_kernel<<<dim3(4, ROWS_TOTAL / BMM), 256, GEMM_SMEM>>>(
        Ah, Al, Wh + (size_t)KRED * CCH, Wl + (size_t)KRED * CCH,
        bias[1], mrow, xb);

    // outputs
    tout_kernel<<<dim3(16, 112, 8), dim3(32, 8)>>>(xb, out);
}

// round 12
// speedup vs baseline: 1.2061x; 1.0284x over previous
#include <cuda_runtime.h>
#include <cuda_bf16.h>
#include <cstdint>

// ---------------------------------------------------------------------------
// FeatureAlign via mma.sync bf16 (HMMA) with fp32->bf16 hi/lo splitting.
//   Y = relu( A(fp32 gathered) @ W(fp32) + b ) * mask
//   A@W ~= Ah@Wh + Ah@Wl + Al@Wh   (fp32 accum)
// GEMM: BMM=64, 4 warps/CTA, 2-stage cp.async, 4 CTAs/SM (4 sync domains).
// ---------------------------------------------------------------------------

#define BSZ 8
#define CCH 512
#define KT  3
#define ROWS_TOTAL 28672
#define LV0 16384
#define LV01 24576
#define KRED 1536

// GEMM tiling
#define BMM 64
#define BNN 128
#define BKK 32
#define AST 40                      // A smem row stride (bf16): 32 + 8 pad
#define BST 136                     // B smem row stride: 128 + 8 pad
#define A_ELE (BMM*AST)             // 2560
#define B_ELE (BKK*BST)             // 4352
#define STG_BYTES ((2*A_ELE + 2*B_ELE)*2)   // 27648 B per stage
#define NSTAGE 2
#define GEMM_SMEM (NSTAGE*STG_BYTES)        // 55296 B; 4 CTAs = 221184 <= 228KB
#define KITERS (KRED/BKK)           // 48

// offset kernel smem
#define OFF_XS_FLOATS (34*CCH)
#define OFF_SMEM ((OFF_XS_FLOATS + KT*KT*CCH) * 4)   // 88064 B

// prep_all grid regions
#define TIN_BLOCKS 14336                    // 112*16*8
#define WSPLIT_TOTAL (2*KRED*CCH + ROWS_TOTAL)
#define PREP_BLOCKS (TIN_BLOCKS + (WSPLIT_TOTAL + 255)/256)

// scratch (device globals; no runtime allocation allowed)
__device__ float g_x[ROWS_TOTAL * CCH];
__device__ float g_y[ROWS_TOTAL * CCH];
__device__ float g_offa[ROWS_TOTAL * 4];
__device__ float g_offb[ROWS_TOTAL * 4];
__device__ float g_mrow[ROWS_TOTAL];
__device__ __nv_bfloat16 g_Ah[(size_t)ROWS_TOTAL * KRED];
__device__ __nv_bfloat16 g_Al[(size_t)ROWS_TOTAL * KRED];
__device__ __nv_bfloat16 g_Wh[2 * KRED * CCH];
__device__ __nv_bfloat16 g_Wl[2 * KRED * CCH];

// ---------------------------------------------------------------------------
__device__ __forceinline__ uint32_t smem_u32(const void* p) {
    return (uint32_t)__cvta_generic_to_shared(p);
}
#define CP16(sa, gp) \
    asm volatile("cp.async.cg.shared.global [%0], [%1], 16;" :: "r"(sa), "l"(gp))
#define CP_COMMIT() asm volatile("cp.async.commit_group;")
#define CP_WAIT0()  asm volatile("cp.async.wait_group 0;")

__device__ __forceinline__ void ldsm_x4(uint32_t* r, uint32_t a) {
    asm volatile("ldmatrix.sync.aligned.m8n8.x4.shared.b16 {%0,%1,%2,%3}, [%4];"
                 : "=r"(r[0]), "=r"(r[1]), "=r"(r[2]), "=r"(r[3]) : "r"(a));
}
__device__ __forceinline__ void ldsm_x4_t(uint32_t* r, uint32_t a) {
    asm volatile("ldmatrix.sync.aligned.m8n8.x4.trans.shared.b16 {%0,%1,%2,%3}, [%4];"
                 : "=r"(r[0]), "=r"(r[1]), "=r"(r[2]), "=r"(r[3]) : "r"(a));
}
__device__ __forceinline__ void mma16816(float* d, const uint32_t* a,
                                         const uint32_t* b) {
    asm volatile("mma.sync.aligned.m16n8k16.row.col.f32.bf16.bf16.f32 "
                 "{%0,%1,%2,%3}, {%4,%5,%6,%7}, {%8,%9}, {%0,%1,%2,%3};"
                 : "+f"(d[0]), "+f"(d[1]), "+f"(d[2]), "+f"(d[3])
                 : "r"(a[0]), "r"(a[1]), "r"(a[2]), "r"(a[3]), "r"(b[0]), "r"(b[1]));
}

// ---------------------------------------------------------------------------
// prep_all: input transposes + weight bf16 hi/lo split + mask rows + bool out.
__global__ void prep_all_kernel(const float* __restrict__ f0,
                                const float* __restrict__ f1,
                                const float* __restrict__ f2,
                                const float* __restrict__ w0,
                                const float* __restrict__ w1,
                                const float* __restrict__ m0,
                                const float* __restrict__ m1,
                                const float* __restrict__ m2,
                                float* __restrict__ xb,
                                __nv_bfloat16* __restrict__ Wh,
                                __nv_bfloat16* __restrict__ Wl,
                                float* __restrict__ mrow,
                                float* __restrict__ out) {
    __shared__ float tile[32][33];
    int bid = blockIdx.x, tid = threadIdx.x;
    if (bid < TIN_BLOCKS) {
        int xv = bid % 112;
        int y  = (bid / 112) % 16;
        int b  = bid / (112 * 16);
        int lv, xs, T, lbase;
        if (xv < 64)      { lv = 0; xs = xv;      T = 2048; lbase = 0;    }
        else if (xv < 96) { lv = 1; xs = xv - 64; T = 1024; lbase = LV0;  }
        else              { lv = 2; xs = xv - 96; T = 512;  lbase = LV01; }
        const float* f = (lv == 0) ? f0 : (lv == 1 ? f1 : f2);
        int tx = tid & 31, ty = tid >> 5;
        int s0 = xs * 32, r0 = y * 32;
        const float* inb = f + (size_t)b * CCH * T;
        float* outb = xb + (size_t)(lbase + b * T) * CCH;
        #pragma unroll
        for (int i = ty; i < 32; i += 8)
            tile[i][tx] = inb[(size_t)(r0 + i) * T + s0 + tx];
        __syncthreads();
        #pragma unroll
        for (int i = ty; i < 32; i += 8)
            outb[(size_t)(s0 + i) * CCH + r0 + tx] = tile[tx][i];
    } else {
        int idx = (bid - TIN_BLOCKS) * 256 + tid;
        if (idx < 2 * KRED * CCH) {
            int n = idx & 511;
            int k = (idx >> 9) % KRED;
            int l = idx / (KRED * CCH);
            int ktap = k >> 9, c = k & 511;
            const float* w = l ? w1 : w0;
            float val = w[(n * CCH + c) * KT + ktap];
            __nv_bfloat16 hi = __float2bfloat16(val);
            Wh[idx] = hi;
            Wl[idx] = __float2bfloat16(val - __bfloat162float(hi));
        } else if (idx < WSPLIT_TOTAL) {
            int m = idx - 2 * KRED * CCH;
            float v = (m < LV0) ? m0[m] : (m < LV01 ? m1[m - LV0] : m2[m - LV01]);
            mrow[m] = v;
            out[(size_t)BSZ * CCH * 3584 + m] = (v != 0.f) ? 1.0f : 0.0f;
        }
    }
}

// ---------------------------------------------------------------------------
// merged output transpose: rows (m, C) -> out (B,C,T) per level slot
__global__ void tout_kernel(const float* __restrict__ xb,
                            float* __restrict__ out) {
    __shared__ float tile[32][33];
    int yv = blockIdx.y;
    int ys, T, lbase;
    size_t obase;
    if (yv < 64)      { ys = yv;      T = 2048; lbase = 0;
                        obase = 0; }
    else if (yv < 96) { ys = yv - 64; T = 1024; lbase = LV0;
                        obase = (size_t)BSZ * CCH * 2048; }
    else              { ys = yv - 96; T = 512;  lbase = LV01;
                        obase = (size_t)BSZ * CCH * (2048 + 1024); }
    int b = blockIdx.z;
    int r0 = ys * 32;
    int s0 = blockIdx.x * 32;
    const float* inb = xb + (size_t)(lbase + b * T) * CCH;
    float* outb = out + obase + (size_t)b * CCH * T;
    #pragma unroll
    for (int i = threadIdx.y; i < 32; i += 8)
        tile[i][threadIdx.x] = inb[(size_t)(r0 + i) * CCH + s0 + threadIdx.x];
    __syncthreads();
    #pragma unroll
    for (int i = threadIdx.y; i < 32; i += 8)
        outb[(size_t)(s0 + i) * T + r0 + threadIdx.x] = tile[threadIdx.x][i];
}

// ---------------------------------------------------------------------------
// offset conv: 32 rows/block, 4 rows/warp; weights+x held in regs per q-chunk.
template <bool EXT>
__global__ void offset_kernel(const float* __restrict__ X,
                              const float* __restrict__ o0,
                              const float* __restrict__ o1,
                              const float* __restrict__ o2,
                              const float* __restrict__ ow,
                              const float* __restrict__ ob,
                              float* __restrict__ off_out) {
    extern __shared__ float sdyn[];
    float* xs = sdyn;
    float* ow_sh2 = sdyn + OFF_XS_FLOATS;
    int tid = threadIdx.x;

    int rl0g = blockIdx.x * 32;
    int lv = (rl0g < LV0) ? 0 : (rl0g < LV01 ? 1 : 2);
    int lbase = (lv == 0) ? 0 : (lv == 1 ? LV0 : LV01);
    int logT = 11 - lv;
    int T = 1 << logT;
    int rl0 = rl0g - lbase;
    const float* Xl = X + (size_t)lbase * CCH;

    for (int i = tid; i < KT * KT * CCH; i += 256) {
        int j = i % 3;
        int r = i / 3;
        int kk = r >> 9, c = r & 511;
        ow_sh2[(kk * 3 + j) * CCH + c] = ow[i];
    }

    int t0 = rl0 & (T - 1);
    for (int fi = tid; fi < 34 * 128; fi += 256) {
        int j = fi >> 7;
        int cf = (fi & 127) * 4;
        int t = t0 + j - 1;
        float4 v = make_float4(0.f, 0.f, 0.f, 0.f);
        if (t >= 0 && t < T)
            v = *(const float4*)(Xl + (size_t)(rl0 - 1 + j) * CCH + cf);
        *(float4*)(xs + j * CCH + cf) = v;
    }
    __syncthreads();

    int warp = tid >> 5, lane = tid & 31;
    int r0l = warp * 4;

    float acc[4][3];
    #pragma unroll
    for (int i = 0; i < 4; i++)
        #pragma unroll
        for (int kk = 0; kk < 3; kk++) acc[i][kk] = 0.f;

    #pragma unroll
    for (int q = 0; q < 4; q++) {
        int c = lane * 4 + q * 128;
        float4 wv[3][3];
        #pragma unroll
        for (int kk = 0; kk < 3; kk++)
            #pragma unroll
            for (int j = 0; j < 3; j++)
                wv[kk][j] = *(const float4*)(ow_sh2 + (kk * 3 + j) * CCH + c);
        float4 xv[6];
        #pragma unroll
        for (int u = 0; u < 6; u++)
            xv[u] = *(const float4*)(xs + (r0l + u) * CCH + c);
        #pragma unroll
        for (int i = 0; i < 4; i++) {
            #pragma unroll
            for (int kk = 0; kk < 3; kk++) {
                float s = 0.f;
                #pragma unroll
                for (int j = 0; j < 3; j++) {
                    float4 wf = wv[kk][j];
                    float4 xf = xv[i + j];
                    s += wf.x * xf.x + wf.y * xf.y + wf.z * xf.z + wf.w * xf.w;
                }
                acc[i][kk] += s;
            }
        }
    }

    #pragma unroll
    for (int i = 0; i < 4; i++)
        #pragma unroll
        for (int kk = 0; kk < 3; kk++)
            #pragma unroll
            for (int s = 16; s; s >>= 1)
                acc[i][kk] += __shfl_down_sync(0xffffffffu, acc[i][kk], s);

    if (lane == 0) {
        #pragma unroll
        for (int i = 0; i < 4; i++) {
            int rl = rl0 + r0l + i;
            int b = rl >> logT, t = rl & (T - 1);
            int m = rl0g + r0l + i;
            float i0, i1, i2;
            if (EXT) {
                const float* oin = (lv == 0) ? o0 : (lv == 1 ? o1 : o2);
                i0 = oin[((size_t)b * KT + 0) * T + t];
                i1 = oin[((size_t)b * KT + 1) * T + t];
                i2 = oin[((size_t)b * KT + 2) * T + t];
            } else {
                i0 = o0[(size_t)m * 4 + 0];
                i1 = o0[(size_t)m * 4 + 1];
                i2 = o0[(size_t)m * 4 + 2];
            }
            off_out[(size_t)m * 4 + 0] = acc[i][0] + ob[0] + i0;
            off_out[(size_t)m * 4 + 1] = acc[i][1] + ob[1] + i1;
            off_out[(size_t)m * 4 + 2] = acc[i][2] + ob[2] + i2;
        }
    }
}

// ---------------------------------------------------------------------------
// im2col gather + lerp + bf16 hi/lo split. grid (ROWS_TOTAL, 3), block 128.
__global__ void im2col_split_kernel(const float* __restrict__ X,
                                    const float* __restrict__ OFF,
                                    __nv_bfloat16* __restrict__ Ah,
                                    __nv_bfloat16* __restrict__ Al) {
    int m = blockIdx.x, k = blockIdx.y;
    int lv = (m < LV0) ? 0 : (m < LV01 ? 1 : 2);
    int lbase = (lv == 0) ? 0 : (lv == 1 ? LV0 : LV01);
    int logT = 11 - lv;
    int T = 1 << logT;
    int rl = m - lbase;
    int b = rl >> logT, t = rl & (T - 1);

    float off = OFF[(size_t)m * 4 + k];
    float pos = (float)(t + k - 1) + off;
    float p0f = floorf(pos);
    float f = pos - p0f;
    int i0 = (int)p0f, i1 = i0 + 1;
    float w0 = (i0 >= 0 && i0 < T) ? (1.0f - f) : 0.0f;
    float w1 = (i1 >= 0 && i1 < T) ? f : 0.0f;
    int i0c = min(max(i0, 0), T - 1);
    int i1c = min(max(i1, 0), T - 1);

    size_t rb = (size_t)lbase + ((size_t)b << logT);
    const float4* r0 = (const float4*)(X + (rb + i0c) * CCH);
    const float4* r1 = (const float4*)(X + (rb + i1c) * CCH);

    int i = threadIdx.x;
    float4 a = r0[i], c = r1[i];
    float e0 = w0 * a.x + w1 * c.x;
    float e1 = w0 * a.y + w1 * c.y;
    float e2 = w0 * a.z + w1 * c.z;
    float e3 = w0 * a.w + w1 * c.w;

    __nv_bfloat162 h01 = __floats2bfloat162_rn(e0, e1);
    __nv_bfloat162 h23 = __floats2bfloat162_rn(e2, e3);
    float2 f01 = __bfloat1622float2(h01);
    float2 f23 = __bfloat1622float2(h23);
    __nv_bfloat162 l01 = __floats2bfloat162_rn(e0 - f01.x, e1 - f01.y);
    __nv_bfloat162 l23 = __floats2bfloat162_rn(e2 - f23.x, e3 - f23.y);

    size_t base = (size_t)m * KRED + (size_t)k * CCH + i * 4;
    uint2 hv, lvv;
    hv.x = *reinterpret_cast<uint32_t*>(&h01);
    hv.y = *reinterpret_cast<uint32_t*>(&h23);
    lvv.x = *reinterpret_cast<uint32_t*>(&l01);
    lvv.y = *reinterpret_cast<uint32_t*>(&l23);
    *(uint2*)(Ah + base) = hv;
    *(uint2*)(Al + base) = lvv;
}

// ---------------------------------------------------------------------------
// GEMM: Y[m,n] = relu( (Ah@Wh + Ah@Wl + Al@Wh)[m,n] + bias[n] ) * maskrow[m]
// grid (4, 448), 128 threads (4 warps, warp tile 64x32), 2-stage, 4 CTAs/SM.
__global__ __launch_bounds__(128, 4)
void gemm_mma_kernel(const __nv_bfloat16* __restrict__ Ahg,
                     const __nv_bfloat16* __restrict__ Alg,
                     const __nv_bfloat16* __restrict__ Whg,
                     const __nv_bfloat16* __restrict__ Wlg,
                     const float* __restrict__ bias,
                     const float* __restrict__ maskrow,
                     float* __restrict__ Y) {
    extern __shared__ __nv_bfloat16 sm[];
    uint32_t sbase = smem_u32(sm);
    int tid = threadIdx.x, warp = tid >> 5, lane = tid & 31;
    int m0 = blockIdx.y * BMM, n0 = blockIdx.x * BNN;

    const uint32_t offAl = A_ELE * 2;          // 5120
    const uint32_t offBh = 2 * A_ELE * 2;      // 10240
    const uint32_t offBl = offBh + B_ELE * 2;  // 18944

    // A: 64 rows x 32 k (2 chunks of 32 rows); B: 32 k x 128 n (4 chunks of 8 k)
    int ar0 = tid >> 2, akc = (tid & 3) * 8;
    int br0 = tid >> 4, bnc = (tid & 15) * 8;
    const __nv_bfloat16* gAh = Ahg + (size_t)(m0 + ar0) * KRED + akc;
    const __nv_bfloat16* gAl = Alg + (size_t)(m0 + ar0) * KRED + akc;
    const __nv_bfloat16* gBh = Whg + (size_t)br0 * CCH + n0 + bnc;
    const __nv_bfloat16* gBl = Wlg + (size_t)br0 * CCH + n0 + bnc;
    const uint32_t A2 = 32u * KRED;
    uint32_t sA0 = (uint32_t)(ar0 * AST + akc) * 2;
    uint32_t sA1 = sA0 + 32u * AST * 2;
    uint32_t sB0 = (uint32_t)(br0 * BST + bnc) * 2;

    int wn = warp * 32;
    int lr = lane & 15, lc = lane >> 4;
    uint32_t a_off[4], b_off[2];
    #pragma unroll
    for (int mt = 0; mt < 4; mt++)
        a_off[mt] = (uint32_t)((mt * 16 + lr) * AST + lc * 8) * 2;
    #pragma unroll
    for (int nt = 0; nt < 2; nt++)
        b_off[nt] = (uint32_t)(lr * BST + wn + nt * 16 + lc * 8) * 2;

    float acc[4][4][4];
    #pragma unroll
    for (int i = 0; i < 4; i++)
        #pragma unroll
        for (int j = 0; j < 4; j++)
            #pragma unroll
            for (int q = 0; q < 4; q++) acc[i][j][q] = 0.f;

    auto load_stage = [&](int st, int k0) {
        uint32_t sb = sbase + (uint32_t)st * STG_BYTES;
        CP16(sb + sA0, gAh + k0);
        CP16(sb + sA1, gAh + A2 + k0);
        CP16(sb + offAl + sA0, gAl + k0);
        CP16(sb + offAl + sA1, gAl + A2 + k0);
        #pragma unroll
        for (int c = 0; c < 4; c++) {
            uint32_t so = sB0 + (uint32_t)c * 8 * BST * 2;
            size_t go = (size_t)(k0 + c * 8) * CCH;
            CP16(sb + offBh + so, gBh + go);
            CP16(sb + offBl + so, gBl + go);
        }
    };

    load_stage(0, 0);
    CP_COMMIT();
    CP_WAIT0();
    __syncthreads();

    for (int it = 0; it < KITERS; it++) {
        if (it + 1 < KITERS) {
            load_stage((it + 1) & 1, (it + 1) * BKK);
            CP_COMMIT();
        }

        uint32_t sb = sbase + (uint32_t)(it & 1) * STG_BYTES;

        // hoist all B fragments for this iteration (both k-halves)
        uint32_t bh[2][2][4], bl[2][2][4];   // [nt][ks][4]
        #pragma unroll
        for (int ks = 0; ks < 2; ks++)
            #pragma unroll
            for (int nt = 0; nt < 2; nt++) {
                ldsm_x4_t(bh[nt][ks], sb + offBh + b_off[nt] + ks * (16 * BST * 2));
                ldsm_x4_t(bl[nt][ks], sb + offBl + b_off[nt] + ks * (16 * BST * 2));
            }

        #pragma unroll
        for (int mt = 0; mt < 4; mt++) {
            #pragma unroll
            for (int ks = 0; ks < 2; ks++) {
                uint32_t ah[4], al[4];
                ldsm_x4(ah, sb + a_off[mt] + ks * 32);
                ldsm_x4(al, sb + offAl + a_off[mt] + ks * 32);
                #pragma unroll
                for (int n8 = 0; n8 < 4; n8++) {
                    const uint32_t* ph = &bh[n8 >> 1][ks][(n8 & 1) * 2];
                    const uint32_t* pl = &bl[n8 >> 1][ks][(n8 & 1) * 2];
                    mma16816(acc[mt][n8], ah, ph);
                    mma16816(acc[mt][n8], ah, pl);
                    mma16816(acc[mt][n8], al, ph);
                }
            }
        }

        if (it + 1 < KITERS) {
            CP_WAIT0();
            __syncthreads();
        }
    }

    #pragma unroll
    for (int mt = 0; mt < 4; mt++) {
        int r0g = m0 + mt * 16 + (lane >> 2);
        float mv0 = maskrow[r0g], mv1 = maskrow[r0g + 8];
        float* y0 = Y + (size_t)r0g * CCH;
        float* y1 = y0 + (size_t)8 * CCH;
        #pragma unroll
        for (int n8 = 0; n8 < 4; n8++) {
            int c0g = n0 + wn + n8 * 8 + (lane & 3) * 2;
            float b0 = bias[c0g], b1 = bias[c0g + 1];
            float2 v0, v1;
            v0.x = fmaxf(acc[mt][n8][0] + b0, 0.f) * mv0;
            v0.y = fmaxf(acc[mt][n8][1] + b1, 0.f) * mv0;
            v1.x = fmaxf(acc[mt][n8][2] + b0, 0.f) * mv1;
            v1.y = fmaxf(acc[mt][n8][3] + b1, 0.f) * mv1;
            *(float2*)(y0 + c0g) = v0;
            *(float2*)(y1 + c0g) = v1;
        }
    }
}

// ---------------------------------------------------------------------------
extern "C" void kernel_launch(void* const* d_in, const int* in_sizes, int n_in,
                              void* d_out, int out_size) {
    const float *feats[3] = {}, *masks[3] = {}, *offs[3] = {};
    const float *w[2] = {}, *bias[2] = {}, *ow[2] = {}, *ob[2] = {};
    int wi = 0, bi = 0, owi = 0, obi = 0;
    for (int i = 0; i < n_in; i++) {
        const float* p = (const float*)d_in[i];
        switch (in_sizes[i]) {
            case 8 * 512 * 2048: feats[0] = p; break;
            case 8 * 512 * 1024: feats[1] = p; break;
            case 8 * 512 * 512:  feats[2] = p; break;
            case 8 * 2048:       masks[0] = p; break;
            case 8 * 1024:       masks[1] = p; break;
            case 8 * 512:        masks[2] = p; break;
            case 8 * 3 * 2048:   offs[0] = p; break;
            case 8 * 3 * 1024:   offs[1] = p; break;
            case 8 * 3 * 512:    offs[2] = p; break;
            case 512 * 512 * 3:  if (wi < 2)  w[wi++] = p; break;
            case 512:            if (bi < 2)  bias[bi++] = p; break;
            case 3 * 512 * 3:    if (owi < 2) ow[owi++] = p; break;
            case 3:              if (obi < 2) ob[obi++] = p; break;
            default: break;
        }
    }

    float *xb, *yb, *offa, *offb, *mrow;
    __nv_bfloat16 *Ah, *Al, *Wh, *Wl;
    cudaGetSymbolAddress((void**)&xb, g_x);
    cudaGetSymbolAddress((void**)&yb, g_y);
    cudaGetSymbolAddress((void**)&offa, g_offa);
    cudaGetSymbolAddress((void**)&offb, g_offb);
    cudaGetSymbolAddress((void**)&mrow, g_mrow);
    cudaGetSymbolAddress((void**)&Ah, g_Ah);
    cudaGetSymbolAddress((void**)&Al, g_Al);
    cudaGetSymbolAddress((void**)&Wh, g_Wh);
    cudaGetSymbolAddress((void**)&Wl, g_Wl);
    float* out = (float*)d_out;

    cudaFuncSetAttribute(gemm_mma_kernel,
                         cudaFuncAttributeMaxDynamicSharedMemorySize, GEMM_SMEM);
    cudaFuncSetAttribute(offset_kernel<true>,
                         cudaFuncAttributeMaxDynamicSharedMemorySize, OFF_SMEM);
    cudaFuncSetAttribute(offset_kernel<false>,
                         cudaFuncAttributeMaxDynamicSharedMemorySize, OFF_SMEM);

    // launch 0: merged prep (transposes + weight split + mask rows + bool out)
    prep_all_kernel<<<PREP_BLOCKS, 256>>>(feats[0], feats[1], feats[2],
                                          w[0], w[1], masks[0], masks[1], masks[2],
                                          xb, Wh, Wl, mrow, out);

    // ---- layer 0 ----  (launches 1,2,3 — ncu captures launch 3 = GEMM)
    offset_kernel<true><<<ROWS_TOTAL / 32, 256, OFF_SMEM>>>(
        xb, offs[0], offs[1], offs[2], ow[0], ob[0], offa);
    im2col_split_kernel<<<dim3(ROWS_TOTAL, KT), 128>>>(xb, offa, Ah, Al);
    gemm_mma_kernel<<<dim3(4, ROWS_TOTAL / BMM), 128, GEMM_SMEM>>>(
        Ah, Al, Wh, Wl, bias[0], mrow, yb);

    // ---- layer 1 ----
    offset_kernel<false><<<ROWS_TOTAL / 32, 256, OFF_SMEM>>>(
        yb, offa, nullptr, nullptr, ow[1], ob[1], offb);
    im2col_split_kernel<<<dim3(ROWS_TOTAL, KT), 128>>>(yb, offb, Ah, Al);
    gemm_mma_kernel<<<dim3(4, ROWS_TOTAL / BMM), 128, GEMM_SMEM>>>(
        Ah, Al, Wh + (size_t)KRED * CCH, Wl + (size_t)KRED * CCH,
        bias[1], mrow, xb);

    // outputs
    tout_kernel<<<dim3(16, 112, 8), dim3(32, 8)>>>(xb, out);
}

// round 13
// speedup vs baseline: 1.2687x; 1.0519x over previous
#include <cuda_runtime.h>
#include <cuda_bf16.h>
#include <cstdint>

// ---------------------------------------------------------------------------
// FeatureAlign via mma.sync bf16 (HMMA) with fp32->bf16 hi/lo splitting.
//   Y = relu( A(fp32 gathered) @ W(fp32) + b ) * mask
//   A@W ~= Ah@Wh + Ah@Wl + Al@Wh   (fp32 accum)
// GEMM: BMM=64, 4 warps/CTA, 2-stage cp.async, 4 CTAs/SM.
// Offset conv + im2col gather FUSED into one deform_kernel per layer.
// ---------------------------------------------------------------------------

#define BSZ 8
#define CCH 512
#define KT  3
#define ROWS_TOTAL 28672
#define LV0 16384
#define LV01 24576
#define KRED 1536

// GEMM tiling
#define BMM 64
#define BNN 128
#define BKK 32
#define AST 40
#define BST 136
#define A_ELE (BMM*AST)             // 2560
#define B_ELE (BKK*BST)             // 4352
#define STG_BYTES ((2*A_ELE + 2*B_ELE)*2)   // 27648 B per stage
#define NSTAGE 2
#define GEMM_SMEM (NSTAGE*STG_BYTES)        // 55296 B; 4 CTAs/SM
#define KITERS (KRED/BKK)           // 48

// deform kernel smem: 34 staged rows + transposed weights + off values
#define OFF_XS_FLOATS (34*CCH)              // 17408
#define DEF_SMEM ((OFF_XS_FLOATS + KT*KT*CCH + 96) * 4)   // 88448 B

#define TIN_BLOCKS 14336                    // 112*16*8

// scratch (device globals; no runtime allocation allowed)
__device__ float g_x[ROWS_TOTAL * CCH];
__device__ float g_y[ROWS_TOTAL * CCH];
__device__ float g_offa[ROWS_TOTAL * 4];
__device__ float g_mrow[ROWS_TOTAL];
__device__ __nv_bfloat16 g_Ah[(size_t)ROWS_TOTAL * KRED];
__device__ __nv_bfloat16 g_Al[(size_t)ROWS_TOTAL * KRED];
__device__ __nv_bfloat16 g_Wh[2 * KRED * CCH];
__device__ __nv_bfloat16 g_Wl[2 * KRED * CCH];

// ---------------------------------------------------------------------------
__device__ __forceinline__ uint32_t smem_u32(const void* p) {
    return (uint32_t)__cvta_generic_to_shared(p);
}
#define CP16(sa, gp) \
    asm volatile("cp.async.cg.shared.global [%0], [%1], 16;" :: "r"(sa), "l"(gp))
#define CP_COMMIT() asm volatile("cp.async.commit_group;")
#define CP_WAIT0()  asm volatile("cp.async.wait_group 0;")

__device__ __forceinline__ void ldsm_x4(uint32_t* r, uint32_t a) {
    asm volatile("ldmatrix.sync.aligned.m8n8.x4.shared.b16 {%0,%1,%2,%3}, [%4];"
                 : "=r"(r[0]), "=r"(r[1]), "=r"(r[2]), "=r"(r[3]) : "r"(a));
}
__device__ __forceinline__ void ldsm_x4_t(uint32_t* r, uint32_t a) {
    asm volatile("ldmatrix.sync.aligned.m8n8.x4.trans.shared.b16 {%0,%1,%2,%3}, [%4];"
                 : "=r"(r[0]), "=r"(r[1]), "=r"(r[2]), "=r"(r[3]) : "r"(a));
}
__device__ __forceinline__ void mma16816(float* d, const uint32_t* a,
                                         const uint32_t* b) {
    asm volatile("mma.sync.aligned.m16n8k16.row.col.f32.bf16.bf16.f32 "
                 "{%0,%1,%2,%3}, {%4,%5,%6,%7}, {%8,%9}, {%0,%1,%2,%3};"
                 : "+f"(d[0]), "+f"(d[1]), "+f"(d[2]), "+f"(d[3])
                 : "r"(a[0]), "r"(a[1]), "r"(a[2]), "r"(a[3]), "r"(b[0]), "r"(b[1]));
}

// ---------------------------------------------------------------------------
// input transposes: feats (B,C,T) per level -> concatenated rows (m, C)
__global__ void tin_kernel(const float* __restrict__ f0,
                           const float* __restrict__ f1,
                           const float* __restrict__ f2,
                           float* __restrict__ xb) {
    __shared__ float tile[32][33];
    int bid = blockIdx.x, tid = threadIdx.x;
    int xv = bid % 112;
    int y  = (bid / 112) % 16;
    int b  = bid / (112 * 16);
    int lv, xs, T, lbase;
    if (xv < 64)      { lv = 0; xs = xv;      T = 2048; lbase = 0;    }
    else if (xv < 96) { lv = 1; xs = xv - 64; T = 1024; lbase = LV0;  }
    else              { lv = 2; xs = xv - 96; T = 512;  lbase = LV01; }
    const float* f = (lv == 0) ? f0 : (lv == 1 ? f1 : f2);
    int tx = tid & 31, ty = tid >> 5;
    int s0 = xs * 32, r0 = y * 32;
    const float* inb = f + (size_t)b * CCH * T;
    float* outb = xb + (size_t)(lbase + b * T) * CCH;
    #pragma unroll
    for (int i = ty; i < 32; i += 8)
        tile[i][tx] = inb[(size_t)(r0 + i) * T + s0 + tx];
    __syncthreads();
    #pragma unroll
    for (int i = ty; i < 32; i += 8)
        outb[(size_t)(s0 + i) * CCH + r0 + tx] = tile[tx][i];
}

// weight bf16 hi/lo split
__global__ void wsplit_kernel(const float* __restrict__ w0,
                              const float* __restrict__ w1,
                              __nv_bfloat16* __restrict__ Wh,
                              __nv_bfloat16* __restrict__ Wl) {
    int idx = blockIdx.x * blockDim.x + threadIdx.x;
    if (idx >= 2 * KRED * CCH) return;
    int n = idx & 511;
    int k = (idx >> 9) % KRED;
    int l = idx / (KRED * CCH);
    int ktap = k >> 9, c = k & 511;
    const float* w = l ? w1 : w0;
    float val = w[(n * CCH + c) * KT + ktap];
    __nv_bfloat16 hi = __float2bfloat16(val);
    Wh[idx] = hi;
    Wl[idx] = __float2bfloat16(val - __bfloat162float(hi));
}

// mask rows + bool outputs
__global__ void maskrow_kernel(const float* __restrict__ m0,
                               const float* __restrict__ m1,
                               const float* __restrict__ m2,
                               float* __restrict__ mrow,
                               float* __restrict__ out) {
    int m = blockIdx.x * 256 + threadIdx.x;
    if (m >= ROWS_TOTAL) return;
    float v = (m < LV0) ? m0[m] : (m < LV01 ? m1[m - LV0] : m2[m - LV01]);
    mrow[m] = v;
    out[(size_t)BSZ * CCH * 3584 + m] = (v != 0.f) ? 1.0f : 0.0f;
}

// ---------------------------------------------------------------------------
// merged output transpose: rows (m, C) -> out (B,C,T) per level slot
__global__ void tout_kernel(const float* __restrict__ xb,
                            float* __restrict__ out) {
    __shared__ float tile[32][33];
    int yv = blockIdx.y;
    int ys, T, lbase;
    size_t obase;
    if (yv < 64)      { ys = yv;      T = 2048; lbase = 0;
                        obase = 0; }
    else if (yv < 96) { ys = yv - 64; T = 1024; lbase = LV0;
                        obase = (size_t)BSZ * CCH * 2048; }
    else              { ys = yv - 96; T = 512;  lbase = LV01;
                        obase = (size_t)BSZ * CCH * (2048 + 1024); }
    int b = blockIdx.z;
    int r0 = ys * 32;
    int s0 = blockIdx.x * 32;
    const float* inb = xb + (size_t)(lbase + b * T) * CCH;
    float* outb = out + obase + (size_t)b * CCH * T;
    #pragma unroll
    for (int i = threadIdx.y; i < 32; i += 8)
        tile[i][threadIdx.x] = inb[(size_t)(r0 + i) * CCH + s0 + threadIdx.x];
    __syncthreads();
    #pragma unroll
    for (int i = threadIdx.y; i < 32; i += 8)
        outb[(size_t)(s0 + i) * T + r0 + threadIdx.x] = tile[threadIdx.x][i];
}

// ---------------------------------------------------------------------------
// FUSED deform kernel: offset conv + im2col gather + bf16 split.
// Block = 32 consecutive rows (one level), 256 threads.
// Phase 1: conv1d(x, ow)+ob+off_in -> off (smem + global for layer 0).
// Phase 2: gather/lerp A rows at offset positions -> Ah/Al (bf16 hi/lo).
template <bool EXT>
__global__ void deform_kernel(const float* __restrict__ X,
                              const float* __restrict__ o0,
                              const float* __restrict__ o1,
                              const float* __restrict__ o2,
                              const float* __restrict__ ow,
                              const float* __restrict__ ob,
                              float* __restrict__ off_out,
                              __nv_bfloat16* __restrict__ Ah,
                              __nv_bfloat16* __restrict__ Al) {
    extern __shared__ float sdyn[];
    float* xs = sdyn;                                   // 34*512
    float* ow_sh2 = sdyn + OFF_XS_FLOATS;               // 4608
    float* off_sh = ow_sh2 + KT * KT * CCH;             // 96
    int tid = threadIdx.x;

    int rl0g = blockIdx.x * 32;
    int lv = (rl0g < LV0) ? 0 : (rl0g < LV01 ? 1 : 2);
    int lbase = (lv == 0) ? 0 : (lv == 1 ? LV0 : LV01);
    int logT = 11 - lv;
    int T = 1 << logT;
    int rl0 = rl0g - lbase;
    const float* Xl = X + (size_t)lbase * CCH;

    for (int i = tid; i < KT * KT * CCH; i += 256) {
        int j = i % 3;
        int r = i / 3;
        int kk = r >> 9, c = r & 511;
        ow_sh2[(kk * 3 + j) * CCH + c] = ow[i];
    }

    int t0 = rl0 & (T - 1);
    // stage rows rl0-1 .. rl0+32 (t0-1 .. t0+32), zero outside [0,T)
    for (int fi = tid; fi < 34 * 128; fi += 256) {
        int j = fi >> 7;
        int cf = (fi & 127) * 4;
        int t = t0 + j - 1;
        float4 v = make_float4(0.f, 0.f, 0.f, 0.f);
        if (t >= 0 && t < T)
            v = *(const float4*)(Xl + (size_t)(rl0 - 1 + j) * CCH + cf);
        *(float4*)(xs + j * CCH + cf) = v;
    }
    __syncthreads();

    int warp = tid >> 5, lane = tid & 31;
    int r0l = warp * 4;

    // ---- phase 1: offset conv, 4 rows per warp ----
    {
        float acc[4][3];
        #pragma unroll
        for (int i = 0; i < 4; i++)
            #pragma unroll
            for (int kk = 0; kk < 3; kk++) acc[i][kk] = 0.f;

        #pragma unroll
        for (int q = 0; q < 4; q++) {
            int c = lane * 4 + q * 128;
            float4 wv[3][3];
            #pragma unroll
            for (int kk = 0; kk < 3; kk++)
                #pragma unroll
                for (int j = 0; j < 3; j++)
                    wv[kk][j] = *(const float4*)(ow_sh2 + (kk * 3 + j) * CCH + c);
            float4 xv[6];
            #pragma unroll
            for (int u = 0; u < 6; u++)
                xv[u] = *(const float4*)(xs + (r0l + u) * CCH + c);
            #pragma unroll
            for (int i = 0; i < 4; i++) {
                #pragma unroll
                for (int kk = 0; kk < 3; kk++) {
                    float s = 0.f;
                    #pragma unroll
                    for (int j = 0; j < 3; j++) {
                        float4 wf = wv[kk][j];
                        float4 xf = xv[i + j];
                        s += wf.x * xf.x + wf.y * xf.y + wf.z * xf.z + wf.w * xf.w;
                    }
                    acc[i][kk] += s;
                }
            }
        }

        #pragma unroll
        for (int i = 0; i < 4; i++)
            #pragma unroll
            for (int kk = 0; kk < 3; kk++)
                #pragma unroll
                for (int s = 16; s; s >>= 1)
                    acc[i][kk] += __shfl_down_sync(0xffffffffu, acc[i][kk], s);

        if (lane == 0) {
            #pragma unroll
            for (int i = 0; i < 4; i++) {
                int rl = rl0 + r0l + i;
                int b = rl >> logT, t = rl & (T - 1);
                int m = rl0g + r0l + i;
                float i0, i1, i2;
                if (EXT) {
                    const float* oin = (lv == 0) ? o0 : (lv == 1 ? o1 : o2);
                    i0 = oin[((size_t)b * KT + 0) * T + t];
                    i1 = oin[((size_t)b * KT + 1) * T + t];
                    i2 = oin[((size_t)b * KT + 2) * T + t];
                } else {
                    i0 = o0[(size_t)m * 4 + 0];
                    i1 = o0[(size_t)m * 4 + 1];
                    i2 = o0[(size_t)m * 4 + 2];
                }
                float v0 = acc[i][0] + ob[0] + i0;
                float v1 = acc[i][1] + ob[1] + i1;
                float v2 = acc[i][2] + ob[2] + i2;
                off_sh[(r0l + i) * 3 + 0] = v0;
                off_sh[(r0l + i) * 3 + 1] = v1;
                off_sh[(r0l + i) * 3 + 2] = v2;
                if (EXT) {               // layer 0's offsets feed layer 1
                    off_out[(size_t)m * 4 + 0] = v0;
                    off_out[(size_t)m * 4 + 1] = v1;
                    off_out[(size_t)m * 4 + 2] = v2;
                }
            }
        }
    }
    __syncthreads();

    // ---- phase 2: gather + lerp + bf16 hi/lo split; 12 (row,tap) pairs/warp
    #pragma unroll 2
    for (int pi = 0; pi < 12; pi++) {
        int pair = warp * 12 + pi;          // 0..95
        int r = pair / 3, k = pair % 3;
        int rl = rl0 + r;
        int b = rl >> logT, t = rl & (T - 1);
        int m = rl0g + r;

        float off = off_sh[r * 3 + k];
        float pos = (float)(t + k - 1) + off;
        float p0f = floorf(pos);
        float f = pos - p0f;
        int i0 = (int)p0f, i1 = i0 + 1;
        float w0 = (i0 >= 0 && i0 < T) ? (1.0f - f) : 0.0f;
        float w1 = (i1 >= 0 && i1 < T) ? f : 0.0f;
        int i0c = min(max(i0, 0), T - 1);
        int i1c = min(max(i1, 0), T - 1);

        int j0 = i0c - t0 + 1, j1 = i1c - t0 + 1;
        const float* p0 = (j0 >= 0 && j0 < 34)
            ? xs + (size_t)j0 * CCH
            : Xl + ((size_t)(b << logT) + i0c) * CCH;
        const float* p1 = (j1 >= 0 && j1 < 34)
            ? xs + (size_t)j1 * CCH
            : Xl + ((size_t)(b << logT) + i1c) * CCH;

        size_t base = (size_t)m * KRED + (size_t)k * CCH;
        #pragma unroll
        for (int q = 0; q < 4; q++) {
            int ch = (lane + q * 32) * 4;
            float4 a = *(const float4*)(p0 + ch);
            float4 c = *(const float4*)(p1 + ch);
            float e0 = w0 * a.x + w1 * c.x;
            float e1 = w0 * a.y + w1 * c.y;
            float e2 = w0 * a.z + w1 * c.z;
            float e3 = w0 * a.w + w1 * c.w;

            __nv_bfloat162 h01 = __floats2bfloat162_rn(e0, e1);
            __nv_bfloat162 h23 = __floats2bfloat162_rn(e2, e3);
            float2 f01 = __bfloat1622float2(h01);
            float2 f23 = __bfloat1622float2(h23);
            __nv_bfloat162 l01 = __floats2bfloat162_rn(e0 - f01.x, e1 - f01.y);
            __nv_bfloat162 l23 = __floats2bfloat162_rn(e2 - f23.x, e3 - f23.y);

            uint2 hv, lvv;
            hv.x = *reinterpret_cast<uint32_t*>(&h01);
            hv.y = *reinterpret_cast<uint32_t*>(&h23);
            lvv.x = *reinterpret_cast<uint32_t*>(&l01);
            lvv.y = *reinterpret_cast<uint32_t*>(&l23);
            *(uint2*)(Ah + base + ch) = hv;
            *(uint2*)(Al + base + ch) = lvv;
        }
    }
}

// ---------------------------------------------------------------------------
// GEMM: Y[m,n] = relu( (Ah@Wh + Ah@Wl + Al@Wh)[m,n] + bias[n] ) * maskrow[m]
// grid (4, 448), 128 threads (4 warps, warp tile 64x32), 2-stage, 4 CTAs/SM.
__global__ __launch_bounds__(128, 4)
void gemm_mma_kernel(const __nv_bfloat16* __restrict__ Ahg,
                     const __nv_bfloat16* __restrict__ Alg,
                     const __nv_bfloat16* __restrict__ Whg,
                     const __nv_bfloat16* __restrict__ Wlg,
                     const float* __restrict__ bias,
                     const float* __restrict__ maskrow,
                     float* __restrict__ Y) {
    extern __shared__ __nv_bfloat16 sm[];
    uint32_t sbase = smem_u32(sm);
    int tid = threadIdx.x, warp = tid >> 5, lane = tid & 31;
    int m0 = blockIdx.y * BMM, n0 = blockIdx.x * BNN;

    const uint32_t offAl = A_ELE * 2;
    const uint32_t offBh = 2 * A_ELE * 2;
    const uint32_t offBl = offBh + B_ELE * 2;

    int ar0 = tid >> 2, akc = (tid & 3) * 8;
    int br0 = tid >> 4, bnc = (tid & 15) * 8;
    const __nv_bfloat16* gAh = Ahg + (size_t)(m0 + ar0) * KRED + akc;
    const __nv_bfloat16* gAl = Alg + (size_t)(m0 + ar0) * KRED + akc;
    const __nv_bfloat16* gBh = Whg + (size_t)br0 * CCH + n0 + bnc;
    const __nv_bfloat16* gBl = Wlg + (size_t)br0 * CCH + n0 + bnc;
    const uint32_t A2 = 32u * KRED;
    uint32_t sA0 = (uint32_t)(ar0 * AST + akc) * 2;
    uint32_t sA1 = sA0 + 32u * AST * 2;
    uint32_t sB0 = (uint32_t)(br0 * BST + bnc) * 2;

    int wn = warp * 32;
    int lr = lane & 15, lc = lane >> 4;
    uint32_t a_off[4], b_off[2];
    #pragma unroll
    for (int mt = 0; mt < 4; mt++)
        a_off[mt] = (uint32_t)((mt * 16 + lr) * AST + lc * 8) * 2;
    #pragma unroll
    for (int nt = 0; nt < 2; nt++)
        b_off[nt] = (uint32_t)(lr * BST + wn + nt * 16 + lc * 8) * 2;

    float acc[4][4][4];
    #pragma unroll
    for (int i = 0; i < 4; i++)
        #pragma unroll
        for (int j = 0; j < 4; j++)
            #pragma unroll
            for (int q = 0; q < 4; q++) acc[i][j][q] = 0.f;

    auto load_stage = [&](int st, int k0) {
        uint32_t sb = sbase + (uint32_t)st * STG_BYTES;
        CP16(sb + sA0, gAh + k0);
        CP16(sb + sA1, gAh + A2 + k0);
        CP16(sb + offAl + sA0, gAl + k0);
        CP16(sb + offAl + sA1, gAl + A2 + k0);
        #pragma unroll
        for (int c = 0; c < 4; c++) {
            uint32_t so = sB0 + (uint32_t)c * 8 * BST * 2;
            size_t go = (size_t)(k0 + c * 8) * CCH;
            CP16(sb + offBh + so, gBh + go);
            CP16(sb + offBl + so, gBl + go);
        }
    };

    load_stage(0, 0);
    CP_COMMIT();
    CP_WAIT0();
    __syncthreads();

    for (int it = 0; it < KITERS; it++) {
        if (it + 1 < KITERS) {
            load_stage((it + 1) & 1, (it + 1) * BKK);
            CP_COMMIT();
        }

        uint32_t sb = sbase + (uint32_t)(it & 1) * STG_BYTES;

        uint32_t bh[2][2][4], bl[2][2][4];
        #pragma unroll
        for (int ks = 0; ks < 2; ks++)
            #pragma unroll
            for (int nt = 0; nt < 2; nt++) {
                ldsm_x4_t(bh[nt][ks], sb + offBh + b_off[nt] + ks * (16 * BST * 2));
                ldsm_x4_t(bl[nt][ks], sb + offBl + b_off[nt] + ks * (16 * BST * 2));
            }

        #pragma unroll
        for (int mt = 0; mt < 4; mt++) {
            #pragma unroll
            for (int ks = 0; ks < 2; ks++) {
                uint32_t ah[4], al[4];
                ldsm_x4(ah, sb + a_off[mt] + ks * 32);
                ldsm_x4(al, sb + offAl + a_off[mt] + ks * 32);
                #pragma unroll
                for (int n8 = 0; n8 < 4; n8++) {
                    const uint32_t* ph = &bh[n8 >> 1][ks][(n8 & 1) * 2];
                    const uint32_t* pl = &bl[n8 >> 1][ks][(n8 & 1) * 2];
                    mma16816(acc[mt][n8], ah, ph);
                    mma16816(acc[mt][n8], ah, pl);
                    mma16816(acc[mt][n8], al, ph);
                }
            }
        }

        if (it + 1 < KITERS) {
            CP_WAIT0();
            __syncthreads();
        }
    }

    #pragma unroll
    for (int mt = 0; mt < 4; mt++) {
        int r0g = m0 + mt * 16 + (lane >> 2);
        float mv0 = maskrow[r0g], mv1 = maskrow[r0g + 8];
        float* y0 = Y + (size_t)r0g * CCH;
        float* y1 = y0 + (size_t)8 * CCH;
        #pragma unroll
        for (int n8 = 0; n8 < 4; n8++) {
            int c0g = n0 + wn + n8 * 8 + (lane & 3) * 2;
            float b0 = bias[c0g], b1 = bias[c0g + 1];
            float2 v0, v1;
            v0.x = fmaxf(acc[mt][n8][0] + b0, 0.f) * mv0;
            v0.y = fmaxf(acc[mt][n8][1] + b1, 0.f) * mv0;
            v1.x = fmaxf(acc[mt][n8][2] + b0, 0.f) * mv1;
            v1.y = fmaxf(acc[mt][n8][3] + b1, 0.f) * mv1;
            *(float2*)(y0 + c0g) = v0;
            *(float2*)(y1 + c0g) = v1;
        }
    }
}

// ---------------------------------------------------------------------------
extern "C" void kernel_launch(void* const* d_in, const int* in_sizes, int n_in,
                              void* d_out, int out_size) {
    const float *feats[3] = {}, *masks[3] = {}, *offs[3] = {};
    const float *w[2] = {}, *bias[2] = {}, *ow[2] = {}, *ob[2] = {};
    int wi = 0, bi = 0, owi = 0, obi = 0;
    for (int i = 0; i < n_in; i++) {
        const float* p = (const float*)d_in[i];
        switch (in_sizes[i]) {
            case 8 * 512 * 2048: feats[0] = p; break;
            case 8 * 512 * 1024: feats[1] = p; break;
            case 8 * 512 * 512:  feats[2] = p; break;
            case 8 * 2048:       masks[0] = p; break;
            case 8 * 1024:       masks[1] = p; break;
            case 8 * 512:        masks[2] = p; break;
            case 8 * 3 * 2048:   offs[0] = p; break;
            case 8 * 3 * 1024:   offs[1] = p; break;
            case 8 * 3 * 512:    offs[2] = p; break;
            case 512 * 512 * 3:  if (wi < 2)  w[wi++] = p; break;
            case 512:            if (bi < 2)  bias[bi++] = p; break;
            case 3 * 512 * 3:    if (owi < 2) ow[owi++] = p; break;
            case 3:              if (obi < 2) ob[obi++] = p; break;
            default: break;
        }
    }

    float *xb, *yb, *offa, *mrow;
    __nv_bfloat16 *Ah, *Al, *Wh, *Wl;
    cudaGetSymbolAddress((void**)&xb, g_x);
    cudaGetSymbolAddress((void**)&yb, g_y);
    cudaGetSymbolAddress((void**)&offa, g_offa);
    cudaGetSymbolAddress((void**)&mrow, g_mrow);
    cudaGetSymbolAddress((void**)&Ah, g_Ah);
    cudaGetSymbolAddress((void**)&Al, g_Al);
    cudaGetSymbolAddress((void**)&Wh, g_Wh);
    cudaGetSymbolAddress((void**)&Wl, g_Wl);
    float* out = (float*)d_out;

    cudaFuncSetAttribute(gemm_mma_kernel,
                         cudaFuncAttributeMaxDynamicSharedMemorySize, GEMM_SMEM);
    cudaFuncSetAttribute(deform_kernel<true>,
                         cudaFuncAttributeMaxDynamicSharedMemorySize, DEF_SMEM);
    cudaFuncSetAttribute(deform_kernel<false>,
                         cudaFuncAttributeMaxDynamicSharedMemorySize, DEF_SMEM);

    // launches 0-2: prep (transposes, weight split, mask rows + bool out)
    tin_kernel<<<TIN_BLOCKS, 256>>>(feats[0], feats[1], feats[2], xb);
    wsplit_kernel<<<(2 * KRED * CCH + 255) / 256, 256>>>(w[0], w[1], Wh, Wl);
    maskrow_kernel<<<(ROWS_TOTAL + 255) / 256, 256>>>(masks[0], masks[1],
                                                      masks[2], mrow, out);

    // ---- layer 0 ----  (launches 3,4)
    deform_kernel<true><<<ROWS_TOTAL / 32, 256, DEF_SMEM>>>(
        xb, offs[0], offs[1], offs[2], ow[0], ob[0], offa, Ah, Al);
    gemm_mma_kernel<<<dim3(4, ROWS_TOTAL / BMM), 128, GEMM_SMEM>>>(
        Ah, Al, Wh, Wl, bias[0], mrow, yb);

    // ---- layer 1 ----  (launch 5 = deform<false> — captured by ncu)
    deform_kernel<false><<<ROWS_TOTAL / 32, 256, DEF_SMEM>>>(
        yb, offa, nullptr, nullptr, ow[1], ob[1], nullptr, Ah, Al);
    gemm_mma_kernel<<<dim3(4, ROWS_TOTAL / BMM), 128, GEMM_SMEM>>>(
        Ah, Al, Wh + (size_t)KRED * CCH, Wl + (size_t)KRED * CCH,
        bias[1], mrow, xb);

    // outputs
    tout_kernel<<<dim3(16, 112, 8), dim3(32, 8)>>>(xb, out);
}

// round 14
// speedup vs baseline: 1.3070x; 1.0302x over previous
#include <cuda_runtime.h>
#include <cuda_bf16.h>
#include <cstdint>

// ---------------------------------------------------------------------------
// FeatureAlign via mma.sync bf16 (HMMA) with fp32->bf16 hi/lo splitting.
//   Y = relu( A(fp32 gathered) @ W(fp32) + b ) * mask
//   A@W ~= Ah@Wh + Ah@Wl + Al@Wh   (fp32 accum)
// GEMM: BMM=64, 4 warps/CTA, 2-stage cp.async, 4 CTAs/SM.
// deform (offset conv + gather + split): 16-row blocks, 4 CTAs/SM.
// ---------------------------------------------------------------------------

#define BSZ 8
#define CCH 512
#define KT  3
#define ROWS_TOTAL 28672
#define LV0 16384
#define LV01 24576
#define KRED 1536

// GEMM tiling
#define BMM 64
#define BNN 128
#define BKK 32
#define AST 40
#define BST 136
#define A_ELE (BMM*AST)             // 2560
#define B_ELE (BKK*BST)             // 4352
#define STG_BYTES ((2*A_ELE + 2*B_ELE)*2)   // 27648 B per stage
#define NSTAGE 2
#define GEMM_SMEM (NSTAGE*STG_BYTES)        // 55296 B; 4 CTAs/SM
#define KITERS (KRED/BKK)           // 48

// deform kernel: 16 rows/block, 18 staged rows
#define DROWS 16
#define DSTG  18
#define OFF_XS_FLOATS (DSTG*CCH)            // 9216
#define DEF_SMEM ((OFF_XS_FLOATS + KT*KT*CCH + DROWS*3) * 4)   // 55488 B

#define TIN_BLOCKS 14336                    // 112*16*8

// scratch (device globals; no runtime allocation allowed)
__device__ float g_x[ROWS_TOTAL * CCH];
__device__ float g_y[ROWS_TOTAL * CCH];
__device__ float g_offa[ROWS_TOTAL * 4];
__device__ float g_mrow[ROWS_TOTAL];
__device__ __nv_bfloat16 g_Ah[(size_t)ROWS_TOTAL * KRED];
__device__ __nv_bfloat16 g_Al[(size_t)ROWS_TOTAL * KRED];
__device__ __nv_bfloat16 g_Wh[2 * KRED * CCH];
__device__ __nv_bfloat16 g_Wl[2 * KRED * CCH];

// ---------------------------------------------------------------------------
__device__ __forceinline__ uint32_t smem_u32(const void* p) {
    return (uint32_t)__cvta_generic_to_shared(p);
}
#define CP16(sa, gp) \
    asm volatile("cp.async.cg.shared.global [%0], [%1], 16;" :: "r"(sa), "l"(gp))
#define CP_COMMIT() asm volatile("cp.async.commit_group;")
#define CP_WAIT0()  asm volatile("cp.async.wait_group 0;")

__device__ __forceinline__ void ldsm_x4(uint32_t* r, uint32_t a) {
    asm volatile("ldmatrix.sync.aligned.m8n8.x4.shared.b16 {%0,%1,%2,%3}, [%4];"
                 : "=r"(r[0]), "=r"(r[1]), "=r"(r[2]), "=r"(r[3]) : "r"(a));
}
__device__ __forceinline__ void ldsm_x4_t(uint32_t* r, uint32_t a) {
    asm volatile("ldmatrix.sync.aligned.m8n8.x4.trans.shared.b16 {%0,%1,%2,%3}, [%4];"
                 : "=r"(r[0]), "=r"(r[1]), "=r"(r[2]), "=r"(r[3]) : "r"(a));
}
__device__ __forceinline__ void mma16816(float* d, const uint32_t* a,
                                         const uint32_t* b) {
    asm volatile("mma.sync.aligned.m16n8k16.row.col.f32.bf16.bf16.f32 "
                 "{%0,%1,%2,%3}, {%4,%5,%6,%7}, {%8,%9}, {%0,%1,%2,%3};"
                 : "+f"(d[0]), "+f"(d[1]), "+f"(d[2]), "+f"(d[3])
                 : "r"(a[0]), "r"(a[1]), "r"(a[2]), "r"(a[3]), "r"(b[0]), "r"(b[1]));
}

// ---------------------------------------------------------------------------
// input transposes: feats (B,C,T) per level -> concatenated rows (m, C)
__global__ void tin_kernel(const float* __restrict__ f0,
                           const float* __restrict__ f1,
                           const float* __restrict__ f2,
                           float* __restrict__ xb) {
    __shared__ float tile[32][33];
    int bid = blockIdx.x, tid = threadIdx.x;
    int xv = bid % 112;
    int y  = (bid / 112) % 16;
    int b  = bid / (112 * 16);
    int lv, xs, T, lbase;
    if (xv < 64)      { lv = 0; xs = xv;      T = 2048; lbase = 0;    }
    else if (xv < 96) { lv = 1; xs = xv - 64; T = 1024; lbase = LV0;  }
    else              { lv = 2; xs = xv - 96; T = 512;  lbase = LV01; }
    const float* f = (lv == 0) ? f0 : (lv == 1 ? f1 : f2);
    int tx = tid & 31, ty = tid >> 5;
    int s0 = xs * 32, r0 = y * 32;
    const float* inb = f + (size_t)b * CCH * T;
    float* outb = xb + (size_t)(lbase + b * T) * CCH;
    #pragma unroll
    for (int i = ty; i < 32; i += 8)
        tile[i][tx] = inb[(size_t)(r0 + i) * T + s0 + tx];
    __syncthreads();
    #pragma unroll
    for (int i = ty; i < 32; i += 8)
        outb[(size_t)(s0 + i) * CCH + r0 + tx] = tile[tx][i];
}

// weight bf16 hi/lo split
__global__ void wsplit_kernel(const float* __restrict__ w0,
                              const float* __restrict__ w1,
                              __nv_bfloat16* __restrict__ Wh,
                              __nv_bfloat16* __restrict__ Wl) {
    int idx = blockIdx.x * blockDim.x + threadIdx.x;
    if (idx >= 2 * KRED * CCH) return;
    int n = idx & 511;
    int k = (idx >> 9) % KRED;
    int l = idx / (KRED * CCH);
    int ktap = k >> 9, c = k & 511;
    const float* w = l ? w1 : w0;
    float val = w[(n * CCH + c) * KT + ktap];
    __nv_bfloat16 hi = __float2bfloat16(val);
    Wh[idx] = hi;
    Wl[idx] = __float2bfloat16(val - __bfloat162float(hi));
}

// mask rows + bool outputs
__global__ void maskrow_kernel(const float* __restrict__ m0,
                               const float* __restrict__ m1,
                               const float* __restrict__ m2,
                               float* __restrict__ mrow,
                               float* __restrict__ out) {
    int m = blockIdx.x * 256 + threadIdx.x;
    if (m >= ROWS_TOTAL) return;
    float v = (m < LV0) ? m0[m] : (m < LV01 ? m1[m - LV0] : m2[m - LV01]);
    mrow[m] = v;
    out[(size_t)BSZ * CCH * 3584 + m] = (v != 0.f) ? 1.0f : 0.0f;
}

// ---------------------------------------------------------------------------
// merged output transpose: rows (m, C) -> out (B,C,T) per level slot
__global__ void tout_kernel(const float* __restrict__ xb,
                            float* __restrict__ out) {
    __shared__ float tile[32][33];
    int yv = blockIdx.y;
    int ys, T, lbase;
    size_t obase;
    if (yv < 64)      { ys = yv;      T = 2048; lbase = 0;
                        obase = 0; }
    else if (yv < 96) { ys = yv - 64; T = 1024; lbase = LV0;
                        obase = (size_t)BSZ * CCH * 2048; }
    else              { ys = yv - 96; T = 512;  lbase = LV01;
                        obase = (size_t)BSZ * CCH * (2048 + 1024); }
    int b = blockIdx.z;
    int r0 = ys * 32;
    int s0 = blockIdx.x * 32;
    const float* inb = xb + (size_t)(lbase + b * T) * CCH;
    float* outb = out + obase + (size_t)b * CCH * T;
    #pragma unroll
    for (int i = threadIdx.y; i < 32; i += 8)
        tile[i][threadIdx.x] = inb[(size_t)(r0 + i) * CCH + s0 + threadIdx.x];
    __syncthreads();
    #pragma unroll
    for (int i = threadIdx.y; i < 32; i += 8)
        outb[(size_t)(s0 + i) * T + r0 + threadIdx.x] = tile[threadIdx.x][i];
}

// ---------------------------------------------------------------------------
// FUSED deform kernel: offset conv + im2col gather + bf16 split.
// Block = 16 consecutive rows (one level), 256 threads, 4 CTAs/SM.
template <bool EXT>
__global__ __launch_bounds__(256, 4)
void deform_kernel(const float* __restrict__ X,
                   const float* __restrict__ o0,
                   const float* __restrict__ o1,
                   const float* __restrict__ o2,
                   const float* __restrict__ ow,
                   const float* __restrict__ ob,
                   float* __restrict__ off_out,
                   __nv_bfloat16* __restrict__ Ah,
                   __nv_bfloat16* __restrict__ Al) {
    extern __shared__ float sdyn[];
    float* xs = sdyn;                                   // 18*512
    float* ow_sh2 = sdyn + OFF_XS_FLOATS;               // 4608
    float* off_sh = ow_sh2 + KT * KT * CCH;             // 48
    int tid = threadIdx.x;

    int rl0g = blockIdx.x * DROWS;
    int lv = (rl0g < LV0) ? 0 : (rl0g < LV01 ? 1 : 2);
    int lbase = (lv == 0) ? 0 : (lv == 1 ? LV0 : LV01);
    int logT = 11 - lv;
    int T = 1 << logT;
    int rl0 = rl0g - lbase;
    const float* Xl = X + (size_t)lbase * CCH;

    for (int i = tid; i < KT * KT * CCH; i += 256) {
        int j = i % 3;
        int r = i / 3;
        int kk = r >> 9, c = r & 511;
        ow_sh2[(kk * 3 + j) * CCH + c] = ow[i];
    }

    int t0 = rl0 & (T - 1);
    // stage rows rl0-1 .. rl0+16 (t0-1 .. t0+16), zero outside [0,T)
    for (int fi = tid; fi < DSTG * 128; fi += 256) {
        int j = fi >> 7;
        int cf = (fi & 127) * 4;
        int t = t0 + j - 1;
        float4 v = make_float4(0.f, 0.f, 0.f, 0.f);
        if (t >= 0 && t < T)
            v = *(const float4*)(Xl + (size_t)(rl0 - 1 + j) * CCH + cf);
        *(float4*)(xs + j * CCH + cf) = v;
    }
    __syncthreads();

    int warp = tid >> 5, lane = tid & 31;
    int r0l = warp * 2;                 // 2 rows per warp

    // ---- phase 1: offset conv ----
    {
        float acc[2][3];
        #pragma unroll
        for (int i = 0; i < 2; i++)
            #pragma unroll
            for (int kk = 0; kk < 3; kk++) acc[i][kk] = 0.f;

        #pragma unroll
        for (int q = 0; q < 4; q++) {
            int c = lane * 4 + q * 128;
            float4 xv[4];
            #pragma unroll
            for (int u = 0; u < 4; u++)
                xv[u] = *(const float4*)(xs + (r0l + u) * CCH + c);
            #pragma unroll
            for (int kk = 0; kk < 3; kk++) {
                float4 wv[3];
                #pragma unroll
                for (int j = 0; j < 3; j++)
                    wv[j] = *(const float4*)(ow_sh2 + (kk * 3 + j) * CCH + c);
                #pragma unroll
                for (int i = 0; i < 2; i++) {
                    float s = 0.f;
                    #pragma unroll
                    for (int j = 0; j < 3; j++) {
                        float4 wf = wv[j];
                        float4 xf = xv[i + j];
                        s += wf.x * xf.x + wf.y * xf.y + wf.z * xf.z + wf.w * xf.w;
                    }
                    acc[i][kk] += s;
                }
            }
        }

        #pragma unroll
        for (int i = 0; i < 2; i++)
            #pragma unroll
            for (int kk = 0; kk < 3; kk++)
                #pragma unroll
                for (int s = 16; s; s >>= 1)
                    acc[i][kk] += __shfl_down_sync(0xffffffffu, acc[i][kk], s);

        if (lane == 0) {
            #pragma unroll
            for (int i = 0; i < 2; i++) {
                int rl = rl0 + r0l + i;
                int b = rl >> logT, t = rl & (T - 1);
                int m = rl0g + r0l + i;
                float i0, i1, i2;
                if (EXT) {
                    const float* oin = (lv == 0) ? o0 : (lv == 1 ? o1 : o2);
                    i0 = oin[((size_t)b * KT + 0) * T + t];
                    i1 = oin[((size_t)b * KT + 1) * T + t];
                    i2 = oin[((size_t)b * KT + 2) * T + t];
                } else {
                    i0 = o0[(size_t)m * 4 + 0];
                    i1 = o0[(size_t)m * 4 + 1];
                    i2 = o0[(size_t)m * 4 + 2];
                }
                float v0 = acc[i][0] + ob[0] + i0;
                float v1 = acc[i][1] + ob[1] + i1;
                float v2 = acc[i][2] + ob[2] + i2;
                off_sh[(r0l + i) * 3 + 0] = v0;
                off_sh[(r0l + i) * 3 + 1] = v1;
                off_sh[(r0l + i) * 3 + 2] = v2;
                if (EXT) {               // layer 0's offsets feed layer 1
                    off_out[(size_t)m * 4 + 0] = v0;
                    off_out[(size_t)m * 4 + 1] = v1;
                    off_out[(size_t)m * 4 + 2] = v2;
                }
            }
        }
    }
    __syncthreads();

    // ---- phase 2: gather + lerp + bf16 hi/lo split; 6 (row,tap) pairs/warp
    #pragma unroll 2
    for (int pi = 0; pi < 6; pi++) {
        int pair = warp * 6 + pi;           // 0..47
        int r = pair / 3, k = pair % 3;
        int rl = rl0 + r;
        int b = rl >> logT, t = rl & (T - 1);
        int m = rl0g + r;

        float off = off_sh[r * 3 + k];
        float pos = (float)(t + k - 1) + off;
        float p0f = floorf(pos);
        float f = pos - p0f;
        int i0 = (int)p0f, i1 = i0 + 1;
        float w0 = (i0 >= 0 && i0 < T) ? (1.0f - f) : 0.0f;
        float w1 = (i1 >= 0 && i1 < T) ? f : 0.0f;
        int i0c = min(max(i0, 0), T - 1);
        int i1c = min(max(i1, 0), T - 1);

        int j0 = i0c - t0 + 1, j1 = i1c - t0 + 1;
        const float* p0 = (j0 >= 0 && j0 < DSTG)
            ? xs + (size_t)j0 * CCH
            : Xl + ((size_t)(b << logT) + i0c) * CCH;
        const float* p1 = (j1 >= 0 && j1 < DSTG)
            ? xs + (size_t)j1 * CCH
            : Xl + ((size_t)(b << logT) + i1c) * CCH;

        size_t base = (size_t)m * KRED + (size_t)k * CCH;
        #pragma unroll
        for (int q = 0; q < 4; q++) {
            int ch = (lane + q * 32) * 4;
            float4 a = *(const float4*)(p0 + ch);
            float4 c = *(const float4*)(p1 + ch);
            float e0 = w0 * a.x + w1 * c.x;
            float e1 = w0 * a.y + w1 * c.y;
            float e2 = w0 * a.z + w1 * c.z;
            float e3 = w0 * a.w + w1 * c.w;

            __nv_bfloat162 h01 = __floats2bfloat162_rn(e0, e1);
            __nv_bfloat162 h23 = __floats2bfloat162_rn(e2, e3);
            float2 f01 = __bfloat1622float2(h01);
            float2 f23 = __bfloat1622float2(h23);
            __nv_bfloat162 l01 = __floats2bfloat162_rn(e0 - f01.x, e1 - f01.y);
            __nv_bfloat162 l23 = __floats2bfloat162_rn(e2 - f23.x, e3 - f23.y);

            uint2 hv, lvv;
            hv.x = *reinterpret_cast<uint32_t*>(&h01);
            hv.y = *reinterpret_cast<uint32_t*>(&h23);
            lvv.x = *reinterpret_cast<uint32_t*>(&l01);
            lvv.y = *reinterpret_cast<uint32_t*>(&l23);
            *(uint2*)(Ah + base + ch) = hv;
            *(uint2*)(Al + base + ch) = lvv;
        }
    }
}

// ---------------------------------------------------------------------------
// GEMM: Y[m,n] = relu( (Ah@Wh + Ah@Wl + Al@Wh)[m,n] + bias[n] ) * maskrow[m]
// grid (4, 448), 128 threads (4 warps, warp tile 64x32), 2-stage, 4 CTAs/SM.
__global__ __launch_bounds__(128, 4)
void gemm_mma_kernel(const __nv_bfloat16* __restrict__ Ahg,
                     const __nv_bfloat16* __restrict__ Alg,
                     const __nv_bfloat16* __restrict__ Whg,
                     const __nv_bfloat16* __restrict__ Wlg,
                     const float* __restrict__ bias,
                     const float* __restrict__ maskrow,
                     float* __restrict__ Y) {
    extern __shared__ __nv_bfloat16 sm[];
    uint32_t sbase = smem_u32(sm);
    int tid = threadIdx.x, warp = tid >> 5, lane = tid & 31;
    int m0 = blockIdx.y * BMM, n0 = blockIdx.x * BNN;

    const uint32_t offAl = A_ELE * 2;
    const uint32_t offBh = 2 * A_ELE * 2;
    const uint32_t offBl = offBh + B_ELE * 2;

    int ar0 = tid >> 2, akc = (tid & 3) * 8;
    int br0 = tid >> 4, bnc = (tid & 15) * 8;
    const __nv_bfloat16* gAh = Ahg + (size_t)(m0 + ar0) * KRED + akc;
    const __nv_bfloat16* gAl = Alg + (size_t)(m0 + ar0) * KRED + akc;
    const __nv_bfloat16* gBh = Whg + (size_t)br0 * CCH + n0 + bnc;
    const __nv_bfloat16* gBl = Wlg + (size_t)br0 * CCH + n0 + bnc;
    const uint32_t A2 = 32u * KRED;
    uint32_t sA0 = (uint32_t)(ar0 * AST + akc) * 2;
    uint32_t sA1 = sA0 + 32u * AST * 2;
    uint32_t sB0 = (uint32_t)(br0 * BST + bnc) * 2;

    int wn = warp * 32;
    int lr = lane & 15, lc = lane >> 4;
    uint32_t a_off[4], b_off[2];
    #pragma unroll
    for (int mt = 0; mt < 4; mt++)
        a_off[mt] = (uint32_t)((mt * 16 + lr) * AST + lc * 8) * 2;
    #pragma unroll
    for (int nt = 0; nt < 2; nt++)
        b_off[nt] = (uint32_t)(lr * BST + wn + nt * 16 + lc * 8) * 2;

    float acc[4][4][4];
    #pragma unroll
    for (int i = 0; i < 4; i++)
        #pragma unroll
        for (int j = 0; j < 4; j++)
            #pragma unroll
            for (int q = 0; q < 4; q++) acc[i][j][q] = 0.f;

    auto load_stage = [&](int st, int k0) {
        uint32_t sb = sbase + (uint32_t)st * STG_BYTES;
        CP16(sb + sA0, gAh + k0);
        CP16(sb + sA1, gAh + A2 + k0);
        CP16(sb + offAl + sA0, gAl + k0);
        CP16(sb + offAl + sA1, gAl + A2 + k0);
        #pragma unroll
        for (int c = 0; c < 4; c++) {
            uint32_t so = sB0 + (uint32_t)c * 8 * BST * 2;
            size_t go = (size_t)(k0 + c * 8) * CCH;
            CP16(sb + offBh + so, gBh + go);
            CP16(sb + offBl + so, gBl + go);
        }
    };

    load_stage(0, 0);
    CP_COMMIT();
    CP_WAIT0();
    __syncthreads();

    for (int it = 0; it < KITERS; it++) {
        if (it + 1 < KITERS) {
            load_stage((it + 1) & 1, (it + 1) * BKK);
            CP_COMMIT();
        }

        uint32_t sb = sbase + (uint32_t)(it & 1) * STG_BYTES;

        uint32_t bh[2][2][4], bl[2][2][4];
        #pragma unroll
        for (int ks = 0; ks < 2; ks++)
            #pragma unroll
            for (int nt = 0; nt < 2; nt++) {
                ldsm_x4_t(bh[nt][ks], sb + offBh + b_off[nt] + ks * (16 * BST * 2));
                ldsm_x4_t(bl[nt][ks], sb + offBl + b_off[nt] + ks * (16 * BST * 2));
            }

        #pragma unroll
        for (int mt = 0; mt < 4; mt++) {
            #pragma unroll
            for (int ks = 0; ks < 2; ks++) {
                uint32_t ah[4], al[4];
                ldsm_x4(ah, sb + a_off[mt] + ks * 32);
                ldsm_x4(al, sb + offAl + a_off[mt] + ks * 32);
                #pragma unroll
                for (int n8 = 0; n8 < 4; n8++) {
                    const uint32_t* ph = &bh[n8 >> 1][ks][(n8 & 1) * 2];
                    const uint32_t* pl = &bl[n8 >> 1][ks][(n8 & 1) * 2];
                    mma16816(acc[mt][n8], ah, ph);
                    mma16816(acc[mt][n8], ah, pl);
                    mma16816(acc[mt][n8], al, ph);
                }
            }
        }

        if (it + 1 < KITERS) {
            CP_WAIT0();
            __syncthreads();
        }
    }

    #pragma unroll
    for (int mt = 0; mt < 4; mt++) {
        int r0g = m0 + mt * 16 + (lane >> 2);
        float mv0 = maskrow[r0g], mv1 = maskrow[r0g + 8];
        float* y0 = Y + (size_t)r0g * CCH;
        float* y1 = y0 + (size_t)8 * CCH;
        #pragma unroll
        for (int n8 = 0; n8 < 4; n8++) {
            int c0g = n0 + wn + n8 * 8 + (lane & 3) * 2;
            float b0 = bias[c0g], b1 = bias[c0g + 1];
            float2 v0, v1;
            v0.x = fmaxf(acc[mt][n8][0] + b0, 0.f) * mv0;
            v0.y = fmaxf(acc[mt][n8][1] + b1, 0.f) * mv0;
            v1.x = fmaxf(acc[mt][n8][2] + b0, 0.f) * mv1;
            v1.y = fmaxf(acc[mt][n8][3] + b1, 0.f) * mv1;
            *(float2*)(y0 + c0g) = v0;
            *(float2*)(y1 + c0g) = v1;
        }
    }
}

// ---------------------------------------------------------------------------
extern "C" void kernel_launch(void* const* d_in, const int* in_sizes, int n_in,
                              void* d_out, int out_size) {
    const float *feats[3] = {}, *masks[3] = {}, *offs[3] = {};
    const float *w[2] = {}, *bias[2] = {}, *ow[2] = {}, *ob[2] = {};
    int wi = 0, bi = 0, owi = 0, obi = 0;
    for (int i = 0; i < n_in; i++) {
        const float* p = (const float*)d_in[i];
        switch (in_sizes[i]) {
            case 8 * 512 * 2048: feats[0] = p; break;
            case 8 * 512 * 1024: feats[1] = p; break;
            case 8 * 512 * 512:  feats[2] = p; break;
            case 8 * 2048:       masks[0] = p; break;
            case 8 * 1024:       masks[1] = p; break;
            case 8 * 512:        masks[2] = p; break;
            case 8 * 3 * 2048:   offs[0] = p; break;
            case 8 * 3 * 1024:   offs[1] = p; break;
            case 8 * 3 * 512:    offs[2] = p; break;
            case 512 * 512 * 3:  if (wi < 2)  w[wi++] = p; break;
            case 512:            if (bi < 2)  bias[bi++] = p; break;
            case 3 * 512 * 3:    if (owi < 2) ow[owi++] = p; break;
            case 3:              if (obi < 2) ob[obi++] = p; break;
            default: break;
        }
    }

    float *xb, *yb, *offa, *mrow;
    __nv_bfloat16 *Ah, *Al, *Wh, *Wl;
    cudaGetSymbolAddress((void**)&xb, g_x);
    cudaGetSymbolAddress((void**)&yb, g_y);
    cudaGetSymbolAddress((void**)&offa, g_offa);
    cudaGetSymbolAddress((void**)&mrow, g_mrow);
    cudaGetSymbolAddress((void**)&Ah, g_Ah);
    cudaGetSymbolAddress((void**)&Al, g_Al);
    cudaGetSymbolAddress((void**)&Wh, g_Wh);
    cudaGetSymbolAddress((void**)&Wl, g_Wl);
    float* out = (float*)d_out;

    cudaFuncSetAttribute(gemm_mma_kernel,
                         cudaFuncAttributeMaxDynamicSharedMemorySize, GEMM_SMEM);
    cudaFuncSetAttribute(deform_kernel<true>,
                         cudaFuncAttributeMaxDynamicSharedMemorySize, DEF_SMEM);
    cudaFuncSetAttribute(deform_kernel<false>,
                         cudaFuncAttributeMaxDynamicSharedMemorySize, DEF_SMEM);

    // launches 0-2: prep (transposes, weight split, mask rows + bool out)
    tin_kernel<<<TIN_BLOCKS, 256>>>(feats[0], feats[1], feats[2], xb);
    wsplit_kernel<<<(2 * KRED * CCH + 255) / 256, 256>>>(w[0], w[1], Wh, Wl);
    maskrow_kernel<<<(ROWS_TOTAL + 255) / 256, 256>>>(masks[0], masks[1],
                                                      masks[2], mrow, out);

    // ---- layer 0 ----  (launches 3,4)
    deform_kernel<true><<<ROWS_TOTAL / DROWS, 256, DEF_SMEM>>>(
        xb, offs[0], offs[1], offs[2], ow[0], ob[0], offa, Ah, Al);
    gemm_mma_kernel<<<dim3(4, ROWS_TOTAL / BMM), 128, GEMM_SMEM>>>(
        Ah, Al, Wh, Wl, bias[0], mrow, yb);

    // ---- layer 1 ----  (launch 5 = deform<false> — captured by ncu)
    deform_kernel<false><<<ROWS_TOTAL / DROWS, 256, DEF_SMEM>>>(
        yb, offa, nullptr, nullptr, ow[1], ob[1], nullptr, Ah, Al);
    gemm_mma_kernel<<<dim3(4, ROWS_TOTAL / BMM), 128, GEMM_SMEM>>>(
        Ah, Al, Wh + (size_t)KRED * CCH, Wl + (size_t)KRED * CCH,
        bias[1], mrow, xb);

    // outputs
    tout_kernel<<<dim3(16, 112, 8), dim3(32, 8)>>>(xb, out);
}

// round 15
// speedup vs baseline: 1.3754x; 1.0523x over previous
#include <cuda_runtime.h>
#include <cuda_bf16.h>
#include <cstdint>

// ---------------------------------------------------------------------------
// FeatureAlign via mma.sync bf16 (HMMA) with fp32->bf16 hi/lo splitting.
//   Y = relu( A(fp32 gathered) @ W(fp32) + b ) * mask
//   A@W ~= Ah@Wh + Ah@Wl + Al@Wh   (fp32 accum)
// GEMM: BMM=64, 4 warps/CTA, 2-stage cp.async, 4 CTAs/SM.
//   Layer-1 GEMM writes transposed (B,C,T) output directly (no tout pass).
// deform: fused offset conv + gather + split; weights from global (no smem img).
// ---------------------------------------------------------------------------

#define BSZ 8
#define CCH 512
#define KT  3
#define ROWS_TOTAL 28672
#define LV0 16384
#define LV01 24576
#define KRED 1536

// GEMM tiling
#define BMM 64
#define BNN 128
#define BKK 32
#define AST 40
#define BST 136
#define A_ELE (BMM*AST)             // 2560
#define B_ELE (BKK*BST)             // 4352
#define STG_BYTES ((2*A_ELE + 2*B_ELE)*2)   // 27648 B per stage
#define NSTAGE 2
#define GEMM_SMEM (NSTAGE*STG_BYTES)        // 55296 B; 4 CTAs/SM
#define KITERS (KRED/BKK)           // 48
#define TPAD 68                     // fp32 out-tile row stride (16B aligned)

// deform kernel: 16 rows/block, 18 staged rows; weights from global
#define DROWS 16
#define DSTG  18
#define DEF_SMEM ((DSTG*CCH + DROWS*3) * 4)   // 37056 B

#define TIN_BLOCKS 14336                    // 112*16*8

// scratch (device globals; no runtime allocation allowed)
__device__ float g_x[ROWS_TOTAL * CCH];
__device__ float g_y[ROWS_TOTAL * CCH];
__device__ float g_offa[ROWS_TOTAL * 4];
__device__ float g_mrow[ROWS_TOTAL];
__device__ float g_ow2[2 * KT * KT * CCH];          // transposed offset weights
__device__ __nv_bfloat16 g_Ah[(size_t)ROWS_TOTAL * KRED];
__device__ __nv_bfloat16 g_Al[(size_t)ROWS_TOTAL * KRED];
__device__ __nv_bfloat16 g_Wh[2 * KRED * CCH];
__device__ __nv_bfloat16 g_Wl[2 * KRED * CCH];

// ---------------------------------------------------------------------------
__device__ __forceinline__ uint32_t smem_u32(const void* p) {
    return (uint32_t)__cvta_generic_to_shared(p);
}
#define CP16(sa, gp) \
    asm volatile("cp.async.cg.shared.global [%0], [%1], 16;" :: "r"(sa), "l"(gp))
#define CP_COMMIT() asm volatile("cp.async.commit_group;")
#define CP_WAIT0()  asm volatile("cp.async.wait_group 0;")

__device__ __forceinline__ void ldsm_x4(uint32_t* r, uint32_t a) {
    asm volatile("ldmatrix.sync.aligned.m8n8.x4.shared.b16 {%0,%1,%2,%3}, [%4];"
                 : "=r"(r[0]), "=r"(r[1]), "=r"(r[2]), "=r"(r[3]) : "r"(a));
}
__device__ __forceinline__ void ldsm_x4_t(uint32_t* r, uint32_t a) {
    asm volatile("ldmatrix.sync.aligned.m8n8.x4.trans.shared.b16 {%0,%1,%2,%3}, [%4];"
                 : "=r"(r[0]), "=r"(r[1]), "=r"(r[2]), "=r"(r[3]) : "r"(a));
}
__device__ __forceinline__ void mma16816(float* d, const uint32_t* a,
                                         const uint32_t* b) {
    asm volatile("mma.sync.aligned.m16n8k16.row.col.f32.bf16.bf16.f32 "
                 "{%0,%1,%2,%3}, {%4,%5,%6,%7}, {%8,%9}, {%0,%1,%2,%3};"
                 : "+f"(d[0]), "+f"(d[1]), "+f"(d[2]), "+f"(d[3])
                 : "r"(a[0]), "r"(a[1]), "r"(a[2]), "r"(a[3]), "r"(b[0]), "r"(b[1]));
}

// ---------------------------------------------------------------------------
// input transposes: feats (B,C,T) per level -> concatenated rows (m, C)
__global__ void tin_kernel(const float* __restrict__ f0,
                           const float* __restrict__ f1,
                           const float* __restrict__ f2,
                           float* __restrict__ xb) {
    __shared__ float tile[32][33];
    int bid = blockIdx.x, tid = threadIdx.x;
    int xv = bid % 112;
    int y  = (bid / 112) % 16;
    int b  = bid / (112 * 16);
    int lv, xs, T, lbase;
    if (xv < 64)      { lv = 0; xs = xv;      T = 2048; lbase = 0;    }
    else if (xv < 96) { lv = 1; xs = xv - 64; T = 1024; lbase = LV0;  }
    else              { lv = 2; xs = xv - 96; T = 512;  lbase = LV01; }
    const float* f = (lv == 0) ? f0 : (lv == 1 ? f1 : f2);
    int tx = tid & 31, ty = tid >> 5;
    int s0 = xs * 32, r0 = y * 32;
    const float* inb = f + (size_t)b * CCH * T;
    float* outb = xb + (size_t)(lbase + b * T) * CCH;
    #pragma unroll
    for (int i = ty; i < 32; i += 8)
        tile[i][tx] = inb[(size_t)(r0 + i) * T + s0 + tx];
    __syncthreads();
    #pragma unroll
    for (int i = ty; i < 32; i += 8)
        outb[(size_t)(s0 + i) * CCH + r0 + tx] = tile[tx][i];
}

// weight bf16 hi/lo split + transposed offset weights
__global__ void wsplit_kernel(const float* __restrict__ w0,
                              const float* __restrict__ w1,
                              const float* __restrict__ ow0,
                              const float* __restrict__ ow1,
                              __nv_bfloat16* __restrict__ Wh,
                              __nv_bfloat16* __restrict__ Wl,
                              float* __restrict__ ow2) {
    int idx = blockIdx.x * blockDim.x + threadIdx.x;
    if (idx < 2 * KRED * CCH) {
        int n = idx & 511;
        int k = (idx >> 9) % KRED;
        int l = idx / (KRED * CCH);
        int ktap = k >> 9, c = k & 511;
        const float* w = l ? w1 : w0;
        float val = w[(n * CCH + c) * KT + ktap];
        __nv_bfloat16 hi = __float2bfloat16(val);
        Wh[idx] = hi;
        Wl[idx] = __float2bfloat16(val - __bfloat162float(hi));
    } else {
        int i = idx - 2 * KRED * CCH;        // 2 * 4608 total
        if (i < 2 * KT * KT * CCH) {
            int l = i / (KT * KT * CCH);
            int r = i % (KT * KT * CCH);     // source index: (kk*512 + c)*3 + j
            int j = r % 3;
            int q = r / 3;
            int kk = q >> 9, c = q & 511;
            const float* ow = l ? ow1 : ow0;
            ow2[l * (KT * KT * CCH) + (kk * 3 + j) * CCH + c] = ow[r];
        }
    }
}

// mask rows + bool outputs
__global__ void maskrow_kernel(const float* __restrict__ m0,
                               const float* __restrict__ m1,
                               const float* __restrict__ m2,
                               float* __restrict__ mrow,
                               float* __restrict__ out) {
    int m = blockIdx.x * 256 + threadIdx.x;
    if (m >= ROWS_TOTAL) return;
    float v = (m < LV0) ? m0[m] : (m < LV01 ? m1[m - LV0] : m2[m - LV01]);
    mrow[m] = v;
    out[(size_t)BSZ * CCH * 3584 + m] = (v != 0.f) ? 1.0f : 0.0f;
}

// ---------------------------------------------------------------------------
// FUSED deform kernel: offset conv + im2col gather + bf16 split.
// Block = 16 consecutive rows (one level), 256 threads, 4 CTAs/SM.
// Offset-conv weights read straight from global (broadcast L1 hits).
template <bool EXT>
__global__ __launch_bounds__(256, 4)
void deform_kernel(const float* __restrict__ X,
                   const float* __restrict__ o0,
                   const float* __restrict__ o1,
                   const float* __restrict__ o2,
                   const float* __restrict__ ow2,
                   const float* __restrict__ ob,
                   float* __restrict__ off_out,
                   __nv_bfloat16* __restrict__ Ah,
                   __nv_bfloat16* __restrict__ Al) {
    extern __shared__ float sdyn[];
    float* xs = sdyn;                                   // 18*512
    float* off_sh = sdyn + DSTG * CCH;                  // 48
    int tid = threadIdx.x;

    int rl0g = blockIdx.x * DROWS;
    int lv = (rl0g < LV0) ? 0 : (rl0g < LV01 ? 1 : 2);
    int lbase = (lv == 0) ? 0 : (lv == 1 ? LV0 : LV01);
    int logT = 11 - lv;
    int T = 1 << logT;
    int rl0 = rl0g - lbase;
    const float* Xl = X + (size_t)lbase * CCH;

    int t0 = rl0 & (T - 1);
    // stage rows rl0-1 .. rl0+16 (t0-1 .. t0+16), zero outside [0,T)
    for (int fi = tid; fi < DSTG * 128; fi += 256) {
        int j = fi >> 7;
        int cf = (fi & 127) * 4;
        int t = t0 + j - 1;
        float4 v = make_float4(0.f, 0.f, 0.f, 0.f);
        if (t >= 0 && t < T)
            v = *(const float4*)(Xl + (size_t)(rl0 - 1 + j) * CCH + cf);
        *(float4*)(xs + j * CCH + cf) = v;
    }
    __syncthreads();

    int warp = tid >> 5, lane = tid & 31;
    int r0l = warp * 2;                 // 2 rows per warp

    // ---- phase 1: offset conv ----
    {
        float acc[2][3];
        #pragma unroll
        for (int i = 0; i < 2; i++)
            #pragma unroll
            for (int kk = 0; kk < 3; kk++) acc[i][kk] = 0.f;

        #pragma unroll
        for (int q = 0; q < 4; q++) {
            int c = lane * 4 + q * 128;
            float4 xv[4];
            #pragma unroll
            for (int u = 0; u < 4; u++)
                xv[u] = *(const float4*)(xs + (r0l + u) * CCH + c);
            #pragma unroll
            for (int kk = 0; kk < 3; kk++) {
                float4 wv[3];
                #pragma unroll
                for (int j = 0; j < 3; j++)
                    wv[j] = *(const float4*)(ow2 + (kk * 3 + j) * CCH + c);
                #pragma unroll
                for (int i = 0; i < 2; i++) {
                    float s = 0.f;
                    #pragma unroll
                    for (int j = 0; j < 3; j++) {
                        float4 wf = wv[j];
                        float4 xf = xv[i + j];
                        s += wf.x * xf.x + wf.y * xf.y + wf.z * xf.z + wf.w * xf.w;
                    }
                    acc[i][kk] += s;
                }
            }
        }

        #pragma unroll
        for (int i = 0; i < 2; i++)
            #pragma unroll
            for (int kk = 0; kk < 3; kk++)
                #pragma unroll
                for (int s = 16; s; s >>= 1)
                    acc[i][kk] += __shfl_down_sync(0xffffffffu, acc[i][kk], s);

        if (lane == 0) {
            #pragma unroll
            for (int i = 0; i < 2; i++) {
                int rl = rl0 + r0l + i;
                int b = rl >> logT, t = rl & (T - 1);
                int m = rl0g + r0l + i;
                float i0, i1, i2;
                if (EXT) {
                    const float* oin = (lv == 0) ? o0 : (lv == 1 ? o1 : o2);
                    i0 = oin[((size_t)b * KT + 0) * T + t];
                    i1 = oin[((size_t)b * KT + 1) * T + t];
                    i2 = oin[((size_t)b * KT + 2) * T + t];
                } else {
                    i0 = o0[(size_t)m * 4 + 0];
                    i1 = o0[(size_t)m * 4 + 1];
                    i2 = o0[(size_t)m * 4 + 2];
                }
                float v0 = acc[i][0] + ob[0] + i0;
                float v1 = acc[i][1] + ob[1] + i1;
                float v2 = acc[i][2] + ob[2] + i2;
                off_sh[(r0l + i) * 3 + 0] = v0;
                off_sh[(r0l + i) * 3 + 1] = v1;
                off_sh[(r0l + i) * 3 + 2] = v2;
                if (EXT) {               // layer 0's offsets feed layer 1
                    off_out[(size_t)m * 4 + 0] = v0;
                    off_out[(size_t)m * 4 + 1] = v1;
                    off_out[(size_t)m * 4 + 2] = v2;
                }
            }
        }
    }
    __syncthreads();

    // ---- phase 2: gather + lerp + bf16 hi/lo split; 6 (row,tap) pairs/warp
    #pragma unroll 2
    for (int pi = 0; pi < 6; pi++) {
        int pair = warp * 6 + pi;           // 0..47
        int r = pair / 3, k = pair % 3;
        int rl = rl0 + r;
        int b = rl >> logT, t = rl & (T - 1);
        int m = rl0g + r;

        float off = off_sh[r * 3 + k];
        float pos = (float)(t + k - 1) + off;
        float p0f = floorf(pos);
        float f = pos - p0f;
        int i0 = (int)p0f, i1 = i0 + 1;
        float w0 = (i0 >= 0 && i0 < T) ? (1.0f - f) : 0.0f;
        float w1 = (i1 >= 0 && i1 < T) ? f : 0.0f;
        int i0c = min(max(i0, 0), T - 1);
        int i1c = min(max(i1, 0), T - 1);

        int j0 = i0c - t0 + 1, j1 = i1c - t0 + 1;
        const float* p0 = (j0 >= 0 && j0 < DSTG)
            ? xs + (size_t)j0 * CCH
            : Xl + ((size_t)(b << logT) + i0c) * CCH;
        const float* p1 = (j1 >= 0 && j1 < DSTG)
            ? xs + (size_t)j1 * CCH
            : Xl + ((size_t)(b << logT) + i1c) * CCH;

        size_t base = (size_t)m * KRED + (size_t)k * CCH;
        #pragma unroll
        for (int q = 0; q < 4; q++) {
            int ch = (lane + q * 32) * 4;
            float4 a = *(const float4*)(p0 + ch);
            float4 c = *(const float4*)(p1 + ch);
            float e0 = w0 * a.x + w1 * c.x;
            float e1 = w0 * a.y + w1 * c.y;
            float e2 = w0 * a.z + w1 * c.z;
            float e3 = w0 * a.w + w1 * c.w;

            __nv_bfloat162 h01 = __floats2bfloat162_rn(e0, e1);
            __nv_bfloat162 h23 = __floats2bfloat162_rn(e2, e3);
            float2 f01 = __bfloat1622float2(h01);
            float2 f23 = __bfloat1622float2(h23);
            __nv_bfloat162 l01 = __floats2bfloat162_rn(e0 - f01.x, e1 - f01.y);
            __nv_bfloat162 l23 = __floats2bfloat162_rn(e2 - f23.x, e3 - f23.y);

            uint2 hv, lvv;
            hv.x = *reinterpret_cast<uint32_t*>(&h01);
            hv.y = *reinterpret_cast<uint32_t*>(&h23);
            lvv.x = *reinterpret_cast<uint32_t*>(&l01);
            lvv.y = *reinterpret_cast<uint32_t*>(&l23);
            *(uint2*)(Ah + base + ch) = hv;
            *(uint2*)(Al + base + ch) = lvv;
        }
    }
}

// ---------------------------------------------------------------------------
// GEMM: Y[m,n] = relu( (Ah@Wh + Ah@Wl + Al@Wh)[m,n] + bias[n] ) * maskrow[m]
// grid (4, 448), 128 threads (4 warps, warp tile 64x32), 2-stage, 4 CTAs/SM.
// TRANS_OUT: write (B,C,T) layout directly into the final output buffer.
template <bool TRANS_OUT>
__global__ __launch_bounds__(128, 4)
void gemm_mma_kernel(const __nv_bfloat16* __restrict__ Ahg,
                     const __nv_bfloat16* __restrict__ Alg,
                     const __nv_bfloat16* __restrict__ Whg,
                     const __nv_bfloat16* __restrict__ Wlg,
                     const float* __restrict__ bias,
                     const float* __restrict__ maskrow,
                     float* __restrict__ Y) {
    extern __shared__ __nv_bfloat16 sm[];
    uint32_t sbase = smem_u32(sm);
    int tid = threadIdx.x, warp = tid >> 5, lane = tid & 31;
    int m0 = blockIdx.y * BMM, n0 = blockIdx.x * BNN;

    const uint32_t offAl = A_ELE * 2;
    const uint32_t offBh = 2 * A_ELE * 2;
    const uint32_t offBl = offBh + B_ELE * 2;

    int ar0 = tid >> 2, akc = (tid & 3) * 8;
    int br0 = tid >> 4, bnc = (tid & 15) * 8;
    const __nv_bfloat16* gAh = Ahg + (size_t)(m0 + ar0) * KRED + akc;
    const __nv_bfloat16* gAl = Alg + (size_t)(m0 + ar0) * KRED + akc;
    const __nv_bfloat16* gBh = Whg + (size_t)br0 * CCH + n0 + bnc;
    const __nv_bfloat16* gBl = Wlg + (size_t)br0 * CCH + n0 + bnc;
    const uint32_t A2 = 32u * KRED;
    uint32_t sA0 = (uint32_t)(ar0 * AST + akc) * 2;
    uint32_t sA1 = sA0 + 32u * AST * 2;
    uint32_t sB0 = (uint32_t)(br0 * BST + bnc) * 2;

    int wn = warp * 32;
    int lr = lane & 15, lc = lane >> 4;
    uint32_t a_off[4], b_off[2];
    #pragma unroll
    for (int mt = 0; mt < 4; mt++)
        a_off[mt] = (uint32_t)((mt * 16 + lr) * AST + lc * 8) * 2;
    #pragma unroll
    for (int nt = 0; nt < 2; nt++)
        b_off[nt] = (uint32_t)(lr * BST + wn + nt * 16 + lc * 8) * 2;

    float acc[4][4][4];
    #pragma unroll
    for (int i = 0; i < 4; i++)
        #pragma unroll
        for (int j = 0; j < 4; j++)
            #pragma unroll
            for (int q = 0; q < 4; q++) acc[i][j][q] = 0.f;

    auto load_stage = [&](int st, int k0) {
        uint32_t sb = sbase + (uint32_t)st * STG_BYTES;
        CP16(sb + sA0, gAh + k0);
        CP16(sb + sA1, gAh + A2 + k0);
        CP16(sb + offAl + sA0, gAl + k0);
        CP16(sb + offAl + sA1, gAl + A2 + k0);
        #pragma unroll
        for (int c = 0; c < 4; c++) {
            uint32_t so = sB0 + (uint32_t)c * 8 * BST * 2;
            size_t go = (size_t)(k0 + c * 8) * CCH;
            CP16(sb + offBh + so, gBh + go);
            CP16(sb + offBl + so, gBl + go);
        }
    };

    load_stage(0, 0);
    CP_COMMIT();
    CP_WAIT0();
    __syncthreads();

    for (int it = 0; it < KITERS; it++) {
        if (it + 1 < KITERS) {
            load_stage((it + 1) & 1, (it + 1) * BKK);
            CP_COMMIT();
        }

        uint32_t sb = sbase + (uint32_t)(it & 1) * STG_BYTES;

        uint32_t bh[2][2][4], bl[2][2][4];
        #pragma unroll
        for (int ks = 0; ks < 2; ks++)
            #pragma unroll
            for (int nt = 0; nt < 2; nt++) {
                ldsm_x4_t(bh[nt][ks], sb + offBh + b_off[nt] + ks * (16 * BST * 2));
                ldsm_x4_t(bl[nt][ks], sb + offBl + b_off[nt] + ks * (16 * BST * 2));
            }

        #pragma unroll
        for (int mt = 0; mt < 4; mt++) {
            #pragma unroll
            for (int ks = 0; ks < 2; ks++) {
                uint32_t ah[4], al[4];
                ldsm_x4(ah, sb + a_off[mt] + ks * 32);
                ldsm_x4(al, sb + offAl + a_off[mt] + ks * 32);
                #pragma unroll
                for (int n8 = 0; n8 < 4; n8++) {
                    const uint32_t* ph = &bh[n8 >> 1][ks][(n8 & 1) * 2];
                    const uint32_t* pl = &bl[n8 >> 1][ks][(n8 & 1) * 2];
                    mma16816(acc[mt][n8], ah, ph);
                    mma16816(acc[mt][n8], ah, pl);
                    mma16816(acc[mt][n8], al, ph);
                }
            }
        }

        if (it + 1 < KITERS) {
            CP_WAIT0();
            __syncthreads();
        }
    }

    if (!TRANS_OUT) {
        #pragma unroll
        for (int mt = 0; mt < 4; mt++) {
            int r0g = m0 + mt * 16 + (lane >> 2);
            float mv0 = maskrow[r0g], mv1 = maskrow[r0g + 8];
            float* y0 = Y + (size_t)r0g * CCH;
            float* y1 = y0 + (size_t)8 * CCH;
            #pragma unroll
            for (int n8 = 0; n8 < 4; n8++) {
                int c0g = n0 + wn + n8 * 8 + (lane & 3) * 2;
                float b0 = bias[c0g], b1 = bias[c0g + 1];
                float2 v0, v1;
                v0.x = fmaxf(acc[mt][n8][0] + b0, 0.f) * mv0;
                v0.y = fmaxf(acc[mt][n8][1] + b1, 0.f) * mv0;
                v1.x = fmaxf(acc[mt][n8][2] + b0, 0.f) * mv1;
                v1.y = fmaxf(acc[mt][n8][3] + b1, 0.f) * mv1;
                *(float2*)(y0 + c0g) = v0;
                *(float2*)(y1 + c0g) = v1;
            }
        }
    } else {
        // stage tile (m-local 0..63, c-local 0..127) as smT[c][m], then write
        // out[(b*CCH + c_global)*T + t0 + m-local]  (64 | T so batch uniform)
        float* smT = (float*)sm;
        __syncthreads();                    // compute done; reuse pipeline smem
        #pragma unroll
        for (int mt = 0; mt < 4; mt++) {
            int ml0 = mt * 16 + (lane >> 2);
            int r0g = m0 + ml0;
            float mv0 = maskrow[r0g], mv1 = maskrow[r0g + 8];
            #pragma unroll
            for (int n8 = 0; n8 < 4; n8++) {
                int cl = wn + n8 * 8 + (lane & 3) * 2;
                float b0 = bias[n0 + cl], b1 = bias[n0 + cl + 1];
                smT[cl * TPAD + ml0]           = fmaxf(acc[mt][n8][0] + b0, 0.f) * mv0;
                smT[(cl + 1) * TPAD + ml0]     = fmaxf(acc[mt][n8][1] + b1, 0.f) * mv0;
                smT[cl * TPAD + ml0 + 8]       = fmaxf(acc[mt][n8][2] + b0, 0.f) * mv1;
                smT[(cl + 1) * TPAD + ml0 + 8] = fmaxf(acc[mt][n8][3] + b1, 0.f) * mv1;
            }
        }
        __syncthreads();
        // level geometry for the output slot
        int lv = (m0 < LV0) ? 0 : (m0 < LV01 ? 1 : 2);
        int lbase = (lv == 0) ? 0 : (lv == 1 ? LV0 : LV01);
        int logT = 11 - lv;
        int T = 1 << logT;
        int rl0 = m0 - lbase;
        int b = rl0 >> logT, t0 = rl0 & (T - 1);
        size_t obase = (lv == 0) ? 0 : (lv == 1 ? (size_t)BSZ * CCH * 2048
                                               : (size_t)BSZ * CCH * 3072);
        float* outb = Y + obase + ((size_t)b * CCH) * T + t0;
        // 128 c-rows x 64 m: each thread copies float4s
        for (int idx = tid; idx < 128 * 16; idx += 128) {
            int cl = idx >> 4, seg = (idx & 15) * 4;
            float4 v = *(float4*)(smT + cl * TPAD + seg);
            *(float4*)(outb + (size_t)(n0 + cl) * T + seg) = v;
        }
    }
}

// ---------------------------------------------------------------------------
extern "C" void kernel_launch(void* const* d_in, const int* in_sizes, int n_in,
                              void* d_out, int out_size) {
    const float *feats[3] = {}, *masks[3] = {}, *offs[3] = {};
    const float *w[2] = {}, *bias[2] = {}, *ow[2] = {}, *ob[2] = {};
    int wi = 0, bi = 0, owi = 0, obi = 0;
    for (int i = 0; i < n_in; i++) {
        const float* p = (const float*)d_in[i];
        switch (in_sizes[i]) {
            case 8 * 512 * 2048: feats[0] = p; break;
            case 8 * 512 * 1024: feats[1] = p; break;
            case 8 * 512 * 512:  feats[2] = p; break;
            case 8 * 2048:       masks[0] = p; break;
            case 8 * 1024:       masks[1] = p; break;
            case 8 * 512:        masks[2] = p; break;
            case 8 * 3 * 2048:   offs[0] = p; break;
            case 8 * 3 * 1024:   offs[1] = p; break;
            case 8 * 3 * 512:    offs[2] = p; break;
            case 512 * 512 * 3:  if (wi < 2)  w[wi++] = p; break;
            case 512:            if (bi < 2)  bias[bi++] = p; break;
            case 3 * 512 * 3:    if (owi < 2) ow[owi++] = p; break;
            case 3:              if (obi < 2) ob[obi++] = p; break;
            default: break;
        }
    }

    float *xb, *yb, *offa, *mrow, *ow2;
    __nv_bfloat16 *Ah, *Al, *Wh, *Wl;
    cudaGetSymbolAddress((void**)&xb, g_x);
    cudaGetSymbolAddress((void**)&yb, g_y);
    cudaGetSymbolAddress((void**)&offa, g_offa);
    cudaGetSymbolAddress((void**)&mrow, g_mrow);
    cudaGetSymbolAddress((void**)&ow2, g_ow2);
    cudaGetSymbolAddress((void**)&Ah, g_Ah);
    cudaGetSymbolAddress((void**)&Al, g_Al);
    cudaGetSymbolAddress((void**)&Wh, g_Wh);
    cudaGetSymbolAddress((void**)&Wl, g_Wl);
    float* out = (float*)d_out;

    cudaFuncSetAttribute(gemm_mma_kernel<false>,
                         cudaFuncAttributeMaxDynamicSharedMemorySize, GEMM_SMEM);
    cudaFuncSetAttribute(gemm_mma_kernel<true>,
                         cudaFuncAttributeMaxDynamicSharedMemorySize, GEMM_SMEM);
    cudaFuncSetAttribute(deform_kernel<true>,
                         cudaFuncAttributeMaxDynamicSharedMemorySize, DEF_SMEM);
    cudaFuncSetAttribute(deform_kernel<false>,
                         cudaFuncAttributeMaxDynamicSharedMemorySize, DEF_SMEM);

    // launches 0-2: prep
    tin_kernel<<<TIN_BLOCKS, 256>>>(feats[0], feats[1], feats[2], xb);
    {
        int total = 2 * KRED * CCH + 2 * KT * KT * CCH;
        wsplit_kernel<<<(total + 255) / 256, 256>>>(w[0], w[1], ow[0], ow[1],
                                                    Wh, Wl, ow2);
    }
    maskrow_kernel<<<(ROWS_TOTAL + 255) / 256, 256>>>(masks[0], masks[1],
                                                      masks[2], mrow, out);

    // ---- layer 0 ----  (launches 3,4)
    deform_kernel<true><<<ROWS_TOTAL / DROWS, 256, DEF_SMEM>>>(
        xb, offs[0], offs[1], offs[2], ow2, ob[0], offa, Ah, Al);
    gemm_mma_kernel<false><<<dim3(4, ROWS_TOTAL / BMM), 128, GEMM_SMEM>>>(
        Ah, Al, Wh, Wl, bias[0], mrow, yb);

    // ---- layer 1 ----  (launch 5 = deform<false> — captured by ncu)
    deform_kernel<false><<<ROWS_TOTAL / DROWS, 256, DEF_SMEM>>>(
        yb, offa, nullptr, nullptr, ow2 + KT * KT * CCH, ob[1], nullptr, Ah, Al);
    gemm_mma_kernel<true><<<dim3(4, ROWS_TOTAL / BMM), 128, GEMM_SMEM>>>(
        Ah, Al, Wh + (size_t)KRED * CCH, Wl + (size_t)KRED * CCH,
        bias[1], mrow, out);
}

// round 16
// speedup vs baseline: 1.3805x; 1.0037x over previous
#include <cuda_runtime.h>
#include <cuda_bf16.h>
#include <cstdint>

// ---------------------------------------------------------------------------
// FeatureAlign via mma.sync bf16 (HMMA) with fp32->bf16 hi/lo splitting.
//   Y = relu( A(fp32 gathered) @ W(fp32) + b ) * mask
//   A@W ~= Ah@Wh + Ah@Wl + Al@Wh   (fp32 accum)
// GEMM: BMM=64, 4 warps/CTA, 2-stage cp.async, 4 CTAs/SM; layer-1 GEMM
//   writes transposed (B,C,T) output directly.
// deform: fused offset conv + gather + split; 8-row/128-thread blocks, 8 CTAs/SM.
// ---------------------------------------------------------------------------

#define BSZ 8
#define CCH 512
#define KT  3
#define ROWS_TOTAL 28672
#define LV0 16384
#define LV01 24576
#define KRED 1536

// GEMM tiling
#define BMM 64
#define BNN 128
#define BKK 32
#define AST 40
#define BST 136
#define A_ELE (BMM*AST)             // 2560
#define B_ELE (BKK*BST)             // 4352
#define STG_BYTES ((2*A_ELE + 2*B_ELE)*2)   // 27648 B per stage
#define NSTAGE 2
#define GEMM_SMEM (NSTAGE*STG_BYTES)        // 55296 B; 4 CTAs/SM
#define KITERS (KRED/BKK)           // 48
#define TPAD 68                     // fp32 out-tile row stride (16B aligned)

// deform kernel: 8 rows/block, 10 staged rows, 128 threads, 8 CTAs/SM
#define DROWS 8
#define DSTG  10
#define DEF_SMEM ((DSTG*CCH + DROWS*3) * 4)   // 20576 B

#define TIN_BLOCKS 14336                    // 112*16*8
#define WSPLIT_ELEMS (2*KRED*CCH)
#define OW2_ELEMS (2*KT*KT*CCH)
#define WSPLIT_TOTAL (WSPLIT_ELEMS + OW2_ELEMS + ROWS_TOTAL)

// scratch (device globals; no runtime allocation allowed)
__device__ float g_x[ROWS_TOTAL * CCH];
__device__ float g_y[ROWS_TOTAL * CCH];
__device__ float g_offa[ROWS_TOTAL * 4];
__device__ float g_mrow[ROWS_TOTAL];
__device__ float g_ow2[OW2_ELEMS];                  // transposed offset weights
__device__ __nv_bfloat16 g_Ah[(size_t)ROWS_TOTAL * KRED];
__device__ __nv_bfloat16 g_Al[(size_t)ROWS_TOTAL * KRED];
__device__ __nv_bfloat16 g_Wh[2 * KRED * CCH];
__device__ __nv_bfloat16 g_Wl[2 * KRED * CCH];

// ---------------------------------------------------------------------------
__device__ __forceinline__ uint32_t smem_u32(const void* p) {
    return (uint32_t)__cvta_generic_to_shared(p);
}
#define CP16(sa, gp) \
    asm volatile("cp.async.cg.shared.global [%0], [%1], 16;" :: "r"(sa), "l"(gp))
#define CP_COMMIT() asm volatile("cp.async.commit_group;")
#define CP_WAIT0()  asm volatile("cp.async.wait_group 0;")

__device__ __forceinline__ void ldsm_x4(uint32_t* r, uint32_t a) {
    asm volatile("ldmatrix.sync.aligned.m8n8.x4.shared.b16 {%0,%1,%2,%3}, [%4];"
                 : "=r"(r[0]), "=r"(r[1]), "=r"(r[2]), "=r"(r[3]) : "r"(a));
}
__device__ __forceinline__ void ldsm_x4_t(uint32_t* r, uint32_t a) {
    asm volatile("ldmatrix.sync.aligned.m8n8.x4.trans.shared.b16 {%0,%1,%2,%3}, [%4];"
                 : "=r"(r[0]), "=r"(r[1]), "=r"(r[2]), "=r"(r[3]) : "r"(a));
}
__device__ __forceinline__ void mma16816(float* d, const uint32_t* a,
                                         const uint32_t* b) {
    asm volatile("mma.sync.aligned.m16n8k16.row.col.f32.bf16.bf16.f32 "
                 "{%0,%1,%2,%3}, {%4,%5,%6,%7}, {%8,%9}, {%0,%1,%2,%3};"
                 : "+f"(d[0]), "+f"(d[1]), "+f"(d[2]), "+f"(d[3])
                 : "r"(a[0]), "r"(a[1]), "r"(a[2]), "r"(a[3]), "r"(b[0]), "r"(b[1]));
}

// ---------------------------------------------------------------------------
// input transposes: feats (B,C,T) per level -> concatenated rows (m, C)
__global__ void tin_kernel(const float* __restrict__ f0,
                           const float* __restrict__ f1,
                           const float* __restrict__ f2,
                           float* __restrict__ xb) {
    __shared__ float tile[32][33];
    int bid = blockIdx.x, tid = threadIdx.x;
    int xv = bid % 112;
    int y  = (bid / 112) % 16;
    int b  = bid / (112 * 16);
    int lv, xs, T, lbase;
    if (xv < 64)      { lv = 0; xs = xv;      T = 2048; lbase = 0;    }
    else if (xv < 96) { lv = 1; xs = xv - 64; T = 1024; lbase = LV0;  }
    else              { lv = 2; xs = xv - 96; T = 512;  lbase = LV01; }
    const float* f = (lv == 0) ? f0 : (lv == 1 ? f1 : f2);
    int tx = tid & 31, ty = tid >> 5;
    int s0 = xs * 32, r0 = y * 32;
    const float* inb = f + (size_t)b * CCH * T;
    float* outb = xb + (size_t)(lbase + b * T) * CCH;
    #pragma unroll
    for (int i = ty; i < 32; i += 8)
        tile[i][tx] = inb[(size_t)(r0 + i) * T + s0 + tx];
    __syncthreads();
    #pragma unroll
    for (int i = ty; i < 32; i += 8)
        outb[(size_t)(s0 + i) * CCH + r0 + tx] = tile[tx][i];
}

// weight bf16 hi/lo split + transposed offset weights + mask rows/bool out
__global__ void wsplit_kernel(const float* __restrict__ w0,
                              const float* __restrict__ w1,
                              const float* __restrict__ ow0,
                              const float* __restrict__ ow1,
                              const float* __restrict__ m0,
                              const float* __restrict__ m1,
                              const float* __restrict__ m2,
                              __nv_bfloat16* __restrict__ Wh,
                              __nv_bfloat16* __restrict__ Wl,
                              float* __restrict__ ow2,
                              float* __restrict__ mrow,
                              float* __restrict__ out) {
    int idx = blockIdx.x * blockDim.x + threadIdx.x;
    if (idx < WSPLIT_ELEMS) {
        int n = idx & 511;
        int k = (idx >> 9) % KRED;
        int l = idx / (KRED * CCH);
        int ktap = k >> 9, c = k & 511;
        const float* w = l ? w1 : w0;
        float val = w[(n * CCH + c) * KT + ktap];
        __nv_bfloat16 hi = __float2bfloat16(val);
        Wh[idx] = hi;
        Wl[idx] = __float2bfloat16(val - __bfloat162float(hi));
    } else if (idx < WSPLIT_ELEMS + OW2_ELEMS) {
        int i = idx - WSPLIT_ELEMS;
        int l = i / (KT * KT * CCH);
        int r = i % (KT * KT * CCH);     // source: (kk*512 + c)*3 + j
        int j = r % 3;
        int q = r / 3;
        int kk = q >> 9, c = q & 511;
        const float* ow = l ? ow1 : ow0;
        ow2[l * (KT * KT * CCH) + (kk * 3 + j) * CCH + c] = ow[r];
    } else if (idx < WSPLIT_TOTAL) {
        int m = idx - WSPLIT_ELEMS - OW2_ELEMS;
        float v = (m < LV0) ? m0[m] : (m < LV01 ? m1[m - LV0] : m2[m - LV01]);
        mrow[m] = v;
        out[(size_t)BSZ * CCH * 3584 + m] = (v != 0.f) ? 1.0f : 0.0f;
    }
}

// ---------------------------------------------------------------------------
// FUSED deform kernel: offset conv + im2col gather + bf16 split.
// Block = 8 rows (one level), 128 threads, 8 CTAs/SM.
template <bool EXT>
__global__ __launch_bounds__(128, 8)
void deform_kernel(const float* __restrict__ X,
                   const float* __restrict__ o0,
                   const float* __restrict__ o1,
                   const float* __restrict__ o2,
                   const float* __restrict__ ow2,
                   const float* __restrict__ ob,
                   float* __restrict__ off_out,
                   __nv_bfloat16* __restrict__ Ah,
                   __nv_bfloat16* __restrict__ Al) {
    extern __shared__ float sdyn[];
    float* xs = sdyn;                                   // 10*512
    float* off_sh = sdyn + DSTG * CCH;                  // 24
    int tid = threadIdx.x;

    int rl0g = blockIdx.x * DROWS;
    int lv = (rl0g < LV0) ? 0 : (rl0g < LV01 ? 1 : 2);
    int lbase = (lv == 0) ? 0 : (lv == 1 ? LV0 : LV01);
    int logT = 11 - lv;
    int T = 1 << logT;
    int rl0 = rl0g - lbase;
    const float* Xl = X + (size_t)lbase * CCH;

    int t0 = rl0 & (T - 1);
    // stage rows rl0-1 .. rl0+8 (t0-1 .. t0+8), zero outside [0,T)
    for (int fi = tid; fi < DSTG * 128; fi += 128) {
        int j = fi >> 7;
        int cf = (fi & 127) * 4;
        int t = t0 + j - 1;
        float4 v = make_float4(0.f, 0.f, 0.f, 0.f);
        if (t >= 0 && t < T)
            v = *(const float4*)(Xl + (size_t)(rl0 - 1 + j) * CCH + cf);
        *(float4*)(xs + j * CCH + cf) = v;
    }
    __syncthreads();

    int warp = tid >> 5, lane = tid & 31;
    int r0l = warp * 2;                 // 2 rows per warp (4 warps, 8 rows)

    // ---- phase 1: offset conv ----
    {
        float acc[2][3];
        #pragma unroll
        for (int i = 0; i < 2; i++)
            #pragma unroll
            for (int kk = 0; kk < 3; kk++) acc[i][kk] = 0.f;

        #pragma unroll
        for (int q = 0; q < 4; q++) {
            int c = lane * 4 + q * 128;
            float4 xv[4];
            #pragma unroll
            for (int u = 0; u < 4; u++)
                xv[u] = *(const float4*)(xs + (r0l + u) * CCH + c);
            #pragma unroll
            for (int kk = 0; kk < 3; kk++) {
                float4 wv[3];
                #pragma unroll
                for (int j = 0; j < 3; j++)
                    wv[j] = *(const float4*)(ow2 + (kk * 3 + j) * CCH + c);
                #pragma unroll
                for (int i = 0; i < 2; i++) {
                    float s = 0.f;
                    #pragma unroll
                    for (int j = 0; j < 3; j++) {
                        float4 wf = wv[j];
                        float4 xf = xv[i + j];
                        s += wf.x * xf.x + wf.y * xf.y + wf.z * xf.z + wf.w * xf.w;
                    }
                    acc[i][kk] += s;
                }
            }
        }

        #pragma unroll
        for (int i = 0; i < 2; i++)
            #pragma unroll
            for (int kk = 0; kk < 3; kk++)
                #pragma unroll
                for (int s = 16; s; s >>= 1)
                    acc[i][kk] += __shfl_down_sync(0xffffffffu, acc[i][kk], s);

        if (lane == 0) {
            #pragma unroll
            for (int i = 0; i < 2; i++) {
                int rl = rl0 + r0l + i;
                int b = rl >> logT, t = rl & (T - 1);
                int m = rl0g + r0l + i;
                float i0, i1, i2;
                if (EXT) {
                    const float* oin = (lv == 0) ? o0 : (lv == 1 ? o1 : o2);
                    i0 = oin[((size_t)b * KT + 0) * T + t];
                    i1 = oin[((size_t)b * KT + 1) * T + t];
                    i2 = oin[((size_t)b * KT + 2) * T + t];
                } else {
                    i0 = o0[(size_t)m * 4 + 0];
                    i1 = o0[(size_t)m * 4 + 1];
                    i2 = o0[(size_t)m * 4 + 2];
                }
                float v0 = acc[i][0] + ob[0] + i0;
                float v1 = acc[i][1] + ob[1] + i1;
                float v2 = acc[i][2] + ob[2] + i2;
                off_sh[(r0l + i) * 3 + 0] = v0;
                off_sh[(r0l + i) * 3 + 1] = v1;
                off_sh[(r0l + i) * 3 + 2] = v2;
                if (EXT) {               // layer 0's offsets feed layer 1
                    off_out[(size_t)m * 4 + 0] = v0;
                    off_out[(size_t)m * 4 + 1] = v1;
                    off_out[(size_t)m * 4 + 2] = v2;
                }
            }
        }
    }
    __syncthreads();

    // ---- phase 2: gather + lerp + bf16 hi/lo split; 6 (row,tap) pairs/warp
    #pragma unroll 2
    for (int pi = 0; pi < 6; pi++) {
        int pair = warp * 6 + pi;           // 0..23
        int r = pair / 3, k = pair % 3;
        int rl = rl0 + r;
        int b = rl >> logT, t = rl & (T - 1);
        int m = rl0g + r;

        float off = off_sh[r * 3 + k];
        float pos = (float)(t + k - 1) + off;
        float p0f = floorf(pos);
        float f = pos - p0f;
        int i0 = (int)p0f, i1 = i0 + 1;
        float w0 = (i0 >= 0 && i0 < T) ? (1.0f - f) : 0.0f;
        float w1 = (i1 >= 0 && i1 < T) ? f : 0.0f;
        int i0c = min(max(i0, 0), T - 1);
        int i1c = min(max(i1, 0), T - 1);

        int j0 = i0c - t0 + 1, j1 = i1c - t0 + 1;
        const float* p0 = (j0 >= 0 && j0 < DSTG)
            ? xs + (size_t)j0 * CCH
            : Xl + ((size_t)(b << logT) + i0c) * CCH;
        const float* p1 = (j1 >= 0 && j1 < DSTG)
            ? xs + (size_t)j1 * CCH
            : Xl + ((size_t)(b << logT) + i1c) * CCH;

        size_t base = (size_t)m * KRED + (size_t)k * CCH;
        #pragma unroll
        for (int q = 0; q < 4; q++) {
            int ch = (lane + q * 32) * 4;
            float4 a = *(const float4*)(p0 + ch);
            float4 c = *(const float4*)(p1 + ch);
            float e0 = w0 * a.x + w1 * c.x;
            float e1 = w0 * a.y + w1 * c.y;
            float e2 = w0 * a.z + w1 * c.z;
            float e3 = w0 * a.w + w1 * c.w;

            __nv_bfloat162 h01 = __floats2bfloat162_rn(e0, e1);
            __nv_bfloat162 h23 = __floats2bfloat162_rn(e2, e3);
            float2 f01 = __bfloat1622float2(h01);
            float2 f23 = __bfloat1622float2(h23);
            __nv_bfloat162 l01 = __floats2bfloat162_rn(e0 - f01.x, e1 - f01.y);
            __nv_bfloat162 l23 = __floats2bfloat162_rn(e2 - f23.x, e3 - f23.y);

            uint2 hv, lvv;
            hv.x = *reinterpret_cast<uint32_t*>(&h01);
            hv.y = *reinterpret_cast<uint32_t*>(&h23);
            lvv.x = *reinterpret_cast<uint32_t*>(&l01);
            lvv.y = *reinterpret_cast<uint32_t*>(&l23);
            *(uint2*)(Ah + base + ch) = hv;
            *(uint2*)(Al + base + ch) = lvv;
        }
    }
}

// ---------------------------------------------------------------------------
// GEMM: Y[m,n] = relu( (Ah@Wh + Ah@Wl + Al@Wh)[m,n] + bias[n] ) * maskrow[m]
// grid (4, 448), 128 threads (4 warps, warp tile 64x32), 2-stage, 4 CTAs/SM.
// TRANS_OUT: write (B,C,T) layout directly into the final output buffer.
template <bool TRANS_OUT>
__global__ __launch_bounds__(128, 4)
void gemm_mma_kernel(const __nv_bfloat16* __restrict__ Ahg,
                     const __nv_bfloat16* __restrict__ Alg,
                     const __nv_bfloat16* __restrict__ Whg,
                     const __nv_bfloat16* __restrict__ Wlg,
                     const float* __restrict__ bias,
                     const float* __restrict__ maskrow,
                     float* __restrict__ Y) {
    extern __shared__ __nv_bfloat16 sm[];
    uint32_t sbase = smem_u32(sm);
    int tid = threadIdx.x, warp = tid >> 5, lane = tid & 31;
    int m0 = blockIdx.y * BMM, n0 = blockIdx.x * BNN;

    const uint32_t offAl = A_ELE * 2;
    const uint32_t offBh = 2 * A_ELE * 2;
    const uint32_t offBl = offBh + B_ELE * 2;

    int ar0 = tid >> 2, akc = (tid & 3) * 8;
    int br0 = tid >> 4, bnc = (tid & 15) * 8;
    const __nv_bfloat16* gAh = Ahg + (size_t)(m0 + ar0) * KRED + akc;
    const __nv_bfloat16* gAl = Alg + (size_t)(m0 + ar0) * KRED + akc;
    const __nv_bfloat16* gBh = Whg + (size_t)br0 * CCH + n0 + bnc;
    const __nv_bfloat16* gBl = Wlg + (size_t)br0 * CCH + n0 + bnc;
    const uint32_t A2 = 32u * KRED;
    uint32_t sA0 = (uint32_t)(ar0 * AST + akc) * 2;
    uint32_t sA1 = sA0 + 32u * AST * 2;
    uint32_t sB0 = (uint32_t)(br0 * BST + bnc) * 2;

    int wn = warp * 32;
    int lr = lane & 15, lc = lane >> 4;
    uint32_t a_off[4], b_off[2];
    #pragma unroll
    for (int mt = 0; mt < 4; mt++)
        a_off[mt] = (uint32_t)((mt * 16 + lr) * AST + lc * 8) * 2;
    #pragma unroll
    for (int nt = 0; nt < 2; nt++)
        b_off[nt] = (uint32_t)(lr * BST + wn + nt * 16 + lc * 8) * 2;

    float acc[4][4][4];
    #pragma unroll
    for (int i = 0; i < 4; i++)
        #pragma unroll
        for (int j = 0; j < 4; j++)
            #pragma unroll
            for (int q = 0; q < 4; q++) acc[i][j][q] = 0.f;

    auto load_stage = [&](int st, int k0) {
        uint32_t sb = sbase + (uint32_t)st * STG_BYTES;
        CP16(sb + sA0, gAh + k0);
        CP16(sb + sA1, gAh + A2 + k0);
        CP16(sb + offAl + sA0, gAl + k0);
        CP16(sb + offAl + sA1, gAl + A2 + k0);
        #pragma unroll
        for (int c = 0; c < 4; c++) {
            uint32_t so = sB0 + (uint32_t)c * 8 * BST * 2;
            size_t go = (size_t)(k0 + c * 8) * CCH;
            CP16(sb + offBh + so, gBh + go);
            CP16(sb + offBl + so, gBl + go);
        }
    };

    load_stage(0, 0);
    CP_COMMIT();
    CP_WAIT0();
    __syncthreads();

    for (int it = 0; it < KITERS; it++) {
        if (it + 1 < KITERS) {
            load_stage((it + 1) & 1, (it + 1) * BKK);
            CP_COMMIT();
        }

        uint32_t sb = sbase + (uint32_t)(it & 1) * STG_BYTES;

        uint32_t bh[2][2][4], bl[2][2][4];
        #pragma unroll
        for (int ks = 0; ks < 2; ks++)
            #pragma unroll
            for (int nt = 0; nt < 2; nt++) {
                ldsm_x4_t(bh[nt][ks], sb + offBh + b_off[nt] + ks * (16 * BST * 2));
                ldsm_x4_t(bl[nt][ks], sb + offBl + b_off[nt] + ks * (16 * BST * 2));
            }

        #pragma unroll
        for (int mt = 0; mt < 4; mt++) {
            #pragma unroll
            for (int ks = 0; ks < 2; ks++) {
                uint32_t ah[4], al[4];
                ldsm_x4(ah, sb + a_off[mt] + ks * 32);
                ldsm_x4(al, sb + offAl + a_off[mt] + ks * 32);
                #pragma unroll
                for (int n8 = 0; n8 < 4; n8++) {
                    const uint32_t* ph = &bh[n8 >> 1][ks][(n8 & 1) * 2];
                    const uint32_t* pl = &bl[n8 >> 1][ks][(n8 & 1) * 2];
                    mma16816(acc[mt][n8], ah, ph);
                    mma16816(acc[mt][n8], ah, pl);
                    mma16816(acc[mt][n8], al, ph);
                }
            }
        }

        if (it + 1 < KITERS) {
            CP_WAIT0();
            __syncthreads();
        }
    }

    if (!TRANS_OUT) {
        #pragma unroll
        for (int mt = 0; mt < 4; mt++) {
            int r0g = m0 + mt * 16 + (lane >> 2);
            float mv0 = maskrow[r0g], mv1 = maskrow[r0g + 8];
            float* y0 = Y + (size_t)r0g * CCH;
            float* y1 = y0 + (size_t)8 * CCH;
            #pragma unroll
            for (int n8 = 0; n8 < 4; n8++) {
                int c0g = n0 + wn + n8 * 8 + (lane & 3) * 2;
                float b0 = bias[c0g], b1 = bias[c0g + 1];
                float2 v0, v1;
                v0.x = fmaxf(acc[mt][n8][0] + b0, 0.f) * mv0;
                v0.y = fmaxf(acc[mt][n8][1] + b1, 0.f) * mv0;
                v1.x = fmaxf(acc[mt][n8][2] + b0, 0.f) * mv1;
                v1.y = fmaxf(acc[mt][n8][3] + b1, 0.f) * mv1;
                *(float2*)(y0 + c0g) = v0;
                *(float2*)(y1 + c0g) = v1;
            }
        }
    } else {
        // stage tile (m-local 0..63, c-local 0..127) as smT[c][m], then write
        // out[(b*CCH + c_global)*T + t0 + m-local]  (64 | T so batch uniform)
        float* smT = (float*)sm;
        __syncthreads();                    // compute done; reuse pipeline smem
        #pragma unroll
        for (int mt = 0; mt < 4; mt++) {
            int ml0 = mt * 16 + (lane >> 2);
            int r0g = m0 + ml0;
            float mv0 = maskrow[r0g], mv1 = maskrow[r0g + 8];
            #pragma unroll
            for (int n8 = 0; n8 < 4; n8++) {
                int cl = wn + n8 * 8 + (lane & 3) * 2;
                float b0 = bias[n0 + cl], b1 = bias[n0 + cl + 1];
                smT[cl * TPAD + ml0]           = fmaxf(acc[mt][n8][0] + b0, 0.f) * mv0;
                smT[(cl + 1) * TPAD + ml0]     = fmaxf(acc[mt][n8][1] + b1, 0.f) * mv0;
                smT[cl * TPAD + ml0 + 8]       = fmaxf(acc[mt][n8][2] + b0, 0.f) * mv1;
                smT[(cl + 1) * TPAD + ml0 + 8] = fmaxf(acc[mt][n8][3] + b1, 0.f) * mv1;
            }
        }
        __syncthreads();
        int lv = (m0 < LV0) ? 0 : (m0 < LV01 ? 1 : 2);
        int lbase = (lv == 0) ? 0 : (lv == 1 ? LV0 : LV01);
        int logT = 11 - lv;
        int T = 1 << logT;
        int rl0 = m0 - lbase;
        int b = rl0 >> logT, t0 = rl0 & (T - 1);
        size_t obase = (lv == 0) ? 0 : (lv == 1 ? (size_t)BSZ * CCH * 2048
                                               : (size_t)BSZ * CCH * 3072);
        float* outb = Y + obase + ((size_t)b * CCH) * T + t0;
        for (int idx = tid; idx < 128 * 16; idx += 128) {
            int cl = idx >> 4, seg = (idx & 15) * 4;
            float4 v = *(float4*)(smT + cl * TPAD + seg);
            *(float4*)(outb + (size_t)(n0 + cl) * T + seg) = v;
        }
    }
}

// ---------------------------------------------------------------------------
extern "C" void kernel_launch(void* const* d_in, const int* in_sizes, int n_in,
                              void* d_out, int out_size) {
    const float *feats[3] = {}, *masks[3] = {}, *offs[3] = {};
    const float *w[2] = {}, *bias[2] = {}, *ow[2] = {}, *ob[2] = {};
    int wi = 0, bi = 0, owi = 0, obi = 0;
    for (int i = 0; i < n_in; i++) {
        const float* p = (const float*)d_in[i];
        switch (in_sizes[i]) {
            case 8 * 512 * 2048: feats[0] = p; break;
            case 8 * 512 * 1024: feats[1] = p; break;
            case 8 * 512 * 512:  feats[2] = p; break;
            case 8 * 2048:       masks[0] = p; break;
            case 8 * 1024:       masks[1] = p; break;
            case 8 * 512:        masks[2] = p; break;
            case 8 * 3 * 2048:   offs[0] = p; break;
            case 8 * 3 * 1024:   offs[1] = p; break;
            case 8 * 3 * 512:    offs[2] = p; break;
            case 512 * 512 * 3:  if (wi < 2)  w[wi++] = p; break;
            case 512:            if (bi < 2)  bias[bi++] = p; break;
            case 3 * 512 * 3:    if (owi < 2) ow[owi++] = p; break;
            case 3:              if (obi < 2) ob[obi++] = p; break;
            default: break;
        }
    }

    float *xb, *yb, *offa, *mrow, *ow2;
    __nv_bfloat16 *Ah, *Al, *Wh, *Wl;
    cudaGetSymbolAddress((void**)&xb, g_x);
    cudaGetSymbolAddress((void**)&yb, g_y);
    cudaGetSymbolAddress((void**)&offa, g_offa);
    cudaGetSymbolAddress((void**)&mrow, g_mrow);
    cudaGetSymbolAddress((void**)&ow2, g_ow2);
    cudaGetSymbolAddress((void**)&Ah, g_Ah);
    cudaGetSymbolAddress((void**)&Al, g_Al);
    cudaGetSymbolAddress((void**)&Wh, g_Wh);
    cudaGetSymbolAddress((void**)&Wl, g_Wl);
    float* out = (float*)d_out;

    cudaFuncSetAttribute(gemm_mma_kernel<false>,
                         cudaFuncAttributeMaxDynamicSharedMemorySize, GEMM_SMEM);
    cudaFuncSetAttribute(gemm_mma_kernel<true>,
                         cudaFuncAttributeMaxDynamicSharedMemorySize, GEMM_SMEM);
    cudaFuncSetAttribute(deform_kernel<true>,
                         cudaFuncAttributeMaxDynamicSharedMemorySize, DEF_SMEM);
    cudaFuncSetAttribute(deform_kernel<false>,
                         cudaFuncAttributeMaxDynamicSharedMemorySize, DEF_SMEM);

    // launch 0: input transposes; launch 1: weight split + masks
    tin_kernel<<<TIN_BLOCKS, 256>>>(feats[0], feats[1], feats[2], xb);
    wsplit_kernel<<<(WSPLIT_TOTAL + 255) / 256, 256>>>(
        w[0], w[1], ow[0], ow[1], masks[0], masks[1], masks[2],
        Wh, Wl, ow2, mrow, out);

    // ---- layer 0 ----  (launches 2,3)
    deform_kernel<true><<<ROWS_TOTAL / DROWS, 128, DEF_SMEM>>>(
        xb, offs[0], offs[1], offs[2], ow2, ob[0], offa, Ah, Al);
    gemm_mma_kernel<false><<<dim3(4, ROWS_TOTAL / BMM), 128, GEMM_SMEM>>>(
        Ah, Al, Wh, Wl, bias[0], mrow, yb);

    // ---- layer 1 ----  (launches 4,5 — ncu captures launch 5 = gemm<true>)
    deform_kernel<false><<<ROWS_TOTAL / DROWS, 128, DEF_SMEM>>>(
        yb, offa, nullptr, nullptr, ow2 + KT * KT * CCH, ob[1], nullptr, Ah, Al);
    gemm_mma_kernel<true><<<dim3(4, ROWS_TOTAL / BMM), 128, GEMM_SMEM>>>(
        Ah, Al, Wh + (size_t)KRED * CCH, Wl + (size_t)KRED * CCH,
        bias[1], mrow, out);
}